// round 1
// baseline (speedup 1.0000x reference)
#include <cuda_runtime.h>
#include <math.h>

// Problem constants
#define BB 2
#define TT 2048
#define DENSE 1024
#define NH 8
#define HD 128
#define WIN 64
#define TOPK 32
#define MT (BB*TT)          // 4096 rows
#define SP 1024             // NH*HD

// ---------------- device scratch (no allocation allowed) ----------------
__device__ float g_qs[MT * SP];       // relu(x @ enc_q)  (b,t, n*HD+e)
__device__ float g_vs[MT * SP];       // relu(x @ enc_v)
__device__ float g_outsp[MT * SP];    // q * context
__device__ float g_sig[BB * SP];
__device__ float g_metric[BB * SP];   // softplus metric (b, n*HD+e)
__device__ float g_heb[NH * HD * HD]; // U@V per head

// ---------------- generic 128x128x8 SGEMM (optional ReLU) ----------------
// C[128 x 128] block per CTA. A row-major with ldA == K.
// B block chosen by: B + blockIdx.y*bOffY + blockIdx.z*bOffZ, ld = ldb.
// C block: C + blockIdx.x*128*ldc + blockIdx.y*cOffY + blockIdx.z*cOffZ.
__global__ __launch_bounds__(256) void gemm128(
    const float* __restrict__ A, const float* __restrict__ B, float* __restrict__ C,
    int K, int ldb, int ldc, int bOffY, int bOffZ, int cOffY, int cOffZ, int doRelu)
{
    __shared__ float As[8][128];
    __shared__ float Bs[8][128];

    const float* Ablk = A + (size_t)blockIdx.x * 128 * K;
    const float* Bblk = B + (size_t)blockIdx.y * bOffY + (size_t)blockIdx.z * bOffZ;
    float* Cblk = C + (size_t)blockIdx.x * 128 * ldc + (size_t)blockIdx.y * cOffY
                    + (size_t)blockIdx.z * cOffZ;

    const int tid = threadIdx.x;
    const int tx = tid & 15;       // N dir
    const int ty = tid >> 4;       // M dir

    float acc[8][8];
#pragma unroll
    for (int i = 0; i < 8; i++)
#pragma unroll
        for (int j = 0; j < 8; j++) acc[i][j] = 0.f;

    const int ar = tid >> 1, ah = (tid & 1) * 4;
    const int br = tid >> 5, bc = (tid & 31) * 4;

    for (int k0 = 0; k0 < K; k0 += 8) {
        float4 av = *reinterpret_cast<const float4*>(Ablk + (size_t)ar * K + k0 + ah);
        As[ah + 0][ar] = av.x; As[ah + 1][ar] = av.y;
        As[ah + 2][ar] = av.z; As[ah + 3][ar] = av.w;
        float4 bv = *reinterpret_cast<const float4*>(Bblk + (size_t)(k0 + br) * ldb + bc);
        *reinterpret_cast<float4*>(&Bs[br][bc]) = bv;
        __syncthreads();

#pragma unroll
        for (int kk = 0; kk < 8; kk++) {
            float a[8], b[8];
            float4 a0 = *reinterpret_cast<const float4*>(&As[kk][ty * 8]);
            float4 a1 = *reinterpret_cast<const float4*>(&As[kk][ty * 8 + 4]);
            a[0]=a0.x; a[1]=a0.y; a[2]=a0.z; a[3]=a0.w;
            a[4]=a1.x; a[5]=a1.y; a[6]=a1.z; a[7]=a1.w;
            float4 b0 = *reinterpret_cast<const float4*>(&Bs[kk][tx * 8]);
            float4 b1 = *reinterpret_cast<const float4*>(&Bs[kk][tx * 8 + 4]);
            b[0]=b0.x; b[1]=b0.y; b[2]=b0.z; b[3]=b0.w;
            b[4]=b1.x; b[5]=b1.y; b[6]=b1.z; b[7]=b1.w;
#pragma unroll
            for (int i = 0; i < 8; i++)
#pragma unroll
                for (int j = 0; j < 8; j++)
                    acc[i][j] = fmaf(a[i], b[j], acc[i][j]);
        }
        __syncthreads();
    }

#pragma unroll
    for (int i = 0; i < 8; i++) {
        float* crow = Cblk + (size_t)(ty * 8 + i) * ldc + tx * 8;
#pragma unroll
        for (int j = 0; j < 8; j++) {
            float v = acc[i][j];
            if (doRelu) v = fmaxf(v, 0.f);
            crow[j] = v;
        }
    }
}

// ---------------- sig reduction: mean over T + strided-8 mean ----------------
__global__ void reduce_sig_kernel(const float* __restrict__ qs, float* __restrict__ sig)
{
    int b = blockIdx.x;
    int c = blockIdx.y * 128 + threadIdx.x;
    const float* p = qs + ((size_t)b * TT) * SP + c;
    double s = 0.0, s8 = 0.0;
    for (int t = 0; t < TT; t++) {
        float v = p[(size_t)t * SP];
        s += (double)v;
        if ((t & 7) == 0) s8 += (double)v;
    }
    sig[b * SP + c] = (float)(s * (1.0 / TT) + 0.5 * s8 * (1.0 / (TT / 8)));
}

// ---------------- metric MLP: gelu(sig@w1+b1)@w2+b2 -> softplus ----------------
__global__ __launch_bounds__(512) void metric_kernel(
    const float* __restrict__ sig, const float* __restrict__ w1, const float* __restrict__ b1,
    const float* __restrict__ w2, const float* __restrict__ b2, const float* __restrict__ base,
    float* __restrict__ metric)
{
    __shared__ float sig_s[SP];
    __shared__ float h_s[SP / 2];
    int b = blockIdx.x, tid = threadIdx.x;
    sig_s[tid] = sig[b * SP + tid];
    sig_s[tid + 512] = sig[b * SP + tid + 512];
    __syncthreads();

    float acc = b1[tid];
    for (int d = 0; d < SP; d++) acc = fmaf(sig_s[d], w1[d * 512 + tid], acc);
    // exact gelu
    h_s[tid] = 0.5f * acc * (1.f + erff(acc * 0.7071067811865475f));
    __syncthreads();

    for (int half = 0; half < 2; half++) {
        int col = tid + half * 512;
        float m = b2[col];
        for (int k = 0; k < 512; k++) m = fmaf(h_s[k], w2[k * SP + col], m);
        float xv = base[col] + 0.1f * m;
        // softplus = max(x,0) + log1p(exp(-|x|))
        metric[b * SP + col] = fmaxf(xv, 0.f) + log1pf(expf(-fabsf(xv)));
    }
}

// ---------------- Hebbian U@V precompute ----------------
__global__ void heb_kernel(const float* __restrict__ U, const float* __restrict__ V,
                           float* __restrict__ hebM)
{
    int h = blockIdx.x, i = threadIdx.x;   // 128 threads = rows
    float u[32];
#pragma unroll
    for (int r = 0; r < 32; r++) u[r] = U[h * HD * 32 + i * 32 + r];
    const float* Vh = V + h * 32 * HD;
    for (int j = 0; j < HD; j++) {
        float s = 0.f;
#pragma unroll
        for (int r = 0; r < 32; r++) s = fmaf(u[r], Vh[r * HD + j], s);
        hebM[h * HD * HD + i * HD + j] = s;
    }
}

// ---------------- windowed metric attention ----------------
// grid (T/16, NH, B), 128 threads (4 warps x 4 t's each)
#define TTILE 16
#define NROWS 79           // 63 history + 16 tile
#define RSTR 129           // padded smem row stride (conflict-free per-lane rows)

__global__ __launch_bounds__(128) void attn_kernel(
    const float* __restrict__ qs, const float* __restrict__ vs,
    const float* __restrict__ metric, const float* __restrict__ hebM,
    float* __restrict__ outsp)
{
    extern __shared__ float sm[];
    float* q_s = sm;                         // NROWS * RSTR
    float* v_s = q_s + NROWS * RSTR;         // NROWS * RSTR
    float* met_s = v_s + NROWS * RSTR;       // 128
    __shared__ float d_s[4][WIN];
    __shared__ float wsel[4][TOPK];
    __shared__ int   rsel[4][TOPK];

    const int t0 = blockIdx.x * TTILE;
    const int h = blockIdx.y;
    const int b = blockIdx.z;
    const int tid = threadIdx.x;
    const int warp = tid >> 5, lane = tid & 31;

    const size_t baseRow = (size_t)b * TT * SP;
    for (int i = tid; i < NROWS * HD; i += 128) {
        int s = i >> 7, e = i & 127;
        int g = t0 - (WIN - 1) + s; if (g < 0) g = 0;
        size_t gi = baseRow + (size_t)g * SP + h * HD + e;
        q_s[s * RSTR + e] = qs[gi];
        v_s[s * RSTR + e] = vs[gi];
    }
    met_s[tid & 127] = metric[b * SP + h * HD + (tid & 127)];
    __syncthreads();

    const float* HM = hebM + h * HD * HD;

    for (int it = 0; it < 4; it++) {
        const int t = t0 + warp * 4 + it;
        const int qrow = t - t0 + (WIN - 1);
        const float* qr = q_s + qrow * RSTR;

        int gg0 = t - lane;        if (gg0 < 0) gg0 = 0;
        int gg1 = t - lane - 32;   if (gg1 < 0) gg1 = 0;
        const int r0 = gg0 - t0 + (WIN - 1);
        const int r1 = gg1 - t0 + (WIN - 1);
        const float* p0 = q_s + r0 * RSTR;
        const float* p1 = q_s + r1 * RSTR;

        float d0 = 0.f, d1 = 0.f;
#pragma unroll 8
        for (int e = 0; e < HD; e++) {
            float qv = qr[e], m = met_s[e];
            float a = qv - p0[e]; d0 = fmaf(a * a, m, d0);
            float c = qv - p1[e]; d1 = fmaf(c * c, m, d1);
        }
        float dist0 = sqrtf(d0 + 1e-8f);
        float dist1 = sqrtf(d1 + 1e-8f);
        d_s[warp][lane] = dist0;
        d_s[warp][lane + 32] = dist1;
        __syncwarp();

        // stable rank (ties -> lower window index), matches jax top_k on -dist
        int rk0 = 0, rk1 = 0;
        const int j1 = lane + 32;
#pragma unroll 8
        for (int j = 0; j < WIN; j++) {
            float dj = d_s[warp][j];
            rk0 += (dj < dist0) || (dj == dist0 && j < lane);
            rk1 += (dj < dist1) || (dj == dist1 && j < j1);
        }
        if (rk0 < TOPK) { wsel[warp][rk0] = expf(-dist0); rsel[warp][rk0] = r0; }
        if (rk1 < TOPK) { wsel[warp][rk1] = expf(-dist1); rsel[warp][rk1] = r1; }
        __syncwarp();

        float wsum = wsel[warp][lane];
#pragma unroll
        for (int o = 16; o; o >>= 1) wsum += __shfl_xor_sync(0xffffffffu, wsum, o);
        const float inv = 1.f / (wsum + 1e-8f);

        float c0 = 0.f, c1 = 0.f, c2 = 0.f, c3 = 0.f;
#pragma unroll 4
        for (int k = 0; k < TOPK; k++) {
            float wk = wsel[warp][k];
            const float* vr = v_s + rsel[warp][k] * RSTR;
            c0 = fmaf(wk, vr[lane], c0);
            c1 = fmaf(wk, vr[lane + 32], c1);
            c2 = fmaf(wk, vr[lane + 64], c2);
            c3 = fmaf(wk, vr[lane + 96], c3);
        }
        c0 *= inv; c1 *= inv; c2 *= inv; c3 *= inv;

        const float q0 = qr[lane], q1 = qr[lane + 32], q2 = qr[lane + 64], q3 = qr[lane + 96];
        float nq = q0 * q0 + q1 * q1 + q2 * q2 + q3 * q3;
#pragma unroll
        for (int o = 16; o; o >>= 1) nq += __shfl_xor_sync(0xffffffffu, nq, o);
        const float nrm = sqrtf(nq);

        if (nrm > 0.2f) {       // gate (warp-uniform)
            const float qinv = 1.f / fmaxf(nrm, 1e-12f);
            float h0 = 0.f, h1 = 0.f, h2 = 0.f, h3 = 0.f;
#pragma unroll 4
            for (int e = 0; e < HD; e++) {
                float qe = qr[e] * qinv;
                const float* hm = HM + e * HD;
                h0 = fmaf(qe, __ldg(hm + lane), h0);
                h1 = fmaf(qe, __ldg(hm + lane + 32), h1);
                h2 = fmaf(qe, __ldg(hm + lane + 64), h2);
                h3 = fmaf(qe, __ldg(hm + lane + 96), h3);
            }
            c0 += 0.1f * h0; c1 += 0.1f * h1; c2 += 0.1f * h2; c3 += 0.1f * h3;
        }

        size_t ob = baseRow + (size_t)t * SP + h * HD;
        outsp[ob + lane]      = q0 * c0;
        outsp[ob + lane + 32] = q1 * c1;
        outsp[ob + lane + 64] = q2 * c2;
        outsp[ob + lane + 96] = q3 * c3;
    }
}

// ---------------- launcher ----------------
extern "C" void kernel_launch(void* const* d_in, const int* in_sizes, int n_in,
                              void* d_out, int out_size)
{
    const float* x      = (const float*)d_in[0];
    const float* enc_q  = (const float*)d_in[1];
    const float* enc_v  = (const float*)d_in[2];
    const float* w1     = (const float*)d_in[3];
    const float* b1     = (const float*)d_in[4];
    const float* w2     = (const float*)d_in[5];
    const float* b2     = (const float*)d_in[6];
    const float* basem  = (const float*)d_in[7];
    const float* hebU   = (const float*)d_in[8];
    const float* hebV   = (const float*)d_in[9];
    const float* dec    = (const float*)d_in[10];
    float* out = (float*)d_out;

    float *qs, *vs, *outsp, *sig, *metric, *hebM;
    cudaGetSymbolAddress((void**)&qs, g_qs);
    cudaGetSymbolAddress((void**)&vs, g_vs);
    cudaGetSymbolAddress((void**)&outsp, g_outsp);
    cudaGetSymbolAddress((void**)&sig, g_sig);
    cudaGetSymbolAddress((void**)&metric, g_metric);
    cudaGetSymbolAddress((void**)&hebM, g_heb);

    const int attn_smem = (2 * NROWS * RSTR + 128) * (int)sizeof(float);
    cudaFuncSetAttribute(attn_kernel, cudaFuncAttributeMaxDynamicSharedMemorySize, attn_smem);

    // 1,2: sparse encoders (per-head 1024x128 weight panels; relu fused)
    dim3 gE(MT / 128, 1, NH);
    gemm128<<<gE, 256>>>(x, enc_q, qs, DENSE, HD, SP, 0, DENSE * HD, 0, HD, 1);
    gemm128<<<gE, 256>>>(x, enc_v, vs, DENSE, HD, SP, 0, DENSE * HD, 0, HD, 1);

    // 3: hebbian matrices (independent of 1-2 numerically but stream-ordered anyway)
    heb_kernel<<<NH, HD>>>(hebU, hebV, hebM);

    // 4,5: metric pathway
    reduce_sig_kernel<<<dim3(BB, SP / 128), 128>>>(qs, sig);
    metric_kernel<<<BB, 512>>>(sig, w1, b1, w2, b2, basem, metric);

    // 6: windowed top-K attention + hebbian context + q*context
    attn_kernel<<<dim3(TT / TTILE, NH, BB), 128, attn_smem>>>(qs, vs, metric, hebM, outsp);

    // 7: decoder
    dim3 gD(MT / 128, SP / 128, 1);
    gemm128<<<gD, 256>>>(outsp, dec, out, SP, DENSE, DENSE, 128, 0, 128, 0, 0);
}

// round 2
// speedup vs baseline: 1.1646x; 1.1646x over previous
#include <cuda_runtime.h>
#include <math.h>

// Problem constants
#define BB 2
#define TT 2048
#define DENSE 1024
#define NH 8
#define HD 128
#define WIN 64
#define TOPK 32
#define MT (BB*TT)          // 4096 rows
#define SP 1024             // NH*HD
#define KC 16               // GEMM k-tile
#define TCH 8               // t-chunks for sig reduction

// ---------------- device scratch (no allocation allowed) ----------------
__device__ float g_qs[MT * SP];
__device__ float g_vs[MT * SP];
__device__ float g_outsp[MT * SP];
__device__ float g_part[2 * BB * TCH * SP];   // partial sums (mean, stride8)
__device__ float g_sig[BB * SP];
__device__ float g_metric[BB * SP];
__device__ float g_heb[NH * HD * HD];

// ---------------- cp.async helpers ----------------
__device__ __forceinline__ unsigned smem_u32(const void* p) {
    return (unsigned)__cvta_generic_to_shared(p);
}
__device__ __forceinline__ void cp16(unsigned dst, const float* src) {
    asm volatile("cp.async.cg.shared.global [%0], [%1], 16;" :: "r"(dst), "l"(src));
}
__device__ __forceinline__ void cp_commit() { asm volatile("cp.async.commit_group;"); }
template<int N> __device__ __forceinline__ void cp_wait() {
    asm volatile("cp.async.wait_group %0;" :: "n"(N));
}

// ---------------- double-buffered 128x128xKC SGEMM core ----------------
// Ablk: 128 rows, ld = K. Bblk: K x 128 panel, ld = ldb. Cblk: 128x128, ld = ldc.
__device__ __forceinline__ void gemm_body(
    const float* __restrict__ Ablk, const float* __restrict__ Bblk, float* __restrict__ Cblk,
    int K, int ldb, int ldc, int doRelu)
{
    __shared__ float As[2][128 * KC];
    __shared__ float Bs[2][KC * 128];

    const int tid = threadIdx.x;
    const int tx = tid & 15;        // N dir (8 cols each)
    const int ty = tid >> 4;        // M dir (8 rows each)

    const int am = tid >> 1, ak = (tid & 1) * 8;       // A: row, k-offset
    const int br = tid >> 4, bc = (tid & 15) * 8;      // B: k-row, col

    float acc[8][8];
#pragma unroll
    for (int i = 0; i < 8; i++)
#pragma unroll
        for (int j = 0; j < 8; j++) acc[i][j] = 0.f;

    const int nk = K / KC;

    // prefetch tile 0
    {
        unsigned ad = smem_u32(&As[0][am * KC + ak]);
        cp16(ad, Ablk + (size_t)am * K + ak);
        cp16(ad + 16, Ablk + (size_t)am * K + ak + 4);
        unsigned bd = smem_u32(&Bs[0][br * 128 + bc]);
        cp16(bd, Bblk + (size_t)br * ldb + bc);
        cp16(bd + 16, Bblk + (size_t)br * ldb + bc + 4);
        cp_commit();
    }

    for (int i = 0; i < nk; i++) {
        if (i + 1 < nk) {
            const int k0 = (i + 1) * KC;
            const int buf = (i + 1) & 1;
            unsigned ad = smem_u32(&As[buf][am * KC + ak]);
            cp16(ad, Ablk + (size_t)am * K + k0 + ak);
            cp16(ad + 16, Ablk + (size_t)am * K + k0 + ak + 4);
            unsigned bd = smem_u32(&Bs[buf][br * 128 + bc]);
            cp16(bd, Bblk + (size_t)(k0 + br) * ldb + bc);
            cp16(bd + 16, Bblk + (size_t)(k0 + br) * ldb + bc + 4);
            cp_commit();
            cp_wait<1>();
        } else {
            cp_wait<0>();
        }
        __syncthreads();

        const float* A_ = &As[i & 1][0];
        const float* B_ = &Bs[i & 1][0];
#pragma unroll
        for (int kk = 0; kk < KC; kk++) {
            float a[8], b[8];
#pragma unroll
            for (int r = 0; r < 8; r++) a[r] = A_[(ty * 8 + r) * KC + kk];
            float4 b0 = *reinterpret_cast<const float4*>(&B_[kk * 128 + tx * 8]);
            float4 b1 = *reinterpret_cast<const float4*>(&B_[kk * 128 + tx * 8 + 4]);
            b[0]=b0.x; b[1]=b0.y; b[2]=b0.z; b[3]=b0.w;
            b[4]=b1.x; b[5]=b1.y; b[6]=b1.z; b[7]=b1.w;
#pragma unroll
            for (int r = 0; r < 8; r++)
#pragma unroll
                for (int c = 0; c < 8; c++)
                    acc[r][c] = fmaf(a[r], b[c], acc[r][c]);
        }
        __syncthreads();
    }

#pragma unroll
    for (int r = 0; r < 8; r++) {
        float* crow = Cblk + (size_t)(ty * 8 + r) * ldc + tx * 8;
#pragma unroll
        for (int c = 0; c < 8; c++) {
            float v = acc[r][c];
            if (doRelu) v = fmaxf(v, 0.f);
            crow[c] = v;
        }
    }
}

// Encoder: one launch does both enc_q and enc_v, all heads (grid.z = 16)
__global__ __launch_bounds__(256, 2) void gemm_enc(
    const float* __restrict__ x, const float* __restrict__ eq, const float* __restrict__ ev,
    float* __restrict__ qs, float* __restrict__ vs)
{
    const int z = blockIdx.z;
    const int n = z & 7, isV = z >> 3;
    const float* B = (isV ? ev : eq) + (size_t)n * DENSE * HD;
    float* C = (isV ? vs : qs) + (size_t)blockIdx.x * 128 * SP + n * HD;
    gemm_body(x + (size_t)blockIdx.x * 128 * DENSE, B, C, DENSE, HD, SP, 1);
}

// Decoder
__global__ __launch_bounds__(256, 2) void gemm_dec(
    const float* __restrict__ A, const float* __restrict__ B, float* __restrict__ C)
{
    gemm_body(A + (size_t)blockIdx.x * 128 * SP,
              B + blockIdx.y * 128,
              C + (size_t)blockIdx.x * 128 * DENSE + blockIdx.y * 128,
              SP, DENSE, DENSE, 0);
}

// ---------------- sig reduction phase A: partial sums over t-chunks ----------------
__global__ void reduce_sig_a(const float* __restrict__ qs, float* __restrict__ part)
{
    const int b = blockIdx.x;
    const int col = blockIdx.y * 128 + threadIdx.x;
    const int tz = blockIdx.z;
    const int t0 = tz * (TT / TCH);
    const float* p = qs + ((size_t)b * TT + t0) * SP + col;
    float s = 0.f, s8 = 0.f;
#pragma unroll 4
    for (int t = 0; t < TT / TCH; t++) {
        float v = p[(size_t)t * SP];
        s += v;
        if (((t0 + t) & 7) == 0) s8 += v;
    }
    part[((size_t)b * TCH + tz) * SP + col] = s;
    part[(size_t)BB * TCH * SP + ((size_t)b * TCH + tz) * SP + col] = s8;
}

// phase B: combine chunks -> sig = mean + 0.5*mean8
__global__ void reduce_sig_b(const float* __restrict__ part, float* __restrict__ sig)
{
    const int b = blockIdx.x;
    const int col = blockIdx.y * 128 + threadIdx.x;
    float s = 0.f, s8 = 0.f;
#pragma unroll
    for (int z = 0; z < TCH; z++) {
        s  += part[((size_t)b * TCH + z) * SP + col];
        s8 += part[(size_t)BB * TCH * SP + ((size_t)b * TCH + z) * SP + col];
    }
    sig[b * SP + col] = s * (1.f / TT) + 0.5f * s8 * (1.f / (TT / 8));
}

// ---------------- metric MLP: gelu(sig@w1+b1)@w2+b2 -> softplus ----------------
__global__ __launch_bounds__(512) void metric_kernel(
    const float* __restrict__ sig, const float* __restrict__ w1, const float* __restrict__ b1,
    const float* __restrict__ w2, const float* __restrict__ b2, const float* __restrict__ base,
    float* __restrict__ metric)
{
    __shared__ float sig_s[SP];
    __shared__ float h_s[SP / 2];
    int b = blockIdx.x, tid = threadIdx.x;
    sig_s[tid] = sig[b * SP + tid];
    sig_s[tid + 512] = sig[b * SP + tid + 512];
    __syncthreads();

    float acc = b1[tid];
    for (int d = 0; d < SP; d++) acc = fmaf(sig_s[d], w1[d * 512 + tid], acc);
    h_s[tid] = 0.5f * acc * (1.f + erff(acc * 0.7071067811865475f));
    __syncthreads();

    for (int half = 0; half < 2; half++) {
        int col = tid + half * 512;
        float m = b2[col];
        for (int k = 0; k < 512; k++) m = fmaf(h_s[k], w2[k * SP + col], m);
        float xv = base[col] + 0.1f * m;
        metric[b * SP + col] = fmaxf(xv, 0.f) + log1pf(expf(-fabsf(xv)));
    }
}

// ---------------- Hebbian U@V precompute ----------------
__global__ void heb_kernel(const float* __restrict__ U, const float* __restrict__ V,
                           float* __restrict__ hebM)
{
    int h = blockIdx.x, i = threadIdx.x;
    float u[32];
#pragma unroll
    for (int r = 0; r < 32; r++) u[r] = U[h * HD * 32 + i * 32 + r];
    const float* Vh = V + h * 32 * HD;
    for (int j = 0; j < HD; j++) {
        float s = 0.f;
#pragma unroll
        for (int r = 0; r < 32; r++) s = fmaf(u[r], Vh[r * HD + j], s);
        hebM[h * HD * HD + i * HD + j] = s;
    }
}

// ---------------- windowed metric attention ----------------
#define TTILE 16
#define NROWS 79
#define RSTR 129

__global__ __launch_bounds__(128) void attn_kernel(
    const float* __restrict__ qs, const float* __restrict__ vs,
    const float* __restrict__ metric, const float* __restrict__ hebM,
    float* __restrict__ outsp)
{
    extern __shared__ float sm[];
    float* q_s = sm;
    float* v_s = q_s + NROWS * RSTR;
    float* met_s = v_s + NROWS * RSTR;
    __shared__ float d_s[4][WIN];
    __shared__ float wsel[4][TOPK];
    __shared__ int   rsel[4][TOPK];

    const int t0 = blockIdx.x * TTILE;
    const int h = blockIdx.y;
    const int b = blockIdx.z;
    const int tid = threadIdx.x;
    const int warp = tid >> 5, lane = tid & 31;

    const size_t baseRow = (size_t)b * TT * SP;
    for (int i = tid; i < NROWS * HD; i += 128) {
        int s = i >> 7, e = i & 127;
        int g = t0 - (WIN - 1) + s; if (g < 0) g = 0;
        size_t gi = baseRow + (size_t)g * SP + h * HD + e;
        q_s[s * RSTR + e] = qs[gi];
        v_s[s * RSTR + e] = vs[gi];
    }
    met_s[tid & 127] = metric[b * SP + h * HD + (tid & 127)];
    __syncthreads();

    const float* HM = hebM + h * HD * HD;

    for (int it = 0; it < 4; it++) {
        const int t = t0 + warp * 4 + it;
        const int qrow = t - t0 + (WIN - 1);
        const float* qr = q_s + qrow * RSTR;

        int gg0 = t - lane;        if (gg0 < 0) gg0 = 0;
        int gg1 = t - lane - 32;   if (gg1 < 0) gg1 = 0;
        const int r0 = gg0 - t0 + (WIN - 1);
        const int r1 = gg1 - t0 + (WIN - 1);
        const float* p0 = q_s + r0 * RSTR;
        const float* p1 = q_s + r1 * RSTR;

        float d0 = 0.f, d1 = 0.f;
#pragma unroll 8
        for (int e = 0; e < HD; e++) {
            float qv = qr[e], m = met_s[e];
            float a = qv - p0[e]; d0 = fmaf(a * a, m, d0);
            float c = qv - p1[e]; d1 = fmaf(c * c, m, d1);
        }
        float dist0 = sqrtf(d0 + 1e-8f);
        float dist1 = sqrtf(d1 + 1e-8f);
        d_s[warp][lane] = dist0;
        d_s[warp][lane + 32] = dist1;
        __syncwarp();

        int rk0 = 0, rk1 = 0;
        const int j1 = lane + 32;
#pragma unroll 8
        for (int j = 0; j < WIN; j++) {
            float dj = d_s[warp][j];
            rk0 += (dj < dist0) || (dj == dist0 && j < lane);
            rk1 += (dj < dist1) || (dj == dist1 && j < j1);
        }
        if (rk0 < TOPK) { wsel[warp][rk0] = expf(-dist0); rsel[warp][rk0] = r0; }
        if (rk1 < TOPK) { wsel[warp][rk1] = expf(-dist1); rsel[warp][rk1] = r1; }
        __syncwarp();

        float wsum = wsel[warp][lane];
#pragma unroll
        for (int o = 16; o; o >>= 1) wsum += __shfl_xor_sync(0xffffffffu, wsum, o);
        const float inv = 1.f / (wsum + 1e-8f);

        float c0 = 0.f, c1 = 0.f, c2 = 0.f, c3 = 0.f;
#pragma unroll 4
        for (int k = 0; k < TOPK; k++) {
            float wk = wsel[warp][k];
            const float* vr = v_s + rsel[warp][k] * RSTR;
            c0 = fmaf(wk, vr[lane], c0);
            c1 = fmaf(wk, vr[lane + 32], c1);
            c2 = fmaf(wk, vr[lane + 64], c2);
            c3 = fmaf(wk, vr[lane + 96], c3);
        }
        c0 *= inv; c1 *= inv; c2 *= inv; c3 *= inv;

        const float q0 = qr[lane], q1 = qr[lane + 32], q2 = qr[lane + 64], q3 = qr[lane + 96];
        float nq = q0 * q0 + q1 * q1 + q2 * q2 + q3 * q3;
#pragma unroll
        for (int o = 16; o; o >>= 1) nq += __shfl_xor_sync(0xffffffffu, nq, o);
        const float nrm = sqrtf(nq);

        if (nrm > 0.2f) {
            const float qinv = 1.f / fmaxf(nrm, 1e-12f);
            float h0 = 0.f, h1 = 0.f, h2 = 0.f, h3 = 0.f;
#pragma unroll 4
            for (int e = 0; e < HD; e++) {
                float qe = qr[e] * qinv;
                const float* hm = HM + e * HD;
                h0 = fmaf(qe, __ldg(hm + lane), h0);
                h1 = fmaf(qe, __ldg(hm + lane + 32), h1);
                h2 = fmaf(qe, __ldg(hm + lane + 64), h2);
                h3 = fmaf(qe, __ldg(hm + lane + 96), h3);
            }
            c0 += 0.1f * h0; c1 += 0.1f * h1; c2 += 0.1f * h2; c3 += 0.1f * h3;
        }

        size_t ob = baseRow + (size_t)t * SP + h * HD;
        outsp[ob + lane]      = q0 * c0;
        outsp[ob + lane + 32] = q1 * c1;
        outsp[ob + lane + 64] = q2 * c2;
        outsp[ob + lane + 96] = q3 * c3;
    }
}

// ---------------- launcher ----------------
extern "C" void kernel_launch(void* const* d_in, const int* in_sizes, int n_in,
                              void* d_out, int out_size)
{
    const float* x      = (const float*)d_in[0];
    const float* enc_q  = (const float*)d_in[1];
    const float* enc_v  = (const float*)d_in[2];
    const float* w1     = (const float*)d_in[3];
    const float* b1     = (const float*)d_in[4];
    const float* w2     = (const float*)d_in[5];
    const float* b2     = (const float*)d_in[6];
    const float* basem  = (const float*)d_in[7];
    const float* hebU   = (const float*)d_in[8];
    const float* hebV   = (const float*)d_in[9];
    const float* dec    = (const float*)d_in[10];
    float* out = (float*)d_out;

    float *qs, *vs, *outsp, *part, *sig, *metric, *hebM;
    cudaGetSymbolAddress((void**)&qs, g_qs);
    cudaGetSymbolAddress((void**)&vs, g_vs);
    cudaGetSymbolAddress((void**)&outsp, g_outsp);
    cudaGetSymbolAddress((void**)&part, g_part);
    cudaGetSymbolAddress((void**)&sig, g_sig);
    cudaGetSymbolAddress((void**)&metric, g_metric);
    cudaGetSymbolAddress((void**)&hebM, g_heb);

    const int attn_smem = (2 * NROWS * RSTR + 128) * (int)sizeof(float);
    cudaFuncSetAttribute(attn_kernel, cudaFuncAttributeMaxDynamicSharedMemorySize, attn_smem);

    // 1: both sparse encoders in one launch (relu fused)
    gemm_enc<<<dim3(MT / 128, 1, 16), 256>>>(x, enc_q, enc_v, qs, vs);

    // 2: hebbian matrices
    heb_kernel<<<NH, HD>>>(hebU, hebV, hebM);

    // 3,4: sig reduction (2-phase, fp32)
    reduce_sig_a<<<dim3(BB, SP / 128, TCH), 128>>>(qs, part);
    reduce_sig_b<<<dim3(BB, SP / 128), 128>>>(part, sig);

    // 5: metric MLP
    metric_kernel<<<BB, 512>>>(sig, w1, b1, w2, b2, basem, metric);

    // 6: windowed top-K attention
    attn_kernel<<<dim3(TT / TTILE, NH, BB), 128, attn_smem>>>(qs, vs, metric, hebM, outsp);

    // 7: decoder
    gemm_dec<<<dim3(MT / 128, SP / 128), 256>>>(outsp, dec, out);
}

// round 3
// speedup vs baseline: 1.4804x; 1.2711x over previous
#include <cuda_runtime.h>
#include <cuda_bf16.h>
#include <math.h>

// Problem constants
#define BB 2
#define TT 2048
#define DENSE 1024
#define NH 8
#define HD 128
#define WIN 64
#define TOPK 32
#define MT (BB*TT)          // 4096 rows
#define SP 1024             // NH*HD
#define TCH 8               // t-chunks for sig reduction

// GEMM tiling
#define KTOT 1024           // all three GEMMs have K = 1024
#define KC2 32              // k-chunk
#define STR 40              // smem row stride in bf16 elems (80B, conflict-free)
#define TILE_ELE (128*STR)  // 5120 elems per tile buffer
#define GEMM_SMEM (8*TILE_ELE*2)  // 4 matrices x 2 buffers x 2B = 81920 B

typedef unsigned short ushort_t;
typedef unsigned int uint32;

// ---------------- device scratch ----------------
__device__ float    g_qs[MT * SP];
__device__ float    g_vs[MT * SP];
__device__ ushort_t g_x_hi[MT * DENSE];
__device__ ushort_t g_x_lo[MT * DENSE];
__device__ ushort_t g_btq_hi[SP * DENSE];   // [n=h*128+e][k=d]
__device__ ushort_t g_btq_lo[SP * DENSE];
__device__ ushort_t g_btv_hi[SP * DENSE];
__device__ ushort_t g_btv_lo[SP * DENSE];
__device__ ushort_t g_btd_hi[DENSE * SP];   // [n][k]
__device__ ushort_t g_btd_lo[DENSE * SP];
__device__ ushort_t g_os_hi[MT * SP];       // outsp hi/lo
__device__ ushort_t g_os_lo[MT * SP];
__device__ float    g_part[2 * BB * TCH * SP];
__device__ float    g_sig[BB * SP];
__device__ float    g_metric[BB * SP];
__device__ float    g_heb[NH * HD * HD];

// ---------------- asm helpers ----------------
__device__ __forceinline__ unsigned smem_u32(const void* p) {
    return (unsigned)__cvta_generic_to_shared(p);
}
__device__ __forceinline__ void cp16(unsigned dst, const void* src) {
    asm volatile("cp.async.cg.shared.global [%0], [%1], 16;" :: "r"(dst), "l"(src));
}
__device__ __forceinline__ void cp_commit() { asm volatile("cp.async.commit_group;"); }
template<int N> __device__ __forceinline__ void cp_wait() {
    asm volatile("cp.async.wait_group %0;" :: "n"(N));
}
__device__ __forceinline__ void ldsm4(uint32& r0, uint32& r1, uint32& r2, uint32& r3,
                                      unsigned addr) {
    asm volatile("ldmatrix.sync.aligned.m8n8.x4.shared.b16 {%0,%1,%2,%3}, [%4];"
                 : "=r"(r0), "=r"(r1), "=r"(r2), "=r"(r3) : "r"(addr));
}
__device__ __forceinline__ void mma16816(float* d, const uint32* a, const uint32* b) {
    asm volatile(
        "mma.sync.aligned.m16n8k16.row.col.f32.bf16.bf16.f32 "
        "{%0,%1,%2,%3}, {%4,%5,%6,%7}, {%8,%9}, {%0,%1,%2,%3};"
        : "+f"(d[0]), "+f"(d[1]), "+f"(d[2]), "+f"(d[3])
        : "r"(a[0]), "r"(a[1]), "r"(a[2]), "r"(a[3]), "r"(b[0]), "r"(b[1]));
}
__device__ __forceinline__ void split_bf16(float v, ushort_t& hi, ushort_t& lo) {
    __nv_bfloat16 h = __float2bfloat16_rn(v);
    float hf = __bfloat162float(h);
    __nv_bfloat16 l = __float2bfloat16_rn(v - hf);
    hi = __bfloat16_as_ushort(h);
    lo = __bfloat16_as_ushort(l);
}

// ---------------- split / transpose-split kernels ----------------
__global__ void split_x_kernel(const float* __restrict__ x,
                               ushort_t* __restrict__ xhi, ushort_t* __restrict__ xlo)
{
    int i = (blockIdx.x * 256 + threadIdx.x) * 4;
    float4 v = *reinterpret_cast<const float4*>(x + i);
    ushort_t h0,l0,h1,l1,h2,l2,h3,l3;
    split_bf16(v.x,h0,l0); split_bf16(v.y,h1,l1);
    split_bf16(v.z,h2,l2); split_bf16(v.w,h3,l3);
    ushort4 hv = {h0,h1,h2,h3}, lv = {l0,l1,l2,l3};
    *reinterpret_cast<ushort4*>(xhi + i) = hv;
    *reinterpret_cast<ushort4*>(xlo + i) = lv;
}

// In: [K rows=1024][N cols], row stride nld. Out[n][k] (ld = 1024), split hi/lo.
__global__ void transpose_split_kernel(const float* __restrict__ In, int nld,
                                       ushort_t* __restrict__ outHi, ushort_t* __restrict__ outLo,
                                       long strideIn, long strideOut)
{
    __shared__ float tile[32][33];
    const float* in = In + (long)blockIdx.z * strideIn;
    ushort_t* oh = outHi + (long)blockIdx.z * strideOut;
    ushort_t* ol = outLo + (long)blockIdx.z * strideOut;
    int k0 = blockIdx.x * 32, n0 = blockIdx.y * 32;
    int tx = threadIdx.x, ty = threadIdx.y;
#pragma unroll
    for (int i = 0; i < 4; i++) {
        int k = ty * 4 + i;
        tile[k][tx] = in[(size_t)(k0 + k) * nld + n0 + tx];
    }
    __syncthreads();
#pragma unroll
    for (int i = 0; i < 4; i++) {
        int n = ty * 4 + i;
        float v = tile[tx][n];
        ushort_t h, l; split_bf16(v, h, l);
        oh[(size_t)(n0 + n) * 1024 + k0 + tx] = h;
        ol[(size_t)(n0 + n) * 1024 + k0 + tx] = l;
    }
}

// ---------------- bf16 split-precision GEMM core ----------------
// A panels: 128 rows x 1024 (hi/lo), B panels: 128 n-rows x 1024 K-major (hi/lo).
// C: 128x128 fp32, ld = ldc. 256 threads.
__device__ __forceinline__ void gemm_core(
    const ushort_t* __restrict__ Ah, const ushort_t* __restrict__ Al,
    const ushort_t* __restrict__ Bh, const ushort_t* __restrict__ Bl,
    float* __restrict__ Cblk, int ldc, int relu)
{
    extern __shared__ ushort_t smem[];
    ushort_t* sA_hi = smem;                    // [2][TILE_ELE]
    ushort_t* sA_lo = sA_hi + 2 * TILE_ELE;
    ushort_t* sB_hi = sA_lo + 2 * TILE_ELE;
    ushort_t* sB_lo = sB_hi + 2 * TILE_ELE;

    const int tid = threadIdx.x;
    const int warp = tid >> 5, lane = tid & 31;
    const int wm = warp & 3, wn = warp >> 2;

    // gmem->smem chunk mapping: 2 chunks of 16B per thread per matrix
    const int c0 = tid * 2;
    const int ldRow0 = c0 >> 2, ldK0 = (c0 & 3) * 8;
    const int ldRow1 = (c0 + 1) >> 2, ldK1 = ((c0 + 1) & 3) * 8;

#define LOAD_TILE(dst, src, k0)                                                   \
    {                                                                             \
        cp16(smem_u32((dst) + ldRow0 * STR + ldK0), (src) + (size_t)ldRow0 * KTOT + (k0) + ldK0); \
        cp16(smem_u32((dst) + ldRow1 * STR + ldK1), (src) + (size_t)ldRow1 * KTOT + (k0) + ldK1); \
    }

    // fragment smem byte offsets (per thread)
    unsigned aOff[2], bOff[4];
#pragma unroll
    for (int mt = 0; mt < 2; mt++)
        aOff[mt] = (unsigned)(((wm * 32 + mt * 16 + (lane & 15)) * STR + (lane >> 4) * 8) * 2);
#pragma unroll
    for (int g = 0; g < 4; g++)
        bOff[g] = (unsigned)(((wn * 64 + g * 16 + (lane & 7) + (lane >> 4) * 8) * STR
                              + ((lane >> 3) & 1) * 8) * 2);

    float acc[2][8][4];
#pragma unroll
    for (int mt = 0; mt < 2; mt++)
#pragma unroll
        for (int nt = 0; nt < 8; nt++)
#pragma unroll
            for (int r = 0; r < 4; r++) acc[mt][nt][r] = 0.f;

    // prefetch chunk 0
    LOAD_TILE(sA_hi, Ah, 0); LOAD_TILE(sA_lo, Al, 0);
    LOAD_TILE(sB_hi, Bh, 0); LOAD_TILE(sB_lo, Bl, 0);
    cp_commit();

    const int nk = KTOT / KC2;   // 32
    for (int i = 0; i < nk; i++) {
        if (i + 1 < nk) {
            const int k0 = (i + 1) * KC2;
            ushort_t* dA_hi = sA_hi + ((i + 1) & 1) * TILE_ELE;
            ushort_t* dA_lo = sA_lo + ((i + 1) & 1) * TILE_ELE;
            ushort_t* dB_hi = sB_hi + ((i + 1) & 1) * TILE_ELE;
            ushort_t* dB_lo = sB_lo + ((i + 1) & 1) * TILE_ELE;
            LOAD_TILE(dA_hi, Ah, k0); LOAD_TILE(dA_lo, Al, k0);
            LOAD_TILE(dB_hi, Bh, k0); LOAD_TILE(dB_lo, Bl, k0);
            cp_commit();
            cp_wait<1>();
        } else {
            cp_wait<0>();
        }
        __syncthreads();

        const unsigned bufAh = smem_u32(sA_hi + (i & 1) * TILE_ELE);
        const unsigned bufAl = smem_u32(sA_lo + (i & 1) * TILE_ELE);
        const unsigned bufBh = smem_u32(sB_hi + (i & 1) * TILE_ELE);
        const unsigned bufBl = smem_u32(sB_lo + (i & 1) * TILE_ELE);

#pragma unroll
        for (int s = 0; s < 2; s++) {
            uint32 ah[2][4], al[2][4];
#pragma unroll
            for (int mt = 0; mt < 2; mt++) {
                ldsm4(ah[mt][0], ah[mt][1], ah[mt][2], ah[mt][3], bufAh + aOff[mt] + s * 32);
                ldsm4(al[mt][0], al[mt][1], al[mt][2], al[mt][3], bufAl + aOff[mt] + s * 32);
            }
            uint32 bh[8][2], bl[8][2];
#pragma unroll
            for (int g = 0; g < 4; g++) {
                uint32 r0, r1, r2, r3;
                ldsm4(r0, r1, r2, r3, bufBh + bOff[g] + s * 32);
                bh[2*g][0] = r0; bh[2*g][1] = r1; bh[2*g+1][0] = r2; bh[2*g+1][1] = r3;
                ldsm4(r0, r1, r2, r3, bufBl + bOff[g] + s * 32);
                bl[2*g][0] = r0; bl[2*g][1] = r1; bl[2*g+1][0] = r2; bl[2*g+1][1] = r3;
            }
#pragma unroll
            for (int mt = 0; mt < 2; mt++)
#pragma unroll
                for (int nt = 0; nt < 8; nt++) {
                    mma16816(acc[mt][nt], ah[mt], bh[nt]);
                    mma16816(acc[mt][nt], ah[mt], bl[nt]);
                    mma16816(acc[mt][nt], al[mt], bh[nt]);
                }
        }
        __syncthreads();
    }

    // epilogue
#pragma unroll
    for (int mt = 0; mt < 2; mt++) {
        const int r0 = wm * 32 + mt * 16 + (lane >> 2);
#pragma unroll
        for (int nt = 0; nt < 8; nt++) {
            const int c = wn * 64 + nt * 8 + 2 * (lane & 3);
            float2 v0 = { acc[mt][nt][0], acc[mt][nt][1] };
            float2 v1 = { acc[mt][nt][2], acc[mt][nt][3] };
            if (relu) {
                v0.x = fmaxf(v0.x, 0.f); v0.y = fmaxf(v0.y, 0.f);
                v1.x = fmaxf(v1.x, 0.f); v1.y = fmaxf(v1.y, 0.f);
            }
            *reinterpret_cast<float2*>(Cblk + (size_t)r0 * ldc + c) = v0;
            *reinterpret_cast<float2*>(Cblk + (size_t)(r0 + 8) * ldc + c) = v1;
        }
    }
#undef LOAD_TILE
}

// Encoder: grid (32, 16): y<8 -> q head y; y>=8 -> v head y-8
__global__ __launch_bounds__(256) void gemm_enc_bf16(
    const ushort_t* __restrict__ xhi, const ushort_t* __restrict__ xlo,
    const ushort_t* __restrict__ bqh, const ushort_t* __restrict__ bql,
    const ushort_t* __restrict__ bvh, const ushort_t* __restrict__ bvl,
    float* __restrict__ qs, float* __restrict__ vs)
{
    const int y = blockIdx.y;
    const int isV = y >> 3, head = y & 7;
    const ushort_t* Bh = (isV ? bvh : bqh) + (size_t)head * 128 * KTOT;
    const ushort_t* Bl = (isV ? bvl : bql) + (size_t)head * 128 * KTOT;
    float* C = (isV ? vs : qs) + (size_t)blockIdx.x * 128 * SP + head * 128;
    gemm_core(xhi + (size_t)blockIdx.x * 128 * KTOT, xlo + (size_t)blockIdx.x * 128 * KTOT,
              Bh, Bl, C, SP, 1);
}

// Decoder: grid (32, 8)
__global__ __launch_bounds__(256) void gemm_dec_bf16(
    const ushort_t* __restrict__ ahi, const ushort_t* __restrict__ alo,
    const ushort_t* __restrict__ bh, const ushort_t* __restrict__ bl,
    float* __restrict__ out)
{
    gemm_core(ahi + (size_t)blockIdx.x * 128 * KTOT, alo + (size_t)blockIdx.x * 128 * KTOT,
              bh + (size_t)blockIdx.y * 128 * KTOT, bl + (size_t)blockIdx.y * 128 * KTOT,
              out + (size_t)blockIdx.x * 128 * DENSE + blockIdx.y * 128, DENSE, 0);
}

// ---------------- sig reduction ----------------
__global__ void reduce_sig_a(const float* __restrict__ qs, float* __restrict__ part)
{
    const int b = blockIdx.x;
    const int col = blockIdx.y * 128 + threadIdx.x;
    const int tz = blockIdx.z;
    const int t0 = tz * (TT / TCH);
    const float* p = qs + ((size_t)b * TT + t0) * SP + col;
    float s = 0.f, s8 = 0.f;
#pragma unroll 4
    for (int t = 0; t < TT / TCH; t++) {
        float v = p[(size_t)t * SP];
        s += v;
        if (((t0 + t) & 7) == 0) s8 += v;
    }
    part[((size_t)b * TCH + tz) * SP + col] = s;
    part[(size_t)BB * TCH * SP + ((size_t)b * TCH + tz) * SP + col] = s8;
}

__global__ void reduce_sig_b(const float* __restrict__ part, float* __restrict__ sig)
{
    const int b = blockIdx.x;
    const int col = blockIdx.y * 128 + threadIdx.x;
    float s = 0.f, s8 = 0.f;
#pragma unroll
    for (int z = 0; z < TCH; z++) {
        s  += part[((size_t)b * TCH + z) * SP + col];
        s8 += part[(size_t)BB * TCH * SP + ((size_t)b * TCH + z) * SP + col];
    }
    sig[b * SP + col] = s * (1.f / TT) + 0.5f * s8 * (1.f / (TT / 8));
}

// ---------------- metric MLP ----------------
__global__ __launch_bounds__(512) void metric_kernel(
    const float* __restrict__ sig, const float* __restrict__ w1, const float* __restrict__ b1,
    const float* __restrict__ w2, const float* __restrict__ b2, const float* __restrict__ base,
    float* __restrict__ metric)
{
    __shared__ float sig_s[SP];
    __shared__ float h_s[SP / 2];
    int b = blockIdx.x, tid = threadIdx.x;
    sig_s[tid] = sig[b * SP + tid];
    sig_s[tid + 512] = sig[b * SP + tid + 512];
    __syncthreads();

    float acc = b1[tid];
    for (int d = 0; d < SP; d++) acc = fmaf(sig_s[d], w1[d * 512 + tid], acc);
    h_s[tid] = 0.5f * acc * (1.f + erff(acc * 0.7071067811865475f));
    __syncthreads();

    for (int half = 0; half < 2; half++) {
        int col = tid + half * 512;
        float m = b2[col];
        for (int k = 0; k < 512; k++) m = fmaf(h_s[k], w2[k * SP + col], m);
        float xv = base[col] + 0.1f * m;
        metric[b * SP + col] = fmaxf(xv, 0.f) + log1pf(expf(-fabsf(xv)));
    }
}

// ---------------- Hebbian U@V ----------------
__global__ void heb_kernel(const float* __restrict__ U, const float* __restrict__ V,
                           float* __restrict__ hebM)
{
    int h = blockIdx.x, i = threadIdx.x;
    float u[32];
#pragma unroll
    for (int r = 0; r < 32; r++) u[r] = U[h * HD * 32 + i * 32 + r];
    const float* Vh = V + h * 32 * HD;
    for (int j = 0; j < HD; j++) {
        float s = 0.f;
#pragma unroll
        for (int r = 0; r < 32; r++) s = fmaf(u[r], Vh[r * HD + j], s);
        hebM[h * HD * HD + i * HD + j] = s;
    }
}

// ---------------- windowed metric attention ----------------
#define TTILE 16
#define NROWS 79
#define RSTR 129

__global__ __launch_bounds__(128) void attn_kernel(
    const float* __restrict__ qs, const float* __restrict__ vs,
    const float* __restrict__ metric, const float* __restrict__ hebM,
    ushort_t* __restrict__ osHi, ushort_t* __restrict__ osLo)
{
    extern __shared__ float sm[];
    float* q_s = sm;
    float* v_s = q_s + NROWS * RSTR;
    float* met_s = v_s + NROWS * RSTR;
    __shared__ float d_s[4][WIN];
    __shared__ float wsel[4][TOPK];
    __shared__ int   rsel[4][TOPK];

    const int t0 = blockIdx.x * TTILE;
    const int h = blockIdx.y;
    const int b = blockIdx.z;
    const int tid = threadIdx.x;
    const int warp = tid >> 5, lane = tid & 31;

    const size_t baseRow = (size_t)b * TT * SP;
    for (int i = tid; i < NROWS * HD; i += 128) {
        int s = i >> 7, e = i & 127;
        int g = t0 - (WIN - 1) + s; if (g < 0) g = 0;
        size_t gi = baseRow + (size_t)g * SP + h * HD + e;
        q_s[s * RSTR + e] = qs[gi];
        v_s[s * RSTR + e] = vs[gi];
    }
    met_s[tid & 127] = metric[b * SP + h * HD + (tid & 127)];
    __syncthreads();

    const float* HM = hebM + h * HD * HD;

    for (int it = 0; it < 4; it++) {
        const int t = t0 + warp * 4 + it;
        const int qrow = t - t0 + (WIN - 1);
        const float* qr = q_s + qrow * RSTR;

        int gg0 = t - lane;        if (gg0 < 0) gg0 = 0;
        int gg1 = t - lane - 32;   if (gg1 < 0) gg1 = 0;
        const int r0 = gg0 - t0 + (WIN - 1);
        const int r1 = gg1 - t0 + (WIN - 1);
        const float* p0 = q_s + r0 * RSTR;
        const float* p1 = q_s + r1 * RSTR;

        float d0 = 0.f, d1 = 0.f;
#pragma unroll 8
        for (int e = 0; e < HD; e++) {
            float qv = qr[e], m = met_s[e];
            float a = qv - p0[e]; d0 = fmaf(a * a, m, d0);
            float c = qv - p1[e]; d1 = fmaf(c * c, m, d1);
        }
        float dist0 = sqrtf(d0 + 1e-8f);
        float dist1 = sqrtf(d1 + 1e-8f);
        d_s[warp][lane] = dist0;
        d_s[warp][lane + 32] = dist1;
        __syncwarp();

        int rk0 = 0, rk1 = 0;
        const int j1 = lane + 32;
#pragma unroll 8
        for (int j = 0; j < WIN; j++) {
            float dj = d_s[warp][j];
            rk0 += (dj < dist0) || (dj == dist0 && j < lane);
            rk1 += (dj < dist1) || (dj == dist1 && j < j1);
        }
        if (rk0 < TOPK) { wsel[warp][rk0] = expf(-dist0); rsel[warp][rk0] = r0; }
        if (rk1 < TOPK) { wsel[warp][rk1] = expf(-dist1); rsel[warp][rk1] = r1; }
        __syncwarp();

        float wsum = wsel[warp][lane];
#pragma unroll
        for (int o = 16; o; o >>= 1) wsum += __shfl_xor_sync(0xffffffffu, wsum, o);
        const float inv = 1.f / (wsum + 1e-8f);

        float c0 = 0.f, c1 = 0.f, c2 = 0.f, c3 = 0.f;
#pragma unroll 4
        for (int k = 0; k < TOPK; k++) {
            float wk = wsel[warp][k];
            const float* vr = v_s + rsel[warp][k] * RSTR;
            c0 = fmaf(wk, vr[lane], c0);
            c1 = fmaf(wk, vr[lane + 32], c1);
            c2 = fmaf(wk, vr[lane + 64], c2);
            c3 = fmaf(wk, vr[lane + 96], c3);
        }
        c0 *= inv; c1 *= inv; c2 *= inv; c3 *= inv;

        const float q0 = qr[lane], q1 = qr[lane + 32], q2 = qr[lane + 64], q3 = qr[lane + 96];
        float nq = q0 * q0 + q1 * q1 + q2 * q2 + q3 * q3;
#pragma unroll
        for (int o = 16; o; o >>= 1) nq += __shfl_xor_sync(0xffffffffu, nq, o);
        const float nrm = sqrtf(nq);

        if (nrm > 0.2f) {
            const float qinv = 1.f / fmaxf(nrm, 1e-12f);
            float h0 = 0.f, h1 = 0.f, h2 = 0.f, h3 = 0.f;
#pragma unroll 4
            for (int e = 0; e < HD; e++) {
                float qe = qr[e] * qinv;
                const float* hm = HM + e * HD;
                h0 = fmaf(qe, __ldg(hm + lane), h0);
                h1 = fmaf(qe, __ldg(hm + lane + 32), h1);
                h2 = fmaf(qe, __ldg(hm + lane + 64), h2);
                h3 = fmaf(qe, __ldg(hm + lane + 96), h3);
            }
            c0 += 0.1f * h0; c1 += 0.1f * h1; c2 += 0.1f * h2; c3 += 0.1f * h3;
        }

        size_t ob = baseRow + (size_t)t * SP + h * HD;
        ushort_t hh, ll;
        split_bf16(q0 * c0, hh, ll); osHi[ob + lane]      = hh; osLo[ob + lane]      = ll;
        split_bf16(q1 * c1, hh, ll); osHi[ob + lane + 32] = hh; osLo[ob + lane + 32] = ll;
        split_bf16(q2 * c2, hh, ll); osHi[ob + lane + 64] = hh; osLo[ob + lane + 64] = ll;
        split_bf16(q3 * c3, hh, ll); osHi[ob + lane + 96] = hh; osLo[ob + lane + 96] = ll;
    }
}

// ---------------- launcher ----------------
extern "C" void kernel_launch(void* const* d_in, const int* in_sizes, int n_in,
                              void* d_out, int out_size)
{
    const float* x      = (const float*)d_in[0];
    const float* enc_q  = (const float*)d_in[1];
    const float* enc_v  = (const float*)d_in[2];
    const float* w1     = (const float*)d_in[3];
    const float* b1     = (const float*)d_in[4];
    const float* w2     = (const float*)d_in[5];
    const float* b2     = (const float*)d_in[6];
    const float* basem  = (const float*)d_in[7];
    const float* hebU   = (const float*)d_in[8];
    const float* hebV   = (const float*)d_in[9];
    const float* dec    = (const float*)d_in[10];
    float* out = (float*)d_out;

    float *qs, *vs, *part, *sig, *metric, *hebM;
    ushort_t *xhi, *xlo, *bqh, *bql, *bvh, *bvl, *bdh, *bdl, *oshi, *oslo;
    cudaGetSymbolAddress((void**)&qs, g_qs);
    cudaGetSymbolAddress((void**)&vs, g_vs);
    cudaGetSymbolAddress((void**)&part, g_part);
    cudaGetSymbolAddress((void**)&sig, g_sig);
    cudaGetSymbolAddress((void**)&metric, g_metric);
    cudaGetSymbolAddress((void**)&hebM, g_heb);
    cudaGetSymbolAddress((void**)&xhi, g_x_hi);
    cudaGetSymbolAddress((void**)&xlo, g_x_lo);
    cudaGetSymbolAddress((void**)&bqh, g_btq_hi);
    cudaGetSymbolAddress((void**)&bql, g_btq_lo);
    cudaGetSymbolAddress((void**)&bvh, g_btv_hi);
    cudaGetSymbolAddress((void**)&bvl, g_btv_lo);
    cudaGetSymbolAddress((void**)&bdh, g_btd_hi);
    cudaGetSymbolAddress((void**)&bdl, g_btd_lo);
    cudaGetSymbolAddress((void**)&oshi, g_os_hi);
    cudaGetSymbolAddress((void**)&oslo, g_os_lo);

    const int attn_smem = (2 * NROWS * RSTR + 128) * (int)sizeof(float);
    cudaFuncSetAttribute(attn_kernel, cudaFuncAttributeMaxDynamicSharedMemorySize, attn_smem);
    cudaFuncSetAttribute(gemm_enc_bf16, cudaFuncAttributeMaxDynamicSharedMemorySize, GEMM_SMEM);
    cudaFuncSetAttribute(gemm_dec_bf16, cudaFuncAttributeMaxDynamicSharedMemorySize, GEMM_SMEM);

    // 0: split/transpose inputs to bf16 hi/lo
    split_x_kernel<<<MT * DENSE / 1024, 256>>>(x, xhi, xlo);
    transpose_split_kernel<<<dim3(32, 4, NH), dim3(32, 8)>>>(enc_q, HD, bqh, bql,
                                                             (long)DENSE * HD, (long)HD * DENSE);
    transpose_split_kernel<<<dim3(32, 4, NH), dim3(32, 8)>>>(enc_v, HD, bvh, bvl,
                                                             (long)DENSE * HD, (long)HD * DENSE);
    transpose_split_kernel<<<dim3(32, 32, 1), dim3(32, 8)>>>(dec, DENSE, bdh, bdl, 0, 0);

    // 1: both sparse encoders, tensor cores (relu fused)
    gemm_enc_bf16<<<dim3(MT / 128, 16), 256, GEMM_SMEM>>>(xhi, xlo, bqh, bql, bvh, bvl, qs, vs);

    // 2: hebbian matrices
    heb_kernel<<<NH, HD>>>(hebU, hebV, hebM);

    // 3,4: sig reduction
    reduce_sig_a<<<dim3(BB, SP / 128, TCH), 128>>>(qs, part);
    reduce_sig_b<<<dim3(BB, SP / 128), 128>>>(part, sig);

    // 5: metric MLP
    metric_kernel<<<BB, 512>>>(sig, w1, b1, w2, b2, basem, metric);

    // 6: attention -> outsp (bf16 hi/lo directly)
    attn_kernel<<<dim3(TT / TTILE, NH, BB), 128, attn_smem>>>(qs, vs, metric, hebM, oshi, oslo);

    // 7: decoder, tensor cores
    gemm_dec_bf16<<<dim3(MT / 128, SP / 128), 256, GEMM_SMEM>>>(oshi, oslo, bdh, bdl, out);
}

// round 5
// speedup vs baseline: 1.5413x; 1.0412x over previous
#include <cuda_runtime.h>
#include <cuda_bf16.h>
#include <math.h>

// Problem constants
#define BB 2
#define TT 2048
#define DENSE 1024
#define NH 8
#define HD 128
#define WIN 64
#define TOPK 32
#define MT (BB*TT)          // 4096 rows
#define SP 1024             // NH*HD
#define TCH 8               // t-chunks for sig reduction

// GEMM tiling
#define KTOT 1024
#define KC2 32
#define STR 40              // smem row stride in bf16 elems (80B, conflict-free)
#define TILE_ELE (128*STR)
#define GEMM_SMEM (8*TILE_ELE*2)  // 81920 B

typedef unsigned short ushort_t;
typedef unsigned int uint32;

// ---------------- device scratch ----------------
__device__ float    g_qs[MT * SP];
__device__ float    g_vs[MT * SP];
__device__ ushort_t g_x_hi[MT * DENSE];
__device__ ushort_t g_x_lo[MT * DENSE];
__device__ ushort_t g_btq_hi[SP * DENSE];
__device__ ushort_t g_btq_lo[SP * DENSE];
__device__ ushort_t g_btv_hi[SP * DENSE];
__device__ ushort_t g_btv_lo[SP * DENSE];
__device__ ushort_t g_btd_hi[DENSE * SP];
__device__ ushort_t g_btd_lo[DENSE * SP];
__device__ ushort_t g_os_hi[MT * SP];
__device__ ushort_t g_os_lo[MT * SP];
__device__ float    g_part[2 * BB * TCH * SP];
__device__ float    g_sig[BB * SP];
__device__ float    g_hbuf[BB * (SP/2)];
__device__ float    g_metric[BB * SP];
__device__ float    g_heb[NH * HD * HD];

// ---------------- asm helpers ----------------
__device__ __forceinline__ unsigned smem_u32(const void* p) {
    return (unsigned)__cvta_generic_to_shared(p);
}
__device__ __forceinline__ void cp16(unsigned dst, const void* src) {
    asm volatile("cp.async.cg.shared.global [%0], [%1], 16;" :: "r"(dst), "l"(src));
}
__device__ __forceinline__ void cp_commit() { asm volatile("cp.async.commit_group;"); }
template<int N> __device__ __forceinline__ void cp_wait() {
    asm volatile("cp.async.wait_group %0;" :: "n"(N));
}
__device__ __forceinline__ void ldsm4(uint32& r0, uint32& r1, uint32& r2, uint32& r3,
                                      unsigned addr) {
    asm volatile("ldmatrix.sync.aligned.m8n8.x4.shared.b16 {%0,%1,%2,%3}, [%4];"
                 : "=r"(r0), "=r"(r1), "=r"(r2), "=r"(r3) : "r"(addr));
}
__device__ __forceinline__ void mma16816(float* d, const uint32* a, const uint32* b) {
    asm volatile(
        "mma.sync.aligned.m16n8k16.row.col.f32.bf16.bf16.f32 "
        "{%0,%1,%2,%3}, {%4,%5,%6,%7}, {%8,%9}, {%0,%1,%2,%3};"
        : "+f"(d[0]), "+f"(d[1]), "+f"(d[2]), "+f"(d[3])
        : "r"(a[0]), "r"(a[1]), "r"(a[2]), "r"(a[3]), "r"(b[0]), "r"(b[1]));
}
__device__ __forceinline__ void split_bf16(float v, ushort_t& hi, ushort_t& lo) {
    __nv_bfloat16 h = __float2bfloat16_rn(v);
    float hf = __bfloat162float(h);
    __nv_bfloat16 l = __float2bfloat16_rn(v - hf);
    hi = __bfloat16_as_ushort(h);
    lo = __bfloat16_as_ushort(l);
}

// ---------------- split / transpose-split kernels ----------------
__global__ void split_x_kernel(const float* __restrict__ x,
                               ushort_t* __restrict__ xhi, ushort_t* __restrict__ xlo)
{
    int i = (blockIdx.x * 256 + threadIdx.x) * 4;
    float4 v = *reinterpret_cast<const float4*>(x + i);
    ushort_t h0,l0,h1,l1,h2,l2,h3,l3;
    split_bf16(v.x,h0,l0); split_bf16(v.y,h1,l1);
    split_bf16(v.z,h2,l2); split_bf16(v.w,h3,l3);
    ushort4 hv = {h0,h1,h2,h3}, lv = {l0,l1,l2,l3};
    *reinterpret_cast<ushort4*>(xhi + i) = hv;
    *reinterpret_cast<ushort4*>(xlo + i) = lv;
}

__global__ void transpose_split_kernel(const float* __restrict__ In, int nld,
                                       ushort_t* __restrict__ outHi, ushort_t* __restrict__ outLo,
                                       long strideIn, long strideOut)
{
    __shared__ float tile[32][33];
    const float* in = In + (long)blockIdx.z * strideIn;
    ushort_t* oh = outHi + (long)blockIdx.z * strideOut;
    ushort_t* ol = outLo + (long)blockIdx.z * strideOut;
    int k0 = blockIdx.x * 32, n0 = blockIdx.y * 32;
    int tx = threadIdx.x, ty = threadIdx.y;
#pragma unroll
    for (int i = 0; i < 4; i++) {
        int k = ty * 4 + i;
        tile[k][tx] = in[(size_t)(k0 + k) * nld + n0 + tx];
    }
    __syncthreads();
#pragma unroll
    for (int i = 0; i < 4; i++) {
        int n = ty * 4 + i;
        float v = tile[tx][n];
        ushort_t h, l; split_bf16(v, h, l);
        oh[(size_t)(n0 + n) * 1024 + k0 + tx] = h;
        ol[(size_t)(n0 + n) * 1024 + k0 + tx] = l;
    }
}

// ---------------- bf16 split-precision HMMA GEMM core ----------------
__device__ __forceinline__ void gemm_core(
    const ushort_t* __restrict__ Ah, const ushort_t* __restrict__ Al,
    const ushort_t* __restrict__ Bh, const ushort_t* __restrict__ Bl,
    float* __restrict__ Cblk, int ldc, int relu)
{
    extern __shared__ ushort_t smem[];
    ushort_t* sA_hi = smem;
    ushort_t* sA_lo = sA_hi + 2 * TILE_ELE;
    ushort_t* sB_hi = sA_lo + 2 * TILE_ELE;
    ushort_t* sB_lo = sB_hi + 2 * TILE_ELE;

    const int tid = threadIdx.x;
    const int warp = tid >> 5, lane = tid & 31;
    const int wm = warp & 3, wn = warp >> 2;

    const int c0 = tid * 2;
    const int ldRow0 = c0 >> 2, ldK0 = (c0 & 3) * 8;
    const int ldRow1 = (c0 + 1) >> 2, ldK1 = ((c0 + 1) & 3) * 8;

#define LOAD_TILE(dst, src, k0)                                                   \
    {                                                                             \
        cp16(smem_u32((dst) + ldRow0 * STR + ldK0), (src) + (size_t)ldRow0 * KTOT + (k0) + ldK0); \
        cp16(smem_u32((dst) + ldRow1 * STR + ldK1), (src) + (size_t)ldRow1 * KTOT + (k0) + ldK1); \
    }

    unsigned aOff[2], bOff[4];
#pragma unroll
    for (int mt = 0; mt < 2; mt++)
        aOff[mt] = (unsigned)(((wm * 32 + mt * 16 + (lane & 15)) * STR + (lane >> 4) * 8) * 2);
#pragma unroll
    for (int g = 0; g < 4; g++)
        bOff[g] = (unsigned)(((wn * 64 + g * 16 + (lane & 7) + (lane >> 4) * 8) * STR
                              + ((lane >> 3) & 1) * 8) * 2);

    float acc[2][8][4];
#pragma unroll
    for (int mt = 0; mt < 2; mt++)
#pragma unroll
        for (int nt = 0; nt < 8; nt++)
#pragma unroll
            for (int r = 0; r < 4; r++) acc[mt][nt][r] = 0.f;

    LOAD_TILE(sA_hi, Ah, 0); LOAD_TILE(sA_lo, Al, 0);
    LOAD_TILE(sB_hi, Bh, 0); LOAD_TILE(sB_lo, Bl, 0);
    cp_commit();

    const int nk = KTOT / KC2;
    for (int i = 0; i < nk; i++) {
        if (i + 1 < nk) {
            const int k0 = (i + 1) * KC2;
            ushort_t* dA_hi = sA_hi + ((i + 1) & 1) * TILE_ELE;
            ushort_t* dA_lo = sA_lo + ((i + 1) & 1) * TILE_ELE;
            ushort_t* dB_hi = sB_hi + ((i + 1) & 1) * TILE_ELE;
            ushort_t* dB_lo = sB_lo + ((i + 1) & 1) * TILE_ELE;
            LOAD_TILE(dA_hi, Ah, k0); LOAD_TILE(dA_lo, Al, k0);
            LOAD_TILE(dB_hi, Bh, k0); LOAD_TILE(dB_lo, Bl, k0);
            cp_commit();
            cp_wait<1>();
        } else {
            cp_wait<0>();
        }
        __syncthreads();

        const unsigned bufAh = smem_u32(sA_hi + (i & 1) * TILE_ELE);
        const unsigned bufAl = smem_u32(sA_lo + (i & 1) * TILE_ELE);
        const unsigned bufBh = smem_u32(sB_hi + (i & 1) * TILE_ELE);
        const unsigned bufBl = smem_u32(sB_lo + (i & 1) * TILE_ELE);

#pragma unroll
        for (int s = 0; s < 2; s++) {
            uint32 ah[2][4], al[2][4];
#pragma unroll
            for (int mt = 0; mt < 2; mt++) {
                ldsm4(ah[mt][0], ah[mt][1], ah[mt][2], ah[mt][3], bufAh + aOff[mt] + s * 32);
                ldsm4(al[mt][0], al[mt][1], al[mt][2], al[mt][3], bufAl + aOff[mt] + s * 32);
            }
            uint32 bh[8][2], bl[8][2];
#pragma unroll
            for (int g = 0; g < 4; g++) {
                uint32 r0, r1, r2, r3;
                ldsm4(r0, r1, r2, r3, bufBh + bOff[g] + s * 32);
                bh[2*g][0] = r0; bh[2*g][1] = r1; bh[2*g+1][0] = r2; bh[2*g+1][1] = r3;
                ldsm4(r0, r1, r2, r3, bufBl + bOff[g] + s * 32);
                bl[2*g][0] = r0; bl[2*g][1] = r1; bl[2*g+1][0] = r2; bl[2*g+1][1] = r3;
            }
#pragma unroll
            for (int mt = 0; mt < 2; mt++)
#pragma unroll
                for (int nt = 0; nt < 8; nt++) {
                    mma16816(acc[mt][nt], ah[mt], bh[nt]);
                    mma16816(acc[mt][nt], ah[mt], bl[nt]);
                    mma16816(acc[mt][nt], al[mt], bh[nt]);
                }
        }
        __syncthreads();
    }

#pragma unroll
    for (int mt = 0; mt < 2; mt++) {
        const int r0 = wm * 32 + mt * 16 + (lane >> 2);
#pragma unroll
        for (int nt = 0; nt < 8; nt++) {
            const int c = wn * 64 + nt * 8 + 2 * (lane & 3);
            float2 v0 = { acc[mt][nt][0], acc[mt][nt][1] };
            float2 v1 = { acc[mt][nt][2], acc[mt][nt][3] };
            if (relu) {
                v0.x = fmaxf(v0.x, 0.f); v0.y = fmaxf(v0.y, 0.f);
                v1.x = fmaxf(v1.x, 0.f); v1.y = fmaxf(v1.y, 0.f);
            }
            *reinterpret_cast<float2*>(Cblk + (size_t)r0 * ldc + c) = v0;
            *reinterpret_cast<float2*>(Cblk + (size_t)(r0 + 8) * ldc + c) = v1;
        }
    }
#undef LOAD_TILE
}

__global__ __launch_bounds__(256) void gemm_enc_bf16(
    const ushort_t* __restrict__ xhi, const ushort_t* __restrict__ xlo,
    const ushort_t* __restrict__ bqh, const ushort_t* __restrict__ bql,
    const ushort_t* __restrict__ bvh, const ushort_t* __restrict__ bvl,
    float* __restrict__ qs, float* __restrict__ vs)
{
    const int y = blockIdx.y;
    const int isV = y >> 3, head = y & 7;
    const ushort_t* Bh = (isV ? bvh : bqh) + (size_t)head * 128 * KTOT;
    const ushort_t* Bl = (isV ? bvl : bql) + (size_t)head * 128 * KTOT;
    float* C = (isV ? vs : qs) + (size_t)blockIdx.x * 128 * SP + head * 128;
    gemm_core(xhi + (size_t)blockIdx.x * 128 * KTOT, xlo + (size_t)blockIdx.x * 128 * KTOT,
              Bh, Bl, C, SP, 1);
}

__global__ __launch_bounds__(256) void gemm_dec_bf16(
    const ushort_t* __restrict__ ahi, const ushort_t* __restrict__ alo,
    const ushort_t* __restrict__ bh, const ushort_t* __restrict__ bl,
    float* __restrict__ out)
{
    gemm_core(ahi + (size_t)blockIdx.x * 128 * KTOT, alo + (size_t)blockIdx.x * 128 * KTOT,
              bh + (size_t)blockIdx.y * 128 * KTOT, bl + (size_t)blockIdx.y * 128 * KTOT,
              out + (size_t)blockIdx.x * 128 * DENSE + blockIdx.y * 128, DENSE, 0);
}

// ---------------- sig reduction ----------------
__global__ void reduce_sig_a(const float* __restrict__ qs, float* __restrict__ part)
{
    const int b = blockIdx.x;
    const int col = blockIdx.y * 128 + threadIdx.x;
    const int tz = blockIdx.z;
    const int t0 = tz * (TT / TCH);
    const float* p = qs + ((size_t)b * TT + t0) * SP + col;
    float s = 0.f, s8 = 0.f;
#pragma unroll 4
    for (int t = 0; t < TT / TCH; t++) {
        float v = p[(size_t)t * SP];
        s += v;
        if (((t0 + t) & 7) == 0) s8 += v;
    }
    part[((size_t)b * TCH + tz) * SP + col] = s;
    part[(size_t)BB * TCH * SP + ((size_t)b * TCH + tz) * SP + col] = s8;
}

__global__ void reduce_sig_b(const float* __restrict__ part, float* __restrict__ sig)
{
    const int b = blockIdx.x;
    const int col = blockIdx.y * 128 + threadIdx.x;
    float s = 0.f, s8 = 0.f;
#pragma unroll
    for (int z = 0; z < TCH; z++) {
        s  += part[((size_t)b * TCH + z) * SP + col];
        s8 += part[(size_t)BB * TCH * SP + ((size_t)b * TCH + z) * SP + col];
    }
    sig[b * SP + col] = s * (1.f / TT) + 0.5f * s8 * (1.f / (TT / 8));
}

// ---------------- parallel metric MLP ----------------
// Phase 1: h[b][j] = gelu(sig[b] . w1[:,j] + b1[j]), j in [0,512)
// grid (BB, 16), 256 threads: 32 cols x 8 k-groups
__global__ __launch_bounds__(256) void metric1_kernel(
    const float* __restrict__ sig, const float* __restrict__ w1,
    const float* __restrict__ b1, float* __restrict__ hbuf)
{
    __shared__ float red[8][32];
    const int b = blockIdx.x;
    const int j = blockIdx.y * 32 + (threadIdx.x & 31);
    const int kg = threadIdx.x >> 5;
    const float* sg = sig + b * SP;
    float s = 0.f;
#pragma unroll 4
    for (int d = kg; d < SP; d += 8)
        s = fmaf(sg[d], w1[d * 512 + j], s);
    red[kg][threadIdx.x & 31] = s;
    __syncthreads();
    if (kg == 0) {
        float acc = b1[j];
#pragma unroll
        for (int g = 0; g < 8; g++) acc += red[g][threadIdx.x & 31];
        hbuf[b * 512 + j] = 0.5f * acc * (1.f + erff(acc * 0.7071067811865475f));
    }
}

// Phase 2: metric[b][col] = softplus(base[col] + 0.1*(h[b] . w2[:,col] + b2[col]))
// grid (BB, 32), 256 threads: 32 cols x 8 k-groups
__global__ __launch_bounds__(256) void metric2_kernel(
    const float* __restrict__ hbuf, const float* __restrict__ w2,
    const float* __restrict__ b2, const float* __restrict__ base,
    float* __restrict__ metric)
{
    __shared__ float red[8][32];
    const int b = blockIdx.x;
    const int col = blockIdx.y * 32 + (threadIdx.x & 31);
    const int kg = threadIdx.x >> 5;
    const float* hb = hbuf + b * 512;
    float s = 0.f;
#pragma unroll 4
    for (int k = kg; k < 512; k += 8)
        s = fmaf(hb[k], w2[k * SP + col], s);
    red[kg][threadIdx.x & 31] = s;
    __syncthreads();
    if (kg == 0) {
        float m = b2[col];
#pragma unroll
        for (int g = 0; g < 8; g++) m += red[g][threadIdx.x & 31];
        float xv = base[col] + 0.1f * m;
        metric[b * SP + col] = fmaxf(xv, 0.f) + log1pf(expf(-fabsf(xv)));
    }
}

// ---------------- Hebbian U@V ----------------
__global__ void heb_kernel(const float* __restrict__ U, const float* __restrict__ V,
                           float* __restrict__ hebM)
{
    int h = blockIdx.x, i = threadIdx.x;
    float u[32];
#pragma unroll
    for (int r = 0; r < 32; r++) u[r] = U[h * HD * 32 + i * 32 + r];
    const float* Vh = V + h * 32 * HD;
    for (int j = 0; j < HD; j++) {
        float s = 0.f;
#pragma unroll
        for (int r = 0; r < 32; r++) s = fmaf(u[r], Vh[r * HD + j], s);
        hebM[h * HD * HD + i * HD + j] = s;
    }
}

// ---------------- windowed metric attention ----------------
#define TTILE 16
#define NROWS 79
#define RSTR 129

__global__ __launch_bounds__(128) void attn_kernel(
    const float* __restrict__ qs, const float* __restrict__ vs,
    const float* __restrict__ metric, const float* __restrict__ hebM,
    ushort_t* __restrict__ osHi, ushort_t* __restrict__ osLo)
{
    extern __shared__ float sm[];
    float* q_s = sm;
    float* v_s = q_s + NROWS * RSTR;
    float* met_s = v_s + NROWS * RSTR;
    __shared__ float d_s[4][WIN];
    __shared__ float wsel[4][TOPK];
    __shared__ int   rsel[4][TOPK];

    const int t0 = blockIdx.x * TTILE;
    const int h = blockIdx.y;
    const int b = blockIdx.z;
    const int tid = threadIdx.x;
    const int warp = tid >> 5, lane = tid & 31;

    const size_t baseRow = (size_t)b * TT * SP;
    for (int i = tid; i < NROWS * HD; i += 128) {
        int s = i >> 7, e = i & 127;
        int g = t0 - (WIN - 1) + s; if (g < 0) g = 0;
        size_t gi = baseRow + (size_t)g * SP + h * HD + e;
        q_s[s * RSTR + e] = qs[gi];
        v_s[s * RSTR + e] = vs[gi];
    }
    met_s[tid & 127] = metric[b * SP + h * HD + (tid & 127)];
    __syncthreads();

    const float* HM = hebM + h * HD * HD;

    for (int it = 0; it < 4; it++) {
        const int t = t0 + warp * 4 + it;
        const int qrow = t - t0 + (WIN - 1);
        const float* qr = q_s + qrow * RSTR;

        int gg0 = t - lane;        if (gg0 < 0) gg0 = 0;
        int gg1 = t - lane - 32;   if (gg1 < 0) gg1 = 0;
        const int r0 = gg0 - t0 + (WIN - 1);
        const int r1 = gg1 - t0 + (WIN - 1);
        const float* p0 = q_s + r0 * RSTR;
        const float* p1 = q_s + r1 * RSTR;

        float d0 = 0.f, d1 = 0.f;
#pragma unroll 8
        for (int e = 0; e < HD; e++) {
            float qv = qr[e], m = met_s[e];
            float a = qv - p0[e]; d0 = fmaf(a * a, m, d0);
            float c = qv - p1[e]; d1 = fmaf(c * c, m, d1);
        }
        float dist0 = sqrtf(d0 + 1e-8f);
        float dist1 = sqrtf(d1 + 1e-8f);
        d_s[warp][lane] = dist0;
        d_s[warp][lane + 32] = dist1;
        __syncwarp();

        int rk0 = 0, rk1 = 0;
        const int j1 = lane + 32;
#pragma unroll 8
        for (int j = 0; j < WIN; j++) {
            float dj = d_s[warp][j];
            rk0 += (dj < dist0) || (dj == dist0 && j < lane);
            rk1 += (dj < dist1) || (dj == dist1 && j < j1);
        }
        if (rk0 < TOPK) { wsel[warp][rk0] = expf(-dist0); rsel[warp][rk0] = r0; }
        if (rk1 < TOPK) { wsel[warp][rk1] = expf(-dist1); rsel[warp][rk1] = r1; }
        __syncwarp();

        float wsum = wsel[warp][lane];
#pragma unroll
        for (int o = 16; o; o >>= 1) wsum += __shfl_xor_sync(0xffffffffu, wsum, o);
        const float inv = 1.f / (wsum + 1e-8f);

        float c0 = 0.f, c1 = 0.f, c2 = 0.f, c3 = 0.f;
#pragma unroll 4
        for (int k = 0; k < TOPK; k++) {
            float wk = wsel[warp][k];
            const float* vr = v_s + rsel[warp][k] * RSTR;
            c0 = fmaf(wk, vr[lane], c0);
            c1 = fmaf(wk, vr[lane + 32], c1);
            c2 = fmaf(wk, vr[lane + 64], c2);
            c3 = fmaf(wk, vr[lane + 96], c3);
        }
        c0 *= inv; c1 *= inv; c2 *= inv; c3 *= inv;

        const float q0 = qr[lane], q1 = qr[lane + 32], q2 = qr[lane + 64], q3 = qr[lane + 96];
        float nq = q0 * q0 + q1 * q1 + q2 * q2 + q3 * q3;
#pragma unroll
        for (int o = 16; o; o >>= 1) nq += __shfl_xor_sync(0xffffffffu, nq, o);
        const float nrm = sqrtf(nq);

        if (nrm > 0.2f) {
            const float qinv = 1.f / fmaxf(nrm, 1e-12f);
            float h0 = 0.f, h1 = 0.f, h2 = 0.f, h3 = 0.f;
#pragma unroll 4
            for (int e = 0; e < HD; e++) {
                float qe = qr[e] * qinv;
                const float* hm = HM + e * HD;
                h0 = fmaf(qe, __ldg(hm + lane), h0);
                h1 = fmaf(qe, __ldg(hm + lane + 32), h1);
                h2 = fmaf(qe, __ldg(hm + lane + 64), h2);
                h3 = fmaf(qe, __ldg(hm + lane + 96), h3);
            }
            c0 += 0.1f * h0; c1 += 0.1f * h1; c2 += 0.1f * h2; c3 += 0.1f * h3;
        }

        size_t ob = baseRow + (size_t)t * SP + h * HD;
        ushort_t hh, ll;
        split_bf16(q0 * c0, hh, ll); osHi[ob + lane]      = hh; osLo[ob + lane]      = ll;
        split_bf16(q1 * c1, hh, ll); osHi[ob + lane + 32] = hh; osLo[ob + lane + 32] = ll;
        split_bf16(q2 * c2, hh, ll); osHi[ob + lane + 64] = hh; osLo[ob + lane + 64] = ll;
        split_bf16(q3 * c3, hh, ll); osHi[ob + lane + 96] = hh; osLo[ob + lane + 96] = ll;
    }
}

// ---------------- launcher ----------------
extern "C" void kernel_launch(void* const* d_in, const int* in_sizes, int n_in,
                              void* d_out, int out_size)
{
    const float* x      = (const float*)d_in[0];
    const float* enc_q  = (const float*)d_in[1];
    const float* enc_v  = (const float*)d_in[2];
    const float* w1     = (const float*)d_in[3];
    const float* b1     = (const float*)d_in[4];
    const float* w2     = (const float*)d_in[5];
    const float* b2     = (const float*)d_in[6];
    const float* basem  = (const float*)d_in[7];
    const float* hebU   = (const float*)d_in[8];
    const float* hebV   = (const float*)d_in[9];
    const float* dec    = (const float*)d_in[10];
    float* out = (float*)d_out;

    float *qs, *vs, *part, *sig, *hbuf, *metric, *hebM;
    ushort_t *xhi, *xlo, *bqh, *bql, *bvh, *bvl, *bdh, *bdl, *oshi, *oslo;
    cudaGetSymbolAddress((void**)&qs, g_qs);
    cudaGetSymbolAddress((void**)&vs, g_vs);
    cudaGetSymbolAddress((void**)&part, g_part);
    cudaGetSymbolAddress((void**)&sig, g_sig);
    cudaGetSymbolAddress((void**)&hbuf, g_hbuf);
    cudaGetSymbolAddress((void**)&metric, g_metric);
    cudaGetSymbolAddress((void**)&hebM, g_heb);
    cudaGetSymbolAddress((void**)&xhi, g_x_hi);
    cudaGetSymbolAddress((void**)&xlo, g_x_lo);
    cudaGetSymbolAddress((void**)&bqh, g_btq_hi);
    cudaGetSymbolAddress((void**)&bql, g_btq_lo);
    cudaGetSymbolAddress((void**)&bvh, g_btv_hi);
    cudaGetSymbolAddress((void**)&bvl, g_btv_lo);
    cudaGetSymbolAddress((void**)&bdh, g_btd_hi);
    cudaGetSymbolAddress((void**)&bdl, g_btd_lo);
    cudaGetSymbolAddress((void**)&oshi, g_os_hi);
    cudaGetSymbolAddress((void**)&oslo, g_os_lo);

    const int attn_smem = (2 * NROWS * RSTR + 128) * (int)sizeof(float);
    cudaFuncSetAttribute(attn_kernel, cudaFuncAttributeMaxDynamicSharedMemorySize, attn_smem);
    cudaFuncSetAttribute(gemm_enc_bf16, cudaFuncAttributeMaxDynamicSharedMemorySize, GEMM_SMEM);
    cudaFuncSetAttribute(gemm_dec_bf16, cudaFuncAttributeMaxDynamicSharedMemorySize, GEMM_SMEM);

    // 1-3: splits needed by encoder
    split_x_kernel<<<MT * DENSE / 1024, 256>>>(x, xhi, xlo);
    transpose_split_kernel<<<dim3(32, 4, NH), dim3(32, 8)>>>(enc_q, HD, bqh, bql,
                                                             (long)DENSE * HD, (long)HD * DENSE);
    transpose_split_kernel<<<dim3(32, 4, NH), dim3(32, 8)>>>(enc_v, HD, bvh, bvl,
                                                             (long)DENSE * HD, (long)HD * DENSE);

    // 4: encoders (PROFILED SLOT)
    gemm_enc_bf16<<<dim3(MT / 128, 16), 256, GEMM_SMEM>>>(xhi, xlo, bqh, bql, bvh, bvl, qs, vs);

    // 5: decoder weight transpose
    transpose_split_kernel<<<dim3(32, 32, 1), dim3(32, 8)>>>(dec, DENSE, bdh, bdl, 0, 0);

    // 6: hebbian matrices
    heb_kernel<<<NH, HD>>>(hebU, hebV, hebM);

    // 7,8: sig reduction
    reduce_sig_a<<<dim3(BB, SP / 128, TCH), 128>>>(qs, part);
    reduce_sig_b<<<dim3(BB, SP / 128), 128>>>(part, sig);

    // 9,10: parallel metric MLP
    metric1_kernel<<<dim3(BB, 16), 256>>>(sig, w1, b1, hbuf);
    metric2_kernel<<<dim3(BB, 32), 256>>>(hbuf, w2, b2, basem, metric);

    // 11: attention
    attn_kernel<<<dim3(TT / TTILE, NH, BB), 128, attn_smem>>>(qs, vs, metric, hebM, oshi, oslo);

    // 12: decoder
    gemm_dec_bf16<<<dim3(MT / 128, SP / 128), 256, GEMM_SMEM>>>(oshi, oslo, bdh, bdl, out);
}

// round 6
// speedup vs baseline: 2.6613x; 1.7266x over previous
#include <cuda_runtime.h>
#include <cuda_bf16.h>
#include <math.h>

// Problem constants
#define BB 2
#define TT 2048
#define DENSE 1024
#define NH 8
#define HD 128
#define WIN 64
#define TOPK 32
#define MT (BB*TT)          // 4096 rows
#define SP 1024             // NH*HD
#define TCH 8               // t-chunks for sig reduction

// GEMM tiling
#define KTOT 1024
#define KC2 32
#define STR 40              // smem row stride in bf16 elems (80B, conflict-free)
#define TILE_ELE (128*STR)
#define GEMM_SMEM (8*TILE_ELE*2)  // 81920 B

typedef unsigned short ushort_t;
typedef unsigned int uint32;

// ---------------- device scratch ----------------
__device__ float    g_qs[MT * SP];
__device__ float    g_vs[MT * SP];
__device__ float    g_hebC[MT * SP];      // precomputed gate*0.1*q_unit@hebM
__device__ ushort_t g_x_hi[MT * DENSE];
__device__ ushort_t g_x_lo[MT * DENSE];
__device__ ushort_t g_btq_hi[SP * DENSE];
__device__ ushort_t g_btq_lo[SP * DENSE];
__device__ ushort_t g_btv_hi[SP * DENSE];
__device__ ushort_t g_btv_lo[SP * DENSE];
__device__ ushort_t g_btd_hi[DENSE * SP];
__device__ ushort_t g_btd_lo[DENSE * SP];
__device__ ushort_t g_os_hi[MT * SP];
__device__ ushort_t g_os_lo[MT * SP];
__device__ float    g_part[2 * BB * TCH * SP];
__device__ float    g_sig[BB * SP];
__device__ float    g_hbuf[BB * (SP/2)];
__device__ float    g_metric[BB * SP];
__device__ float    g_heb[NH * HD * HD];

// ---------------- asm helpers ----------------
__device__ __forceinline__ unsigned smem_u32(const void* p) {
    return (unsigned)__cvta_generic_to_shared(p);
}
__device__ __forceinline__ void cp16(unsigned dst, const void* src) {
    asm volatile("cp.async.cg.shared.global [%0], [%1], 16;" :: "r"(dst), "l"(src));
}
__device__ __forceinline__ void cp_commit() { asm volatile("cp.async.commit_group;"); }
template<int N> __device__ __forceinline__ void cp_wait() {
    asm volatile("cp.async.wait_group %0;" :: "n"(N));
}
__device__ __forceinline__ void ldsm4(uint32& r0, uint32& r1, uint32& r2, uint32& r3,
                                      unsigned addr) {
    asm volatile("ldmatrix.sync.aligned.m8n8.x4.shared.b16 {%0,%1,%2,%3}, [%4];"
                 : "=r"(r0), "=r"(r1), "=r"(r2), "=r"(r3) : "r"(addr));
}
__device__ __forceinline__ void mma16816(float* d, const uint32* a, const uint32* b) {
    asm volatile(
        "mma.sync.aligned.m16n8k16.row.col.f32.bf16.bf16.f32 "
        "{%0,%1,%2,%3}, {%4,%5,%6,%7}, {%8,%9}, {%0,%1,%2,%3};"
        : "+f"(d[0]), "+f"(d[1]), "+f"(d[2]), "+f"(d[3])
        : "r"(a[0]), "r"(a[1]), "r"(a[2]), "r"(a[3]), "r"(b[0]), "r"(b[1]));
}
__device__ __forceinline__ void split_bf16(float v, ushort_t& hi, ushort_t& lo) {
    __nv_bfloat16 h = __float2bfloat16_rn(v);
    float hf = __bfloat162float(h);
    __nv_bfloat16 l = __float2bfloat16_rn(v - hf);
    hi = __bfloat16_as_ushort(h);
    lo = __bfloat16_as_ushort(l);
}

// ---------------- split / transpose-split kernels ----------------
__global__ void split_x_kernel(const float* __restrict__ x,
                               ushort_t* __restrict__ xhi, ushort_t* __restrict__ xlo)
{
    int i = (blockIdx.x * 256 + threadIdx.x) * 4;
    float4 v = *reinterpret_cast<const float4*>(x + i);
    ushort_t h0,l0,h1,l1,h2,l2,h3,l3;
    split_bf16(v.x,h0,l0); split_bf16(v.y,h1,l1);
    split_bf16(v.z,h2,l2); split_bf16(v.w,h3,l3);
    ushort4 hv = {h0,h1,h2,h3}, lv = {l0,l1,l2,l3};
    *reinterpret_cast<ushort4*>(xhi + i) = hv;
    *reinterpret_cast<ushort4*>(xlo + i) = lv;
}

__global__ void transpose_split_kernel(const float* __restrict__ In, int nld,
                                       ushort_t* __restrict__ outHi, ushort_t* __restrict__ outLo,
                                       long strideIn, long strideOut)
{
    __shared__ float tile[32][33];
    const float* in = In + (long)blockIdx.z * strideIn;
    ushort_t* oh = outHi + (long)blockIdx.z * strideOut;
    ushort_t* ol = outLo + (long)blockIdx.z * strideOut;
    int k0 = blockIdx.x * 32, n0 = blockIdx.y * 32;
    int tx = threadIdx.x, ty = threadIdx.y;
#pragma unroll
    for (int i = 0; i < 4; i++) {
        int k = ty * 4 + i;
        tile[k][tx] = in[(size_t)(k0 + k) * nld + n0 + tx];
    }
    __syncthreads();
#pragma unroll
    for (int i = 0; i < 4; i++) {
        int n = ty * 4 + i;
        float v = tile[tx][n];
        ushort_t h, l; split_bf16(v, h, l);
        oh[(size_t)(n0 + n) * 1024 + k0 + tx] = h;
        ol[(size_t)(n0 + n) * 1024 + k0 + tx] = l;
    }
}

// ---------------- bf16 split-precision HMMA GEMM core ----------------
__device__ __forceinline__ void gemm_core(
    const ushort_t* __restrict__ Ah, const ushort_t* __restrict__ Al,
    const ushort_t* __restrict__ Bh, const ushort_t* __restrict__ Bl,
    float* __restrict__ Cblk, int ldc, int relu)
{
    extern __shared__ ushort_t smem[];
    ushort_t* sA_hi = smem;
    ushort_t* sA_lo = sA_hi + 2 * TILE_ELE;
    ushort_t* sB_hi = sA_lo + 2 * TILE_ELE;
    ushort_t* sB_lo = sB_hi + 2 * TILE_ELE;

    const int tid = threadIdx.x;
    const int warp = tid >> 5, lane = tid & 31;
    const int wm = warp & 3, wn = warp >> 2;

    const int c0 = tid * 2;
    const int ldRow0 = c0 >> 2, ldK0 = (c0 & 3) * 8;
    const int ldRow1 = (c0 + 1) >> 2, ldK1 = ((c0 + 1) & 3) * 8;

#define LOAD_TILE(dst, src, k0)                                                   \
    {                                                                             \
        cp16(smem_u32((dst) + ldRow0 * STR + ldK0), (src) + (size_t)ldRow0 * KTOT + (k0) + ldK0); \
        cp16(smem_u32((dst) + ldRow1 * STR + ldK1), (src) + (size_t)ldRow1 * KTOT + (k0) + ldK1); \
    }

    unsigned aOff[2], bOff[4];
#pragma unroll
    for (int mt = 0; mt < 2; mt++)
        aOff[mt] = (unsigned)(((wm * 32 + mt * 16 + (lane & 15)) * STR + (lane >> 4) * 8) * 2);
#pragma unroll
    for (int g = 0; g < 4; g++)
        bOff[g] = (unsigned)(((wn * 64 + g * 16 + (lane & 7) + (lane >> 4) * 8) * STR
                              + ((lane >> 3) & 1) * 8) * 2);

    float acc[2][8][4];
#pragma unroll
    for (int mt = 0; mt < 2; mt++)
#pragma unroll
        for (int nt = 0; nt < 8; nt++)
#pragma unroll
            for (int r = 0; r < 4; r++) acc[mt][nt][r] = 0.f;

    LOAD_TILE(sA_hi, Ah, 0); LOAD_TILE(sA_lo, Al, 0);
    LOAD_TILE(sB_hi, Bh, 0); LOAD_TILE(sB_lo, Bl, 0);
    cp_commit();

    const int nk = KTOT / KC2;
    for (int i = 0; i < nk; i++) {
        if (i + 1 < nk) {
            const int k0 = (i + 1) * KC2;
            ushort_t* dA_hi = sA_hi + ((i + 1) & 1) * TILE_ELE;
            ushort_t* dA_lo = sA_lo + ((i + 1) & 1) * TILE_ELE;
            ushort_t* dB_hi = sB_hi + ((i + 1) & 1) * TILE_ELE;
            ushort_t* dB_lo = sB_lo + ((i + 1) & 1) * TILE_ELE;
            LOAD_TILE(dA_hi, Ah, k0); LOAD_TILE(dA_lo, Al, k0);
            LOAD_TILE(dB_hi, Bh, k0); LOAD_TILE(dB_lo, Bl, k0);
            cp_commit();
            cp_wait<1>();
        } else {
            cp_wait<0>();
        }
        __syncthreads();

        const unsigned bufAh = smem_u32(sA_hi + (i & 1) * TILE_ELE);
        const unsigned bufAl = smem_u32(sA_lo + (i & 1) * TILE_ELE);
        const unsigned bufBh = smem_u32(sB_hi + (i & 1) * TILE_ELE);
        const unsigned bufBl = smem_u32(sB_lo + (i & 1) * TILE_ELE);

#pragma unroll
        for (int s = 0; s < 2; s++) {
            uint32 ah[2][4], al[2][4];
#pragma unroll
            for (int mt = 0; mt < 2; mt++) {
                ldsm4(ah[mt][0], ah[mt][1], ah[mt][2], ah[mt][3], bufAh + aOff[mt] + s * 32);
                ldsm4(al[mt][0], al[mt][1], al[mt][2], al[mt][3], bufAl + aOff[mt] + s * 32);
            }
            uint32 bh[8][2], bl[8][2];
#pragma unroll
            for (int g = 0; g < 4; g++) {
                uint32 r0, r1, r2, r3;
                ldsm4(r0, r1, r2, r3, bufBh + bOff[g] + s * 32);
                bh[2*g][0] = r0; bh[2*g][1] = r1; bh[2*g+1][0] = r2; bh[2*g+1][1] = r3;
                ldsm4(r0, r1, r2, r3, bufBl + bOff[g] + s * 32);
                bl[2*g][0] = r0; bl[2*g][1] = r1; bl[2*g+1][0] = r2; bl[2*g+1][1] = r3;
            }
#pragma unroll
            for (int mt = 0; mt < 2; mt++)
#pragma unroll
                for (int nt = 0; nt < 8; nt++) {
                    mma16816(acc[mt][nt], ah[mt], bh[nt]);
                    mma16816(acc[mt][nt], ah[mt], bl[nt]);
                    mma16816(acc[mt][nt], al[mt], bh[nt]);
                }
        }
        __syncthreads();
    }

#pragma unroll
    for (int mt = 0; mt < 2; mt++) {
        const int r0 = wm * 32 + mt * 16 + (lane >> 2);
#pragma unroll
        for (int nt = 0; nt < 8; nt++) {
            const int c = wn * 64 + nt * 8 + 2 * (lane & 3);
            float2 v0 = { acc[mt][nt][0], acc[mt][nt][1] };
            float2 v1 = { acc[mt][nt][2], acc[mt][nt][3] };
            if (relu) {
                v0.x = fmaxf(v0.x, 0.f); v0.y = fmaxf(v0.y, 0.f);
                v1.x = fmaxf(v1.x, 0.f); v1.y = fmaxf(v1.y, 0.f);
            }
            *reinterpret_cast<float2*>(Cblk + (size_t)r0 * ldc + c) = v0;
            *reinterpret_cast<float2*>(Cblk + (size_t)(r0 + 8) * ldc + c) = v1;
        }
    }
#undef LOAD_TILE
}

__global__ __launch_bounds__(256) void gemm_enc_bf16(
    const ushort_t* __restrict__ xhi, const ushort_t* __restrict__ xlo,
    const ushort_t* __restrict__ bqh, const ushort_t* __restrict__ bql,
    const ushort_t* __restrict__ bvh, const ushort_t* __restrict__ bvl,
    float* __restrict__ qs, float* __restrict__ vs)
{
    const int y = blockIdx.y;
    const int isV = y >> 3, head = y & 7;
    const ushort_t* Bh = (isV ? bvh : bqh) + (size_t)head * 128 * KTOT;
    const ushort_t* Bl = (isV ? bvl : bql) + (size_t)head * 128 * KTOT;
    float* C = (isV ? vs : qs) + (size_t)blockIdx.x * 128 * SP + head * 128;
    gemm_core(xhi + (size_t)blockIdx.x * 128 * KTOT, xlo + (size_t)blockIdx.x * 128 * KTOT,
              Bh, Bl, C, SP, 1);
}

__global__ __launch_bounds__(256) void gemm_dec_bf16(
    const ushort_t* __restrict__ ahi, const ushort_t* __restrict__ alo,
    const ushort_t* __restrict__ bh, const ushort_t* __restrict__ bl,
    float* __restrict__ out)
{
    gemm_core(ahi + (size_t)blockIdx.x * 128 * KTOT, alo + (size_t)blockIdx.x * 128 * KTOT,
              bh + (size_t)blockIdx.y * 128 * KTOT, bl + (size_t)blockIdx.y * 128 * KTOT,
              out + (size_t)blockIdx.x * 128 * DENSE + blockIdx.y * 128, DENSE, 0);
}

// ---------------- sig reduction ----------------
__global__ void reduce_sig_a(const float* __restrict__ qs, float* __restrict__ part)
{
    const int b = blockIdx.x;
    const int col = blockIdx.y * 128 + threadIdx.x;
    const int tz = blockIdx.z;
    const int t0 = tz * (TT / TCH);
    const float* p = qs + ((size_t)b * TT + t0) * SP + col;
    float s = 0.f, s8 = 0.f;
#pragma unroll 4
    for (int t = 0; t < TT / TCH; t++) {
        float v = p[(size_t)t * SP];
        s += v;
        if (((t0 + t) & 7) == 0) s8 += v;
    }
    part[((size_t)b * TCH + tz) * SP + col] = s;
    part[(size_t)BB * TCH * SP + ((size_t)b * TCH + tz) * SP + col] = s8;
}

__global__ void reduce_sig_b(const float* __restrict__ part, float* __restrict__ sig)
{
    const int b = blockIdx.x;
    const int col = blockIdx.y * 128 + threadIdx.x;
    float s = 0.f, s8 = 0.f;
#pragma unroll
    for (int z = 0; z < TCH; z++) {
        s  += part[((size_t)b * TCH + z) * SP + col];
        s8 += part[(size_t)BB * TCH * SP + ((size_t)b * TCH + z) * SP + col];
    }
    sig[b * SP + col] = s * (1.f / TT) + 0.5f * s8 * (1.f / (TT / 8));
}

// ---------------- parallel metric MLP ----------------
__global__ __launch_bounds__(256) void metric1_kernel(
    const float* __restrict__ sig, const float* __restrict__ w1,
    const float* __restrict__ b1, float* __restrict__ hbuf)
{
    __shared__ float red[8][32];
    const int b = blockIdx.x;
    const int j = blockIdx.y * 32 + (threadIdx.x & 31);
    const int kg = threadIdx.x >> 5;
    const float* sg = sig + b * SP;
    float s = 0.f;
#pragma unroll 4
    for (int d = kg; d < SP; d += 8)
        s = fmaf(sg[d], w1[d * 512 + j], s);
    red[kg][threadIdx.x & 31] = s;
    __syncthreads();
    if (kg == 0) {
        float acc = b1[j];
#pragma unroll
        for (int g = 0; g < 8; g++) acc += red[g][threadIdx.x & 31];
        hbuf[b * 512 + j] = 0.5f * acc * (1.f + erff(acc * 0.7071067811865475f));
    }
}

__global__ __launch_bounds__(256) void metric2_kernel(
    const float* __restrict__ hbuf, const float* __restrict__ w2,
    const float* __restrict__ b2, const float* __restrict__ base,
    float* __restrict__ metric)
{
    __shared__ float red[8][32];
    const int b = blockIdx.x;
    const int col = blockIdx.y * 32 + (threadIdx.x & 31);
    const int kg = threadIdx.x >> 5;
    const float* hb = hbuf + b * 512;
    float s = 0.f;
#pragma unroll 4
    for (int k = kg; k < 512; k += 8)
        s = fmaf(hb[k], w2[k * SP + col], s);
    red[kg][threadIdx.x & 31] = s;
    __syncthreads();
    if (kg == 0) {
        float m = b2[col];
#pragma unroll
        for (int g = 0; g < 8; g++) m += red[g][threadIdx.x & 31];
        float xv = base[col] + 0.1f * m;
        metric[b * SP + col] = fmaxf(xv, 0.f) + log1pf(expf(-fabsf(xv)));
    }
}

// ---------------- Hebbian U@V ----------------
__global__ void heb_kernel(const float* __restrict__ U, const float* __restrict__ V,
                           float* __restrict__ hebM)
{
    int h = blockIdx.x, i = threadIdx.x;
    float u[32];
#pragma unroll
    for (int r = 0; r < 32; r++) u[r] = U[h * HD * 32 + i * 32 + r];
    const float* Vh = V + h * 32 * HD;
    for (int j = 0; j < HD; j++) {
        float s = 0.f;
#pragma unroll
        for (int r = 0; r < 32; r++) s = fmaf(u[r], Vh[r * HD + j], s);
        hebM[h * HD * HD + i * HD + j] = s;
    }
}

// ---------------- Hebbian context precompute ----------------
// hebC[r, h*HD+j] = (|q|>0.2) ? (0.1/max(|q|,1e-12)) * (q . hebM[:,j]) : 0
// grid (MT/32, NH), 256 threads; hebM[h] resident in smem.
#define HEB_SMEM ((HD*HD + 8*HD) * 4)
__global__ __launch_bounds__(256) void heb_ctx_kernel(
    const float* __restrict__ qs, const float* __restrict__ hebM,
    float* __restrict__ hebC)
{
    extern __shared__ float hsm[];
    float* HM = hsm;                 // HD*HD
    float* qrow = hsm + HD * HD;     // 8*HD
    const int h = blockIdx.y;
    const int row0 = blockIdx.x * 32;
    const int tid = threadIdx.x, warp = tid >> 5, lane = tid & 31;

    const float* src = hebM + h * HD * HD;
    for (int i = tid * 4; i < HD * HD; i += 1024)
        *reinterpret_cast<float4*>(HM + i) = *reinterpret_cast<const float4*>(src + i);
    __syncthreads();

    float* qw = qrow + warp * HD;
#pragma unroll 1
    for (int it = 0; it < 4; it++) {
        const int r = row0 + warp * 4 + it;
        const float* q = qs + (size_t)r * SP + h * HD;
        float q0 = q[lane], q1 = q[lane + 32], q2 = q[lane + 64], q3 = q[lane + 96];
        qw[lane] = q0; qw[lane + 32] = q1; qw[lane + 64] = q2; qw[lane + 96] = q3;
        float nq = q0 * q0 + q1 * q1 + q2 * q2 + q3 * q3;
#pragma unroll
        for (int o = 16; o; o >>= 1) nq += __shfl_xor_sync(0xffffffffu, nq, o);
        const float nrm = sqrtf(nq);
        const float sc = (nrm > 0.2f) ? (0.1f / fmaxf(nrm, 1e-12f)) : 0.f;
        __syncwarp();

        float a0 = 0.f, a1 = 0.f, a2 = 0.f, a3 = 0.f;
        const int j = lane * 4;
#pragma unroll 8
        for (int e = 0; e < HD; e++) {
            float qe = qw[e];
            float4 hv = *reinterpret_cast<const float4*>(HM + e * HD + j);
            a0 = fmaf(qe, hv.x, a0);
            a1 = fmaf(qe, hv.y, a1);
            a2 = fmaf(qe, hv.z, a2);
            a3 = fmaf(qe, hv.w, a3);
        }
        float4 o4 = { a0 * sc, a1 * sc, a2 * sc, a3 * sc };
        *reinterpret_cast<float4*>(hebC + (size_t)r * SP + h * HD + j) = o4;
        __syncwarp();
    }
}

// ---------------- windowed metric attention ----------------
#define TTILE 32
#define NROWS 95           // 63 history + 32 tile
#define RSTR 129
#define ATTN_SMEM ((2*NROWS*RSTR + 128) * 4)

__global__ __launch_bounds__(256) void attn_kernel(
    const float* __restrict__ qs, const float* __restrict__ vs,
    const float* __restrict__ metric, const float* __restrict__ hebC,
    ushort_t* __restrict__ osHi, ushort_t* __restrict__ osLo)
{
    extern __shared__ float sm[];
    float* q_s = sm;
    float* v_s = q_s + NROWS * RSTR;
    float* met_s = v_s + NROWS * RSTR;
    __shared__ float d_s[8][WIN];
    __shared__ float wsel[8][TOPK];
    __shared__ int   rsel[8][TOPK];

    const int t0 = blockIdx.x * TTILE;
    const int h = blockIdx.y;
    const int b = blockIdx.z;
    const int tid = threadIdx.x;
    const int warp = tid >> 5, lane = tid & 31;

    const size_t baseRow = (size_t)b * TT * SP;
    for (int i = tid; i < NROWS * HD; i += 256) {
        int s = i >> 7, e = i & 127;
        int g = t0 - (WIN - 1) + s; if (g < 0) g = 0;
        size_t gi = baseRow + (size_t)g * SP + h * HD + e;
        q_s[s * RSTR + e] = qs[gi];
        v_s[s * RSTR + e] = vs[gi];
    }
    if (tid < 128) met_s[tid] = metric[b * SP + h * HD + tid];
    __syncthreads();

    for (int it = 0; it < 4; it++) {
        const int t = t0 + warp * 4 + it;
        const int qrow = t - t0 + (WIN - 1);
        const float* qr = q_s + qrow * RSTR;

        int gg0 = t - lane;        if (gg0 < 0) gg0 = 0;
        int gg1 = t - lane - 32;   if (gg1 < 0) gg1 = 0;
        const int r0 = gg0 - t0 + (WIN - 1);
        const int r1 = gg1 - t0 + (WIN - 1);
        const float* p0 = q_s + r0 * RSTR;
        const float* p1 = q_s + r1 * RSTR;

        float d0 = 0.f, d1 = 0.f;
#pragma unroll 8
        for (int e = 0; e < HD; e++) {
            float qv = qr[e], m = met_s[e];
            float a = qv - p0[e]; d0 = fmaf(a * a, m, d0);
            float c = qv - p1[e]; d1 = fmaf(c * c, m, d1);
        }
        float dist0 = sqrtf(d0 + 1e-8f);
        float dist1 = sqrtf(d1 + 1e-8f);
        d_s[warp][lane] = dist0;
        d_s[warp][lane + 32] = dist1;
        __syncwarp();

        int rk0 = 0, rk1 = 0;
        const int j1 = lane + 32;
#pragma unroll 8
        for (int j = 0; j < WIN; j++) {
            float dj = d_s[warp][j];
            rk0 += (dj < dist0) || (dj == dist0 && j < lane);
            rk1 += (dj < dist1) || (dj == dist1 && j < j1);
        }
        if (rk0 < TOPK) { wsel[warp][rk0] = expf(-dist0); rsel[warp][rk0] = r0; }
        if (rk1 < TOPK) { wsel[warp][rk1] = expf(-dist1); rsel[warp][rk1] = r1; }
        __syncwarp();

        float wsum = wsel[warp][lane];
#pragma unroll
        for (int o = 16; o; o >>= 1) wsum += __shfl_xor_sync(0xffffffffu, wsum, o);
        const float inv = 1.f / (wsum + 1e-8f);

        float c0 = 0.f, c1 = 0.f, c2 = 0.f, c3 = 0.f;
#pragma unroll 4
        for (int k = 0; k < TOPK; k++) {
            float wk = wsel[warp][k];
            const float* vr = v_s + rsel[warp][k] * RSTR;
            c0 = fmaf(wk, vr[lane], c0);
            c1 = fmaf(wk, vr[lane + 32], c1);
            c2 = fmaf(wk, vr[lane + 64], c2);
            c3 = fmaf(wk, vr[lane + 96], c3);
        }

        const size_t ob = baseRow + (size_t)t * SP + h * HD;
        c0 = c0 * inv + hebC[ob + lane];
        c1 = c1 * inv + hebC[ob + lane + 32];
        c2 = c2 * inv + hebC[ob + lane + 64];
        c3 = c3 * inv + hebC[ob + lane + 96];

        const float q0 = qr[lane], q1 = qr[lane + 32], q2 = qr[lane + 64], q3 = qr[lane + 96];
        ushort_t hh, ll;
        split_bf16(q0 * c0, hh, ll); osHi[ob + lane]      = hh; osLo[ob + lane]      = ll;
        split_bf16(q1 * c1, hh, ll); osHi[ob + lane + 32] = hh; osLo[ob + lane + 32] = ll;
        split_bf16(q2 * c2, hh, ll); osHi[ob + lane + 64] = hh; osLo[ob + lane + 64] = ll;
        split_bf16(q3 * c3, hh, ll); osHi[ob + lane + 96] = hh; osLo[ob + lane + 96] = ll;
    }
}

// ---------------- launcher ----------------
extern "C" void kernel_launch(void* const* d_in, const int* in_sizes, int n_in,
                              void* d_out, int out_size)
{
    const float* x      = (const float*)d_in[0];
    const float* enc_q  = (const float*)d_in[1];
    const float* enc_v  = (const float*)d_in[2];
    const float* w1     = (const float*)d_in[3];
    const float* b1     = (const float*)d_in[4];
    const float* w2     = (const float*)d_in[5];
    const float* b2     = (const float*)d_in[6];
    const float* basem  = (const float*)d_in[7];
    const float* hebU   = (const float*)d_in[8];
    const float* hebV   = (const float*)d_in[9];
    const float* dec    = (const float*)d_in[10];
    float* out = (float*)d_out;

    float *qs, *vs, *hebc, *part, *sig, *hbuf, *metric, *hebM;
    ushort_t *xhi, *xlo, *bqh, *bql, *bvh, *bvl, *bdh, *bdl, *oshi, *oslo;
    cudaGetSymbolAddress((void**)&qs, g_qs);
    cudaGetSymbolAddress((void**)&vs, g_vs);
    cudaGetSymbolAddress((void**)&hebc, g_hebC);
    cudaGetSymbolAddress((void**)&part, g_part);
    cudaGetSymbolAddress((void**)&sig, g_sig);
    cudaGetSymbolAddress((void**)&hbuf, g_hbuf);
    cudaGetSymbolAddress((void**)&metric, g_metric);
    cudaGetSymbolAddress((void**)&hebM, g_heb);
    cudaGetSymbolAddress((void**)&xhi, g_x_hi);
    cudaGetSymbolAddress((void**)&xlo, g_x_lo);
    cudaGetSymbolAddress((void**)&bqh, g_btq_hi);
    cudaGetSymbolAddress((void**)&bql, g_btq_lo);
    cudaGetSymbolAddress((void**)&bvh, g_btv_hi);
    cudaGetSymbolAddress((void**)&bvl, g_btv_lo);
    cudaGetSymbolAddress((void**)&bdh, g_btd_hi);
    cudaGetSymbolAddress((void**)&bdl, g_btd_lo);
    cudaGetSymbolAddress((void**)&oshi, g_os_hi);
    cudaGetSymbolAddress((void**)&oslo, g_os_lo);

    cudaFuncSetAttribute(attn_kernel, cudaFuncAttributeMaxDynamicSharedMemorySize, ATTN_SMEM);
    cudaFuncSetAttribute(heb_ctx_kernel, cudaFuncAttributeMaxDynamicSharedMemorySize, HEB_SMEM);
    cudaFuncSetAttribute(gemm_enc_bf16, cudaFuncAttributeMaxDynamicSharedMemorySize, GEMM_SMEM);
    cudaFuncSetAttribute(gemm_dec_bf16, cudaFuncAttributeMaxDynamicSharedMemorySize, GEMM_SMEM);

    // 1-3: splits needed by encoder
    split_x_kernel<<<MT * DENSE / 1024, 256>>>(x, xhi, xlo);
    transpose_split_kernel<<<dim3(32, 4, NH), dim3(32, 8)>>>(enc_q, HD, bqh, bql,
                                                             (long)DENSE * HD, (long)HD * DENSE);
    transpose_split_kernel<<<dim3(32, 4, NH), dim3(32, 8)>>>(enc_v, HD, bvh, bvl,
                                                             (long)DENSE * HD, (long)HD * DENSE);

    // 4: encoders (PROFILED SLOT)
    gemm_enc_bf16<<<dim3(MT / 128, 16), 256, GEMM_SMEM>>>(xhi, xlo, bqh, bql, bvh, bvl, qs, vs);

    // 5: hebbian matrices, 6: hebbian contexts
    heb_kernel<<<NH, HD>>>(hebU, hebV, hebM);
    heb_ctx_kernel<<<dim3(MT / 32, NH), 256, HEB_SMEM>>>(qs, hebM, hebc);

    // 7: decoder weight transpose
    transpose_split_kernel<<<dim3(32, 32, 1), dim3(32, 8)>>>(dec, DENSE, bdh, bdl, 0, 0);

    // 8,9: sig reduction
    reduce_sig_a<<<dim3(BB, SP / 128, TCH), 128>>>(qs, part);
    reduce_sig_b<<<dim3(BB, SP / 128), 128>>>(part, sig);

    // 10,11: parallel metric MLP
    metric1_kernel<<<dim3(BB, 16), 256>>>(sig, w1, b1, hbuf);
    metric2_kernel<<<dim3(BB, 32), 256>>>(hbuf, w2, b2, basem, metric);

    // 12: attention (+hebC add)
    attn_kernel<<<dim3(TT / TTILE, NH, BB), 256, ATTN_SMEM>>>(qs, vs, metric, hebc, oshi, oslo);

    // 13: decoder
    gemm_dec_bf16<<<dim3(MT / 128, SP / 128), 256, GEMM_SMEM>>>(oshi, oslo, bdh, bdl, out);
}

// round 10
// speedup vs baseline: 2.7900x; 1.0484x over previous
#include <cuda_runtime.h>
#include <cuda_bf16.h>
#include <math.h>

// Problem constants
#define BB 2
#define TT 2048
#define DENSE 1024
#define NH 8
#define HD 128
#define WIN 64
#define TOPK 32
#define MT (BB*TT)          // 4096 rows
#define SP 1024             // NH*HD
#define TCH 8               // t-chunks for sig reduction

// GEMM tiling: 128x128 tile, KC=16, 3-stage cp.async ring, 2 CTAs/SM
#define KTOT 1024
#define KC3 16
#define STR3 24                   // smem row stride in bf16 elems (48B, conflict-free ldsm)
#define TILE3 (128*STR3)          // 3072 elems
#define STAGE3 (4*TILE3)          // Ah, Al, Bh, Bl
#define NBUF 3
#define GEMM_SMEM (NBUF*STAGE3*2) // 73728 B

typedef unsigned short ushort_t;
typedef unsigned int uint32;

// ---------------- device scratch ----------------
__device__ float    g_qs[MT * SP];
__device__ float    g_vs[MT * SP];
__device__ float    g_hebC[MT * SP];
__device__ ushort_t g_x_hi[MT * DENSE];
__device__ ushort_t g_x_lo[MT * DENSE];
__device__ ushort_t g_btq_hi[SP * DENSE];
__device__ ushort_t g_btq_lo[SP * DENSE];
__device__ ushort_t g_btv_hi[SP * DENSE];
__device__ ushort_t g_btv_lo[SP * DENSE];
__device__ ushort_t g_btd_hi[DENSE * SP];
__device__ ushort_t g_btd_lo[DENSE * SP];
__device__ ushort_t g_os_hi[MT * SP];
__device__ ushort_t g_os_lo[MT * SP];
__device__ float    g_part[2 * BB * TCH * SP];
__device__ float    g_sig[BB * SP];
__device__ float    g_hbuf[BB * (SP/2)];
__device__ float    g_metric[BB * SP];
__device__ float    g_heb[NH * HD * HD];

// ---------------- asm helpers ----------------
__device__ __forceinline__ unsigned smem_u32(const void* p) {
    return (unsigned)__cvta_generic_to_shared(p);
}
__device__ __forceinline__ void cp16(unsigned dst, const void* src) {
    asm volatile("cp.async.cg.shared.global [%0], [%1], 16;" :: "r"(dst), "l"(src));
}
__device__ __forceinline__ void cp_commit() { asm volatile("cp.async.commit_group;"); }
template<int N> __device__ __forceinline__ void cp_wait() {
    asm volatile("cp.async.wait_group %0;" :: "n"(N));
}
__device__ __forceinline__ void ldsm4(uint32& r0, uint32& r1, uint32& r2, uint32& r3,
                                      unsigned addr) {
    asm volatile("ldmatrix.sync.aligned.m8n8.x4.shared.b16 {%0,%1,%2,%3}, [%4];"
                 : "=r"(r0), "=r"(r1), "=r"(r2), "=r"(r3) : "r"(addr));
}
__device__ __forceinline__ void mma16816(float* d, const uint32* a, const uint32* b) {
    asm volatile(
        "mma.sync.aligned.m16n8k16.row.col.f32.bf16.bf16.f32 "
        "{%0,%1,%2,%3}, {%4,%5,%6,%7}, {%8,%9}, {%0,%1,%2,%3};"
        : "+f"(d[0]), "+f"(d[1]), "+f"(d[2]), "+f"(d[3])
        : "r"(a[0]), "r"(a[1]), "r"(a[2]), "r"(a[3]), "r"(b[0]), "r"(b[1]));
}
__device__ __forceinline__ void split_bf16(float v, ushort_t& hi, ushort_t& lo) {
    __nv_bfloat16 h = __float2bfloat16_rn(v);
    float hf = __bfloat162float(h);
    __nv_bfloat16 l = __float2bfloat16_rn(v - hf);
    hi = __bfloat16_as_ushort(h);
    lo = __bfloat16_as_ushort(l);
}

// ---------------- split / transpose-split kernels ----------------
__global__ void split_x_kernel(const float* __restrict__ x,
                               ushort_t* __restrict__ xhi, ushort_t* __restrict__ xlo)
{
    int i = (blockIdx.x * 256 + threadIdx.x) * 4;
    float4 v = *reinterpret_cast<const float4*>(x + i);
    ushort_t h0,l0,h1,l1,h2,l2,h3,l3;
    split_bf16(v.x,h0,l0); split_bf16(v.y,h1,l1);
    split_bf16(v.z,h2,l2); split_bf16(v.w,h3,l3);
    ushort4 hv = {h0,h1,h2,h3}, lv = {l0,l1,l2,l3};
    *reinterpret_cast<ushort4*>(xhi + i) = hv;
    *reinterpret_cast<ushort4*>(xlo + i) = lv;
}

__global__ void transpose_split_kernel(const float* __restrict__ In, int nld,
                                       ushort_t* __restrict__ outHi, ushort_t* __restrict__ outLo,
                                       long strideIn, long strideOut)
{
    __shared__ float tile[32][33];
    const float* in = In + (long)blockIdx.z * strideIn;
    ushort_t* oh = outHi + (long)blockIdx.z * strideOut;
    ushort_t* ol = outLo + (long)blockIdx.z * strideOut;
    int k0 = blockIdx.x * 32, n0 = blockIdx.y * 32;
    int tx = threadIdx.x, ty = threadIdx.y;
#pragma unroll
    for (int i = 0; i < 4; i++) {
        int k = ty * 4 + i;
        tile[k][tx] = in[(size_t)(k0 + k) * nld + n0 + tx];
    }
    __syncthreads();
#pragma unroll
    for (int i = 0; i < 4; i++) {
        int n = ty * 4 + i;
        float v = tile[tx][n];
        ushort_t h, l; split_bf16(v, h, l);
        oh[(size_t)(n0 + n) * 1024 + k0 + tx] = h;
        ol[(size_t)(n0 + n) * 1024 + k0 + tx] = l;
    }
}

// ---------------- bf16 split-precision HMMA GEMM core (3-stage, 2 CTA/SM) ----------------
__device__ __forceinline__ void gemm_core(
    const ushort_t* __restrict__ Ah, const ushort_t* __restrict__ Al,
    const ushort_t* __restrict__ Bh, const ushort_t* __restrict__ Bl,
    float* __restrict__ Cblk, int ldc, int relu)
{
    extern __shared__ ushort_t smem[];

    const int tid = threadIdx.x;
    const int warp = tid >> 5, lane = tid & 31;
    const int wm = warp & 3, wn = warp >> 2;

    // load mapping: per matrix 256 chunks of 16B; thread tid -> chunk tid
    const int ldRow = tid >> 1, ldSeg = (tid & 1) * 8;
    const ushort_t* srcs[4] = { Ah, Al, Bh, Bl };

    // fragment smem byte offsets (within a matrix tile)
    unsigned aOff[2];
#pragma unroll
    for (int mt = 0; mt < 2; mt++)
        aOff[mt] = (unsigned)(((wm * 32 + mt * 16 + (lane & 15)) * STR3 + (lane >> 4) * 8) * 2);
    unsigned bOff[4];
#pragma unroll
    for (int g = 0; g < 4; g++)
        bOff[g] = (unsigned)(((wn * 64 + g * 16 + (lane & 7) + (lane >> 4) * 8) * STR3
                              + ((lane >> 3) & 1) * 8) * 2);

    float acc[2][8][4];
#pragma unroll
    for (int mt = 0; mt < 2; mt++)
#pragma unroll
        for (int nt = 0; nt < 8; nt++)
#pragma unroll
            for (int r = 0; r < 4; r++) acc[mt][nt][r] = 0.f;

#define PREFETCH(stage, k0)                                                     \
    {                                                                           \
        ushort_t* stb = smem + (stage) * STAGE3;                                \
        _Pragma("unroll")                                                       \
        for (int m = 0; m < 4; m++) {                                           \
            cp16(smem_u32(stb + m * TILE3 + ldRow * STR3 + ldSeg),              \
                 srcs[m] + (size_t)ldRow * KTOT + (k0) + ldSeg);                \
        }                                                                       \
        cp_commit();                                                            \
    }

    const int nk = KTOT / KC3;     // 64
    PREFETCH(0, 0);
    PREFETCH(1, KC3);

    int cur = 0;
    for (int i = 0; i < nk; i++) {
        if (i + 1 < nk) cp_wait<1>(); else cp_wait<0>();
        __syncthreads();
        if (i + 2 < nk) {
            int nstage = cur + 2; if (nstage >= NBUF) nstage -= NBUF;
            PREFETCH(nstage, (i + 2) * KC3);
        }

        const unsigned stb = smem_u32(smem + cur * STAGE3);
        const unsigned bAh = stb;
        const unsigned bAl = stb + TILE3 * 2;
        const unsigned bBh = stb + 2 * TILE3 * 2;
        const unsigned bBl = stb + 3 * TILE3 * 2;

        uint32 ah[2][4], al[2][4], b[8][2];
#pragma unroll
        for (int mt = 0; mt < 2; mt++) {
            ldsm4(ah[mt][0], ah[mt][1], ah[mt][2], ah[mt][3], bAh + aOff[mt]);
            ldsm4(al[mt][0], al[mt][1], al[mt][2], al[mt][3], bAl + aOff[mt]);
        }
#pragma unroll
        for (int g = 0; g < 4; g++) {
            uint32 r0, r1, r2, r3;
            ldsm4(r0, r1, r2, r3, bBh + bOff[g]);
            b[2*g][0] = r0; b[2*g][1] = r1; b[2*g+1][0] = r2; b[2*g+1][1] = r3;
        }
#pragma unroll
        for (int mt = 0; mt < 2; mt++)
#pragma unroll
            for (int nt = 0; nt < 8; nt++) {
                mma16816(acc[mt][nt], ah[mt], b[nt]);
                mma16816(acc[mt][nt], al[mt], b[nt]);
            }
#pragma unroll
        for (int g = 0; g < 4; g++) {
            uint32 r0, r1, r2, r3;
            ldsm4(r0, r1, r2, r3, bBl + bOff[g]);
            b[2*g][0] = r0; b[2*g][1] = r1; b[2*g+1][0] = r2; b[2*g+1][1] = r3;
        }
#pragma unroll
        for (int mt = 0; mt < 2; mt++)
#pragma unroll
            for (int nt = 0; nt < 8; nt++)
                mma16816(acc[mt][nt], ah[mt], b[nt]);

        cur++; if (cur >= NBUF) cur = 0;
    }
#undef PREFETCH

#pragma unroll
    for (int mt = 0; mt < 2; mt++) {
        const int r0 = wm * 32 + mt * 16 + (lane >> 2);
#pragma unroll
        for (int nt = 0; nt < 8; nt++) {
            const int c = wn * 64 + nt * 8 + 2 * (lane & 3);
            float2 v0 = { acc[mt][nt][0], acc[mt][nt][1] };
            float2 v1 = { acc[mt][nt][2], acc[mt][nt][3] };
            if (relu) {
                v0.x = fmaxf(v0.x, 0.f); v0.y = fmaxf(v0.y, 0.f);
                v1.x = fmaxf(v1.x, 0.f); v1.y = fmaxf(v1.y, 0.f);
            }
            *reinterpret_cast<float2*>(Cblk + (size_t)r0 * ldc + c) = v0;
            *reinterpret_cast<float2*>(Cblk + (size_t)(r0 + 8) * ldc + c) = v1;
        }
    }
}

__global__ __launch_bounds__(256, 2) void gemm_enc_bf16(
    const ushort_t* __restrict__ xhi, const ushort_t* __restrict__ xlo,
    const ushort_t* __restrict__ bqh, const ushort_t* __restrict__ bql,
    const ushort_t* __restrict__ bvh, const ushort_t* __restrict__ bvl,
    float* __restrict__ qs, float* __restrict__ vs)
{
    const int y = blockIdx.y;
    const int isV = y >> 3, head = y & 7;
    const ushort_t* Bh = (isV ? bvh : bqh) + (size_t)head * 128 * KTOT;
    const ushort_t* Bl = (isV ? bvl : bql) + (size_t)head * 128 * KTOT;
    float* C = (isV ? vs : qs) + (size_t)blockIdx.x * 128 * SP + head * 128;
    gemm_core(xhi + (size_t)blockIdx.x * 128 * KTOT, xlo + (size_t)blockIdx.x * 128 * KTOT,
              Bh, Bl, C, SP, 1);
}

__global__ __launch_bounds__(256, 2) void gemm_dec_bf16(
    const ushort_t* __restrict__ ahi, const ushort_t* __restrict__ alo,
    const ushort_t* __restrict__ bh, const ushort_t* __restrict__ bl,
    float* __restrict__ out)
{
    gemm_core(ahi + (size_t)blockIdx.x * 128 * KTOT, alo + (size_t)blockIdx.x * 128 * KTOT,
              bh + (size_t)blockIdx.y * 128 * KTOT, bl + (size_t)blockIdx.y * 128 * KTOT,
              out + (size_t)blockIdx.x * 128 * DENSE + blockIdx.y * 128, DENSE, 0);
}

// ---------------- sig reduction ----------------
__global__ void reduce_sig_a(const float* __restrict__ qs, float* __restrict__ part)
{
    const int b = blockIdx.x;
    const int col = blockIdx.y * 128 + threadIdx.x;
    const int tz = blockIdx.z;
    const int t0 = tz * (TT / TCH);
    const float* p = qs + ((size_t)b * TT + t0) * SP + col;
    float s = 0.f, s8 = 0.f;
#pragma unroll 4
    for (int t = 0; t < TT / TCH; t++) {
        float v = p[(size_t)t * SP];
        s += v;
        if (((t0 + t) & 7) == 0) s8 += v;
    }
    part[((size_t)b * TCH + tz) * SP + col] = s;
    part[(size_t)BB * TCH * SP + ((size_t)b * TCH + tz) * SP + col] = s8;
}

__global__ void reduce_sig_b(const float* __restrict__ part, float* __restrict__ sig)
{
    const int b = blockIdx.x;
    const int col = blockIdx.y * 128 + threadIdx.x;
    float s = 0.f, s8 = 0.f;
#pragma unroll
    for (int z = 0; z < TCH; z++) {
        s  += part[((size_t)b * TCH + z) * SP + col];
        s8 += part[(size_t)BB * TCH * SP + ((size_t)b * TCH + z) * SP + col];
    }
    sig[b * SP + col] = s * (1.f / TT) + 0.5f * s8 * (1.f / (TT / 8));
}

// ---------------- parallel metric MLP ----------------
__global__ __launch_bounds__(256) void metric1_kernel(
    const float* __restrict__ sig, const float* __restrict__ w1,
    const float* __restrict__ b1, float* __restrict__ hbuf)
{
    __shared__ float red[8][32];
    const int b = blockIdx.x;
    const int j = blockIdx.y * 32 + (threadIdx.x & 31);
    const int kg = threadIdx.x >> 5;
    const float* sg = sig + b * SP;
    float s = 0.f;
#pragma unroll 4
    for (int d = kg; d < SP; d += 8)
        s = fmaf(sg[d], w1[d * 512 + j], s);
    red[kg][threadIdx.x & 31] = s;
    __syncthreads();
    if (kg == 0) {
        float acc = b1[j];
#pragma unroll
        for (int g = 0; g < 8; g++) acc += red[g][threadIdx.x & 31];
        hbuf[b * 512 + j] = 0.5f * acc * (1.f + erff(acc * 0.7071067811865475f));
    }
}

__global__ __launch_bounds__(256) void metric2_kernel(
    const float* __restrict__ hbuf, const float* __restrict__ w2,
    const float* __restrict__ b2, const float* __restrict__ base,
    float* __restrict__ metric)
{
    __shared__ float red[8][32];
    const int b = blockIdx.x;
    const int col = blockIdx.y * 32 + (threadIdx.x & 31);
    const int kg = threadIdx.x >> 5;
    const float* hb = hbuf + b * 512;
    float s = 0.f;
#pragma unroll 4
    for (int k = kg; k < 512; k += 8)
        s = fmaf(hb[k], w2[k * SP + col], s);
    red[kg][threadIdx.x & 31] = s;
    __syncthreads();
    if (kg == 0) {
        float m = b2[col];
#pragma unroll
        for (int g = 0; g < 8; g++) m += red[g][threadIdx.x & 31];
        float xv = base[col] + 0.1f * m;
        metric[b * SP + col] = fmaxf(xv, 0.f) + log1pf(expf(-fabsf(xv)));
    }
}

// ---------------- Hebbian U@V ----------------
__global__ void heb_kernel(const float* __restrict__ U, const float* __restrict__ V,
                           float* __restrict__ hebM)
{
    int h = blockIdx.x, i = threadIdx.x;
    float u[32];
#pragma unroll
    for (int r = 0; r < 32; r++) u[r] = U[h * HD * 32 + i * 32 + r];
    const float* Vh = V + h * 32 * HD;
    for (int j = 0; j < HD; j++) {
        float s = 0.f;
#pragma unroll
        for (int r = 0; r < 32; r++) s = fmaf(u[r], Vh[r * HD + j], s);
        hebM[h * HD * HD + i * HD + j] = s;
    }
}

// ---------------- Hebbian context precompute ----------------
#define HEB_SMEM ((HD*HD + 8*HD) * 4)
__global__ __launch_bounds__(256) void heb_ctx_kernel(
    const float* __restrict__ qs, const float* __restrict__ hebM,
    float* __restrict__ hebC)
{
    extern __shared__ float hsm[];
    float* HM = hsm;
    float* qrow = hsm + HD * HD;
    const int h = blockIdx.y;
    const int row0 = blockIdx.x * 32;
    const int tid = threadIdx.x, warp = tid >> 5, lane = tid & 31;

    const float* src = hebM + h * HD * HD;
    for (int i = tid * 4; i < HD * HD; i += 1024)
        *reinterpret_cast<float4*>(HM + i) = *reinterpret_cast<const float4*>(src + i);
    __syncthreads();

    float* qw = qrow + warp * HD;
#pragma unroll 1
    for (int it = 0; it < 4; it++) {
        const int r = row0 + warp * 4 + it;
        const float* q = qs + (size_t)r * SP + h * HD;
        float q0 = q[lane], q1 = q[lane + 32], q2 = q[lane + 64], q3 = q[lane + 96];
        qw[lane] = q0; qw[lane + 32] = q1; qw[lane + 64] = q2; qw[lane + 96] = q3;
        float nq = q0 * q0 + q1 * q1 + q2 * q2 + q3 * q3;
#pragma unroll
        for (int o = 16; o; o >>= 1) nq += __shfl_xor_sync(0xffffffffu, nq, o);
        const float nrm = sqrtf(nq);
        const float sc = (nrm > 0.2f) ? (0.1f / fmaxf(nrm, 1e-12f)) : 0.f;
        __syncwarp();

        float a0 = 0.f, a1 = 0.f, a2 = 0.f, a3 = 0.f;
        const int j = lane * 4;
#pragma unroll 8
        for (int e = 0; e < HD; e++) {
            float qe = qw[e];
            float4 hv = *reinterpret_cast<const float4*>(HM + e * HD + j);
            a0 = fmaf(qe, hv.x, a0);
            a1 = fmaf(qe, hv.y, a1);
            a2 = fmaf(qe, hv.z, a2);
            a3 = fmaf(qe, hv.w, a3);
        }
        float4 o4 = { a0 * sc, a1 * sc, a2 * sc, a3 * sc };
        *reinterpret_cast<float4*>(hebC + (size_t)r * SP + h * HD + j) = o4;
        __syncwarp();
    }
}

// ---------------- windowed metric attention ----------------
#define TTILE 32
#define NROWS 95
#define RSTR 129
#define ATTN_SMEM ((2*NROWS*RSTR + 128) * 4)

__global__ __launch_bounds__(256) void attn_kernel(
    const float* __restrict__ qs, const float* __restrict__ vs,
    const float* __restrict__ metric, const float* __restrict__ hebC,
    ushort_t* __restrict__ osHi, ushort_t* __restrict__ osLo)
{
    extern __shared__ float sm[];
    float* q_s = sm;
    float* v_s = q_s + NROWS * RSTR;
    float* met_s = v_s + NROWS * RSTR;
    __shared__ float d_s[8][WIN];
    __shared__ float wsel[8][TOPK];
    __shared__ int   rsel[8][TOPK];

    const int t0 = blockIdx.x * TTILE;
    const int h = blockIdx.y;
    const int b = blockIdx.z;
    const int tid = threadIdx.x;
    const int warp = tid >> 5, lane = tid & 31;

    const size_t baseRow = (size_t)b * TT * SP;
    for (int i = tid; i < NROWS * HD; i += 256) {
        int s = i >> 7, e = i & 127;
        int g = t0 - (WIN - 1) + s; if (g < 0) g = 0;
        size_t gi = baseRow + (size_t)g * SP + h * HD + e;
        q_s[s * RSTR + e] = qs[gi];
        v_s[s * RSTR + e] = vs[gi];
    }
    if (tid < 128) met_s[tid] = metric[b * SP + h * HD + tid];
    __syncthreads();

    for (int it = 0; it < 4; it++) {
        const int t = t0 + warp * 4 + it;
        const int qrow = t - t0 + (WIN - 1);
        const float* qr = q_s + qrow * RSTR;

        int gg0 = t - lane;        if (gg0 < 0) gg0 = 0;
        int gg1 = t - lane - 32;   if (gg1 < 0) gg1 = 0;
        const int r0 = gg0 - t0 + (WIN - 1);
        const int r1 = gg1 - t0 + (WIN - 1);
        const float* p0 = q_s + r0 * RSTR;
        const float* p1 = q_s + r1 * RSTR;

        float d0 = 0.f, d1 = 0.f;
#pragma unroll 8
        for (int e = 0; e < HD; e++) {
            float qv = qr[e], m = met_s[e];
            float a = qv - p0[e]; d0 = fmaf(a * a, m, d0);
            float c = qv - p1[e]; d1 = fmaf(c * c, m, d1);
        }
        float dist0 = sqrtf(d0 + 1e-8f);
        float dist1 = sqrtf(d1 + 1e-8f);
        d_s[warp][lane] = dist0;
        d_s[warp][lane + 32] = dist1;
        __syncwarp();

        int rk0 = 0, rk1 = 0;
        const int j1 = lane + 32;
#pragma unroll 8
        for (int j = 0; j < WIN; j++) {
            float dj = d_s[warp][j];
            rk0 += (dj < dist0) || (dj == dist0 && j < lane);
            rk1 += (dj < dist1) || (dj == dist1 && j < j1);
        }
        if (rk0 < TOPK) { wsel[warp][rk0] = expf(-dist0); rsel[warp][rk0] = r0; }
        if (rk1 < TOPK) { wsel[warp][rk1] = expf(-dist1); rsel[warp][rk1] = r1; }
        __syncwarp();

        float wsum = wsel[warp][lane];
#pragma unroll
        for (int o = 16; o; o >>= 1) wsum += __shfl_xor_sync(0xffffffffu, wsum, o);
        const float inv = 1.f / (wsum + 1e-8f);

        float c0 = 0.f, c1 = 0.f, c2 = 0.f, c3 = 0.f;
#pragma unroll 4
        for (int k = 0; k < TOPK; k++) {
            float wk = wsel[warp][k];
            const float* vr = v_s + rsel[warp][k] * RSTR;
            c0 = fmaf(wk, vr[lane], c0);
            c1 = fmaf(wk, vr[lane + 32], c1);
            c2 = fmaf(wk, vr[lane + 64], c2);
            c3 = fmaf(wk, vr[lane + 96], c3);
        }

        const size_t ob = baseRow + (size_t)t * SP + h * HD;
        c0 = c0 * inv + hebC[ob + lane];
        c1 = c1 * inv + hebC[ob + lane + 32];
        c2 = c2 * inv + hebC[ob + lane + 64];
        c3 = c3 * inv + hebC[ob + lane + 96];

        const float q0 = qr[lane], q1 = qr[lane + 32], q2 = qr[lane + 64], q3 = qr[lane + 96];
        ushort_t hh, ll;
        split_bf16(q0 * c0, hh, ll); osHi[ob + lane]      = hh; osLo[ob + lane]      = ll;
        split_bf16(q1 * c1, hh, ll); osHi[ob + lane + 32] = hh; osLo[ob + lane + 32] = ll;
        split_bf16(q2 * c2, hh, ll); osHi[ob + lane + 64] = hh; osLo[ob + lane + 64] = ll;
        split_bf16(q3 * c3, hh, ll); osHi[ob + lane + 96] = hh; osLo[ob + lane + 96] = ll;
    }
}

// ---------------- launcher ----------------
extern "C" void kernel_launch(void* const* d_in, const int* in_sizes, int n_in,
                              void* d_out, int out_size)
{
    const float* x      = (const float*)d_in[0];
    const float* enc_q  = (const float*)d_in[1];
    const float* enc_v  = (const float*)d_in[2];
    const float* w1     = (const float*)d_in[3];
    const float* b1     = (const float*)d_in[4];
    const float* w2     = (const float*)d_in[5];
    const float* b2     = (const float*)d_in[6];
    const float* basem  = (const float*)d_in[7];
    const float* hebU   = (const float*)d_in[8];
    const float* hebV   = (const float*)d_in[9];
    const float* dec    = (const float*)d_in[10];
    float* out = (float*)d_out;

    float *qs, *vs, *hebc, *part, *sig, *hbuf, *metric, *hebM;
    ushort_t *xhi, *xlo, *bqh, *bql, *bvh, *bvl, *bdh, *bdl, *oshi, *oslo;
    cudaGetSymbolAddress((void**)&qs, g_qs);
    cudaGetSymbolAddress((void**)&vs, g_vs);
    cudaGetSymbolAddress((void**)&hebc, g_hebC);
    cudaGetSymbolAddress((void**)&part, g_part);
    cudaGetSymbolAddress((void**)&sig, g_sig);
    cudaGetSymbolAddress((void**)&hbuf, g_hbuf);
    cudaGetSymbolAddress((void**)&metric, g_metric);
    cudaGetSymbolAddress((void**)&hebM, g_heb);
    cudaGetSymbolAddress((void**)&xhi, g_x_hi);
    cudaGetSymbolAddress((void**)&xlo, g_x_lo);
    cudaGetSymbolAddress((void**)&bqh, g_btq_hi);
    cudaGetSymbolAddress((void**)&bql, g_btq_lo);
    cudaGetSymbolAddress((void**)&bvh, g_btv_hi);
    cudaGetSymbolAddress((void**)&bvl, g_btv_lo);
    cudaGetSymbolAddress((void**)&bdh, g_btd_hi);
    cudaGetSymbolAddress((void**)&bdl, g_btd_lo);
    cudaGetSymbolAddress((void**)&oshi, g_os_hi);
    cudaGetSymbolAddress((void**)&oslo, g_os_lo);

    cudaFuncSetAttribute(attn_kernel, cudaFuncAttributeMaxDynamicSharedMemorySize, ATTN_SMEM);
    cudaFuncSetAttribute(heb_ctx_kernel, cudaFuncAttributeMaxDynamicSharedMemorySize, HEB_SMEM);
    cudaFuncSetAttribute(gemm_enc_bf16, cudaFuncAttributeMaxDynamicSharedMemorySize, GEMM_SMEM);
    cudaFuncSetAttribute(gemm_dec_bf16, cudaFuncAttributeMaxDynamicSharedMemorySize, GEMM_SMEM);

    // 1-3: splits needed by encoder
    split_x_kernel<<<MT * DENSE / 1024, 256>>>(x, xhi, xlo);
    transpose_split_kernel<<<dim3(32, 4, NH), dim3(32, 8)>>>(enc_q, HD, bqh, bql,
                                                             (long)DENSE * HD, (long)HD * DENSE);
    transpose_split_kernel<<<dim3(32, 4, NH), dim3(32, 8)>>>(enc_v, HD, bvh, bvl,
                                                             (long)DENSE * HD, (long)HD * DENSE);

    // 4: encoders (PROFILED SLOT)
    gemm_enc_bf16<<<dim3(MT / 128, 16), 256, GEMM_SMEM>>>(xhi, xlo, bqh, bql, bvh, bvl, qs, vs);

    // 5: hebbian matrices, 6: hebbian contexts
    heb_kernel<<<NH, HD>>>(hebU, hebV, hebM);
    heb_ctx_kernel<<<dim3(MT / 32, NH), 256, HEB_SMEM>>>(qs, hebM, hebc);

    // 7: decoder weight transpose
    transpose_split_kernel<<<dim3(32, 32, 1), dim3(32, 8)>>>(dec, DENSE, bdh, bdl, 0, 0);

    // 8,9: sig reduction
    reduce_sig_a<<<dim3(BB, SP / 128, TCH), 128>>>(qs, part);
    reduce_sig_b<<<dim3(BB, SP / 128), 128>>>(part, sig);

    // 10,11: parallel metric MLP
    metric1_kernel<<<dim3(BB, 16), 256>>>(sig, w1, b1, hbuf);
    metric2_kernel<<<dim3(BB, 32), 256>>>(hbuf, w2, b2, basem, metric);

    // 12: attention (+hebC add)
    attn_kernel<<<dim3(TT / TTILE, NH, BB), 256, ATTN_SMEM>>>(qs, vs, metric, hebc, oshi, oslo);

    // 13: decoder
    gemm_dec_bf16<<<dim3(MT / 128, SP / 128), 256, GEMM_SMEM>>>(oshi, oslo, bdh, bdl, out);
}

// round 11
// speedup vs baseline: 2.8398x; 1.0179x over previous
#include <cuda_runtime.h>
#include <cuda_bf16.h>
#include <math.h>

// Problem constants
#define BB 2
#define TT 2048
#define DENSE 1024
#define NH 8
#define HD 128
#define WIN 64
#define TOPK 32
#define MT (BB*TT)          // 4096 rows
#define SP 1024             // NH*HD
#define TCH 8               // t-chunks for sig reduction

// GEMM tiling: 128x128 tile, KC=16, 3-stage cp.async ring, 2 CTAs/SM
#define KTOT 1024
#define KC3 16
#define STR3 24                   // smem row stride in bf16 elems (48B, conflict-free ldsm)
#define TILE3 (128*STR3)          // 3072 elems
#define STAGE3 (4*TILE3)          // Ah, Al, Bh, Bl
#define NBUF 3
#define GEMM_SMEM (NBUF*STAGE3*2) // 73728 B

typedef unsigned short ushort_t;
typedef unsigned int uint32;

// ---------------- device scratch ----------------
__device__ float    g_qs[MT * SP];
__device__ float    g_vs[MT * SP];
__device__ float    g_hebC[MT * SP];
__device__ ushort_t g_x_hi[MT * DENSE];
__device__ ushort_t g_x_lo[MT * DENSE];
__device__ ushort_t g_btq_hi[SP * DENSE];
__device__ ushort_t g_btq_lo[SP * DENSE];
__device__ ushort_t g_btv_hi[SP * DENSE];
__device__ ushort_t g_btv_lo[SP * DENSE];
__device__ ushort_t g_btd_hi[DENSE * SP];
__device__ ushort_t g_btd_lo[DENSE * SP];
__device__ ushort_t g_os_hi[MT * SP];
__device__ ushort_t g_os_lo[MT * SP];
__device__ float    g_part[2 * BB * TCH * SP];
__device__ float    g_sig[BB * SP];
__device__ float    g_hbuf[BB * (SP/2)];
__device__ float    g_metric[BB * SP];
__device__ float    g_heb[NH * HD * HD];

// ---------------- asm helpers ----------------
__device__ __forceinline__ unsigned smem_u32(const void* p) {
    return (unsigned)__cvta_generic_to_shared(p);
}
__device__ __forceinline__ void cp16(unsigned dst, const void* src) {
    asm volatile("cp.async.cg.shared.global [%0], [%1], 16;" :: "r"(dst), "l"(src));
}
__device__ __forceinline__ void cp_commit() { asm volatile("cp.async.commit_group;"); }
template<int N> __device__ __forceinline__ void cp_wait() {
    asm volatile("cp.async.wait_group %0;" :: "n"(N));
}
__device__ __forceinline__ void ldsm4(uint32& r0, uint32& r1, uint32& r2, uint32& r3,
                                      unsigned addr) {
    asm volatile("ldmatrix.sync.aligned.m8n8.x4.shared.b16 {%0,%1,%2,%3}, [%4];"
                 : "=r"(r0), "=r"(r1), "=r"(r2), "=r"(r3) : "r"(addr));
}
__device__ __forceinline__ void mma16816(float* d, const uint32* a, const uint32* b) {
    asm volatile(
        "mma.sync.aligned.m16n8k16.row.col.f32.bf16.bf16.f32 "
        "{%0,%1,%2,%3}, {%4,%5,%6,%7}, {%8,%9}, {%0,%1,%2,%3};"
        : "+f"(d[0]), "+f"(d[1]), "+f"(d[2]), "+f"(d[3])
        : "r"(a[0]), "r"(a[1]), "r"(a[2]), "r"(a[3]), "r"(b[0]), "r"(b[1]));
}
__device__ __forceinline__ void split_bf16(float v, ushort_t& hi, ushort_t& lo) {
    __nv_bfloat16 h = __float2bfloat16_rn(v);
    float hf = __bfloat162float(h);
    __nv_bfloat16 l = __float2bfloat16_rn(v - hf);
    hi = __bfloat16_as_ushort(h);
    lo = __bfloat16_as_ushort(l);
}

// ---------------- split / transpose-split kernels ----------------
__global__ void split_x_kernel(const float* __restrict__ x,
                               ushort_t* __restrict__ xhi, ushort_t* __restrict__ xlo)
{
    int i = (blockIdx.x * 256 + threadIdx.x) * 4;
    float4 v = *reinterpret_cast<const float4*>(x + i);
    ushort_t h0,l0,h1,l1,h2,l2,h3,l3;
    split_bf16(v.x,h0,l0); split_bf16(v.y,h1,l1);
    split_bf16(v.z,h2,l2); split_bf16(v.w,h3,l3);
    ushort4 hv = {h0,h1,h2,h3}, lv = {l0,l1,l2,l3};
    *reinterpret_cast<ushort4*>(xhi + i) = hv;
    *reinterpret_cast<ushort4*>(xlo + i) = lv;
}

__global__ void transpose_split_kernel(const float* __restrict__ In, int nld,
                                       ushort_t* __restrict__ outHi, ushort_t* __restrict__ outLo,
                                       long strideIn, long strideOut)
{
    __shared__ float tile[32][33];
    const float* in = In + (long)blockIdx.z * strideIn;
    ushort_t* oh = outHi + (long)blockIdx.z * strideOut;
    ushort_t* ol = outLo + (long)blockIdx.z * strideOut;
    int k0 = blockIdx.x * 32, n0 = blockIdx.y * 32;
    int tx = threadIdx.x, ty = threadIdx.y;
#pragma unroll
    for (int i = 0; i < 4; i++) {
        int k = ty * 4 + i;
        tile[k][tx] = in[(size_t)(k0 + k) * nld + n0 + tx];
    }
    __syncthreads();
#pragma unroll
    for (int i = 0; i < 4; i++) {
        int n = ty * 4 + i;
        float v = tile[tx][n];
        ushort_t h, l; split_bf16(v, h, l);
        oh[(size_t)(n0 + n) * 1024 + k0 + tx] = h;
        ol[(size_t)(n0 + n) * 1024 + k0 + tx] = l;
    }
}

// ---------------- bf16 split-precision HMMA GEMM core (3-stage, 2 CTA/SM) ----------------
__device__ __forceinline__ void gemm_core(
    const ushort_t* __restrict__ Ah, const ushort_t* __restrict__ Al,
    const ushort_t* __restrict__ Bh, const ushort_t* __restrict__ Bl,
    float* __restrict__ Cblk, int ldc, int relu)
{
    extern __shared__ ushort_t smem[];

    const int tid = threadIdx.x;
    const int warp = tid >> 5, lane = tid & 31;
    const int wm = warp & 3, wn = warp >> 2;

    const int ldRow = tid >> 1, ldSeg = (tid & 1) * 8;
    const ushort_t* srcs[4] = { Ah, Al, Bh, Bl };

    unsigned aOff[2];
#pragma unroll
    for (int mt = 0; mt < 2; mt++)
        aOff[mt] = (unsigned)(((wm * 32 + mt * 16 + (lane & 15)) * STR3 + (lane >> 4) * 8) * 2);
    unsigned bOff[4];
#pragma unroll
    for (int g = 0; g < 4; g++)
        bOff[g] = (unsigned)(((wn * 64 + g * 16 + (lane & 7) + (lane >> 4) * 8) * STR3
                              + ((lane >> 3) & 1) * 8) * 2);

    float acc[2][8][4];
#pragma unroll
    for (int mt = 0; mt < 2; mt++)
#pragma unroll
        for (int nt = 0; nt < 8; nt++)
#pragma unroll
            for (int r = 0; r < 4; r++) acc[mt][nt][r] = 0.f;

#define PREFETCH(stage, k0)                                                     \
    {                                                                           \
        ushort_t* stb = smem + (stage) * STAGE3;                                \
        _Pragma("unroll")                                                       \
        for (int m = 0; m < 4; m++) {                                           \
            cp16(smem_u32(stb + m * TILE3 + ldRow * STR3 + ldSeg),              \
                 srcs[m] + (size_t)ldRow * KTOT + (k0) + ldSeg);                \
        }                                                                       \
        cp_commit();                                                            \
    }

    const int nk = KTOT / KC3;     // 64
    PREFETCH(0, 0);
    PREFETCH(1, KC3);

    int cur = 0;
    for (int i = 0; i < nk; i++) {
        if (i + 1 < nk) cp_wait<1>(); else cp_wait<0>();
        __syncthreads();
        if (i + 2 < nk) {
            int nstage = cur + 2; if (nstage >= NBUF) nstage -= NBUF;
            PREFETCH(nstage, (i + 2) * KC3);
        }

        const unsigned stb = smem_u32(smem + cur * STAGE3);
        const unsigned bAh = stb;
        const unsigned bAl = stb + TILE3 * 2;
        const unsigned bBh = stb + 2 * TILE3 * 2;
        const unsigned bBl = stb + 3 * TILE3 * 2;

        uint32 ah[2][4], al[2][4], b[8][2];
#pragma unroll
        for (int mt = 0; mt < 2; mt++) {
            ldsm4(ah[mt][0], ah[mt][1], ah[mt][2], ah[mt][3], bAh + aOff[mt]);
            ldsm4(al[mt][0], al[mt][1], al[mt][2], al[mt][3], bAl + aOff[mt]);
        }
#pragma unroll
        for (int g = 0; g < 4; g++) {
            uint32 r0, r1, r2, r3;
            ldsm4(r0, r1, r2, r3, bBh + bOff[g]);
            b[2*g][0] = r0; b[2*g][1] = r1; b[2*g+1][0] = r2; b[2*g+1][1] = r3;
        }
#pragma unroll
        for (int mt = 0; mt < 2; mt++)
#pragma unroll
            for (int nt = 0; nt < 8; nt++) {
                mma16816(acc[mt][nt], ah[mt], b[nt]);
                mma16816(acc[mt][nt], al[mt], b[nt]);
            }
#pragma unroll
        for (int g = 0; g < 4; g++) {
            uint32 r0, r1, r2, r3;
            ldsm4(r0, r1, r2, r3, bBl + bOff[g]);
            b[2*g][0] = r0; b[2*g][1] = r1; b[2*g+1][0] = r2; b[2*g+1][1] = r3;
        }
#pragma unroll
        for (int mt = 0; mt < 2; mt++)
#pragma unroll
            for (int nt = 0; nt < 8; nt++)
                mma16816(acc[mt][nt], ah[mt], b[nt]);

        cur++; if (cur >= NBUF) cur = 0;
    }
#undef PREFETCH

#pragma unroll
    for (int mt = 0; mt < 2; mt++) {
        const int r0 = wm * 32 + mt * 16 + (lane >> 2);
#pragma unroll
        for (int nt = 0; nt < 8; nt++) {
            const int c = wn * 64 + nt * 8 + 2 * (lane & 3);
            float2 v0 = { acc[mt][nt][0], acc[mt][nt][1] };
            float2 v1 = { acc[mt][nt][2], acc[mt][nt][3] };
            if (relu) {
                v0.x = fmaxf(v0.x, 0.f); v0.y = fmaxf(v0.y, 0.f);
                v1.x = fmaxf(v1.x, 0.f); v1.y = fmaxf(v1.y, 0.f);
            }
            *reinterpret_cast<float2*>(Cblk + (size_t)r0 * ldc + c) = v0;
            *reinterpret_cast<float2*>(Cblk + (size_t)(r0 + 8) * ldc + c) = v1;
        }
    }
}

__global__ __launch_bounds__(256, 2) void gemm_enc_bf16(
    const ushort_t* __restrict__ xhi, const ushort_t* __restrict__ xlo,
    const ushort_t* __restrict__ bqh, const ushort_t* __restrict__ bql,
    const ushort_t* __restrict__ bvh, const ushort_t* __restrict__ bvl,
    float* __restrict__ qs, float* __restrict__ vs)
{
    const int y = blockIdx.y;
    const int isV = y >> 3, head = y & 7;
    const ushort_t* Bh = (isV ? bvh : bqh) + (size_t)head * 128 * KTOT;
    const ushort_t* Bl = (isV ? bvl : bql) + (size_t)head * 128 * KTOT;
    float* C = (isV ? vs : qs) + (size_t)blockIdx.x * 128 * SP + head * 128;
    gemm_core(xhi + (size_t)blockIdx.x * 128 * KTOT, xlo + (size_t)blockIdx.x * 128 * KTOT,
              Bh, Bl, C, SP, 1);
}

__global__ __launch_bounds__(256, 2) void gemm_dec_bf16(
    const ushort_t* __restrict__ ahi, const ushort_t* __restrict__ alo,
    const ushort_t* __restrict__ bh, const ushort_t* __restrict__ bl,
    float* __restrict__ out)
{
    gemm_core(ahi + (size_t)blockIdx.x * 128 * KTOT, alo + (size_t)blockIdx.x * 128 * KTOT,
              bh + (size_t)blockIdx.y * 128 * KTOT, bl + (size_t)blockIdx.y * 128 * KTOT,
              out + (size_t)blockIdx.x * 128 * DENSE + blockIdx.y * 128, DENSE, 0);
}

// ---------------- sig reduction ----------------
__global__ void reduce_sig_a(const float* __restrict__ qs, float* __restrict__ part)
{
    const int b = blockIdx.x;
    const int col = blockIdx.y * 128 + threadIdx.x;
    const int tz = blockIdx.z;
    const int t0 = tz * (TT / TCH);
    const float* p = qs + ((size_t)b * TT + t0) * SP + col;
    float s = 0.f, s8 = 0.f;
#pragma unroll 4
    for (int t = 0; t < TT / TCH; t++) {
        float v = p[(size_t)t * SP];
        s += v;
        if (((t0 + t) & 7) == 0) s8 += v;
    }
    part[((size_t)b * TCH + tz) * SP + col] = s;
    part[(size_t)BB * TCH * SP + ((size_t)b * TCH + tz) * SP + col] = s8;
}

__global__ void reduce_sig_b(const float* __restrict__ part, float* __restrict__ sig)
{
    const int b = blockIdx.x;
    const int col = blockIdx.y * 128 + threadIdx.x;
    float s = 0.f, s8 = 0.f;
#pragma unroll
    for (int z = 0; z < TCH; z++) {
        s  += part[((size_t)b * TCH + z) * SP + col];
        s8 += part[(size_t)BB * TCH * SP + ((size_t)b * TCH + z) * SP + col];
    }
    sig[b * SP + col] = s * (1.f / TT) + 0.5f * s8 * (1.f / (TT / 8));
}

// ---------------- parallel metric MLP ----------------
__global__ __launch_bounds__(256) void metric1_kernel(
    const float* __restrict__ sig, const float* __restrict__ w1,
    const float* __restrict__ b1, float* __restrict__ hbuf)
{
    __shared__ float red[8][32];
    const int b = blockIdx.x;
    const int j = blockIdx.y * 32 + (threadIdx.x & 31);
    const int kg = threadIdx.x >> 5;
    const float* sg = sig + b * SP;
    float s = 0.f;
#pragma unroll 4
    for (int d = kg; d < SP; d += 8)
        s = fmaf(sg[d], w1[d * 512 + j], s);
    red[kg][threadIdx.x & 31] = s;
    __syncthreads();
    if (kg == 0) {
        float acc = b1[j];
#pragma unroll
        for (int g = 0; g < 8; g++) acc += red[g][threadIdx.x & 31];
        hbuf[b * 512 + j] = 0.5f * acc * (1.f + erff(acc * 0.7071067811865475f));
    }
}

__global__ __launch_bounds__(256) void metric2_kernel(
    const float* __restrict__ hbuf, const float* __restrict__ w2,
    const float* __restrict__ b2, const float* __restrict__ base,
    float* __restrict__ metric)
{
    __shared__ float red[8][32];
    const int b = blockIdx.x;
    const int col = blockIdx.y * 32 + (threadIdx.x & 31);
    const int kg = threadIdx.x >> 5;
    const float* hb = hbuf + b * 512;
    float s = 0.f;
#pragma unroll 4
    for (int k = kg; k < 512; k += 8)
        s = fmaf(hb[k], w2[k * SP + col], s);
    red[kg][threadIdx.x & 31] = s;
    __syncthreads();
    if (kg == 0) {
        float m = b2[col];
#pragma unroll
        for (int g = 0; g < 8; g++) m += red[g][threadIdx.x & 31];
        float xv = base[col] + 0.1f * m;
        metric[b * SP + col] = fmaxf(xv, 0.f) + log1pf(expf(-fabsf(xv)));
    }
}

// ---------------- Hebbian U@V ----------------
__global__ void heb_kernel(const float* __restrict__ U, const float* __restrict__ V,
                           float* __restrict__ hebM)
{
    int h = blockIdx.x, i = threadIdx.x;
    float u[32];
#pragma unroll
    for (int r = 0; r < 32; r++) u[r] = U[h * HD * 32 + i * 32 + r];
    const float* Vh = V + h * 32 * HD;
    for (int j = 0; j < HD; j++) {
        float s = 0.f;
#pragma unroll
        for (int r = 0; r < 32; r++) s = fmaf(u[r], Vh[r * HD + j], s);
        hebM[h * HD * HD + i * HD + j] = s;
    }
}

// ---------------- Hebbian context precompute ----------------
#define HEB_SMEM ((HD*HD + 8*HD) * 4)
__global__ __launch_bounds__(256) void heb_ctx_kernel(
    const float* __restrict__ qs, const float* __restrict__ hebM,
    float* __restrict__ hebC)
{
    extern __shared__ float hsm[];
    float* HM = hsm;
    float* qrow = hsm + HD * HD;
    const int h = blockIdx.y;
    const int row0 = blockIdx.x * 32;
    const int tid = threadIdx.x, warp = tid >> 5, lane = tid & 31;

    const float* src = hebM + h * HD * HD;
    for (int i = tid * 4; i < HD * HD; i += 1024)
        *reinterpret_cast<float4*>(HM + i) = *reinterpret_cast<const float4*>(src + i);
    __syncthreads();

    float* qw = qrow + warp * HD;
#pragma unroll 1
    for (int it = 0; it < 4; it++) {
        const int r = row0 + warp * 4 + it;
        const float* q = qs + (size_t)r * SP + h * HD;
        float q0 = q[lane], q1 = q[lane + 32], q2 = q[lane + 64], q3 = q[lane + 96];
        qw[lane] = q0; qw[lane + 32] = q1; qw[lane + 64] = q2; qw[lane + 96] = q3;
        float nq = q0 * q0 + q1 * q1 + q2 * q2 + q3 * q3;
#pragma unroll
        for (int o = 16; o; o >>= 1) nq += __shfl_xor_sync(0xffffffffu, nq, o);
        const float nrm = sqrtf(nq);
        const float sc = (nrm > 0.2f) ? (0.1f / fmaxf(nrm, 1e-12f)) : 0.f;
        __syncwarp();

        float a0 = 0.f, a1 = 0.f, a2 = 0.f, a3 = 0.f;
        const int j = lane * 4;
#pragma unroll 8
        for (int e = 0; e < HD; e++) {
            float qe = qw[e];
            float4 hv = *reinterpret_cast<const float4*>(HM + e * HD + j);
            a0 = fmaf(qe, hv.x, a0);
            a1 = fmaf(qe, hv.y, a1);
            a2 = fmaf(qe, hv.z, a2);
            a3 = fmaf(qe, hv.w, a3);
        }
        float4 o4 = { a0 * sc, a1 * sc, a2 * sc, a3 * sc };
        *reinterpret_cast<float4*>(hebC + (size_t)r * SP + h * HD + j) = o4;
        __syncwarp();
    }
}

// ---------------- windowed metric attention (float4 smem everywhere) ----------------
#define TTILE 32
#define NROWS 95
#define RSTR 132            // 16B-aligned rows, conflict-free float4 phases
#define ATTN_SMEM ((2*NROWS*RSTR + 128) * 4)

__global__ __launch_bounds__(256) void attn_kernel(
    const float* __restrict__ qs, const float* __restrict__ vs,
    const float* __restrict__ metric, const float* __restrict__ hebC,
    ushort_t* __restrict__ osHi, ushort_t* __restrict__ osLo)
{
    extern __shared__ float sm[];
    float* q_s = sm;
    float* v_s = q_s + NROWS * RSTR;
    float* met_s = v_s + NROWS * RSTR;
    __shared__ float d_s[8][WIN];
    __shared__ float wsel[8][TOPK];
    __shared__ int   rsel[8][TOPK];

    const int t0 = blockIdx.x * TTILE;
    const int h = blockIdx.y;
    const int b = blockIdx.z;
    const int tid = threadIdx.x;
    const int warp = tid >> 5, lane = tid & 31;

    const size_t baseRow = (size_t)b * TT * SP;
    // fill: float4 loads/stores (NROWS*32 float4 chunks)
    for (int i = tid; i < NROWS * 32; i += 256) {
        int s = i >> 5, e4 = (i & 31) * 4;
        int g = t0 - (WIN - 1) + s; if (g < 0) g = 0;
        size_t gi = baseRow + (size_t)g * SP + h * HD + e4;
        *reinterpret_cast<float4*>(q_s + s * RSTR + e4) =
            *reinterpret_cast<const float4*>(qs + gi);
        *reinterpret_cast<float4*>(v_s + s * RSTR + e4) =
            *reinterpret_cast<const float4*>(vs + gi);
    }
    if (tid < 32)
        *reinterpret_cast<float4*>(met_s + tid * 4) =
            *reinterpret_cast<const float4*>(metric + b * SP + h * HD + tid * 4);
    __syncthreads();

    for (int it = 0; it < 4; it++) {
        const int t = t0 + warp * 4 + it;
        const int qrow = t - t0 + (WIN - 1);
        const float* qr = q_s + qrow * RSTR;

        int gg0 = t - lane;        if (gg0 < 0) gg0 = 0;
        int gg1 = t - lane - 32;   if (gg1 < 0) gg1 = 0;
        const int r0 = gg0 - t0 + (WIN - 1);
        const int r1 = gg1 - t0 + (WIN - 1);
        const float* p0 = q_s + r0 * RSTR;
        const float* p1 = q_s + r1 * RSTR;

        float d0 = 0.f, d1 = 0.f;
#pragma unroll 8
        for (int e = 0; e < HD; e += 4) {
            float4 qv = *reinterpret_cast<const float4*>(qr + e);
            float4 m4 = *reinterpret_cast<const float4*>(met_s + e);
            float4 a4 = *reinterpret_cast<const float4*>(p0 + e);
            float4 b4 = *reinterpret_cast<const float4*>(p1 + e);
            float a;
            a = qv.x - a4.x; d0 = fmaf(a * a, m4.x, d0);
            a = qv.y - a4.y; d0 = fmaf(a * a, m4.y, d0);
            a = qv.z - a4.z; d0 = fmaf(a * a, m4.z, d0);
            a = qv.w - a4.w; d0 = fmaf(a * a, m4.w, d0);
            a = qv.x - b4.x; d1 = fmaf(a * a, m4.x, d1);
            a = qv.y - b4.y; d1 = fmaf(a * a, m4.y, d1);
            a = qv.z - b4.z; d1 = fmaf(a * a, m4.z, d1);
            a = qv.w - b4.w; d1 = fmaf(a * a, m4.w, d1);
        }
        float dist0 = sqrtf(d0 + 1e-8f);
        float dist1 = sqrtf(d1 + 1e-8f);
        d_s[warp][lane] = dist0;
        d_s[warp][lane + 32] = dist1;
        __syncwarp();

        int rk0 = 0, rk1 = 0;
        const int j1 = lane + 32;
#pragma unroll 8
        for (int j = 0; j < WIN; j++) {
            float dj = d_s[warp][j];
            rk0 += (dj < dist0) || (dj == dist0 && j < lane);
            rk1 += (dj < dist1) || (dj == dist1 && j < j1);
        }
        if (rk0 < TOPK) { wsel[warp][rk0] = expf(-dist0); rsel[warp][rk0] = r0; }
        if (rk1 < TOPK) { wsel[warp][rk1] = expf(-dist1); rsel[warp][rk1] = r1; }
        __syncwarp();

        float wsum = wsel[warp][lane];
#pragma unroll
        for (int o = 16; o; o >>= 1) wsum += __shfl_xor_sync(0xffffffffu, wsum, o);
        const float inv = 1.f / (wsum + 1e-8f);

        // context: each lane owns dims e0..e0+3
        const int e0 = lane * 4;
        float c0 = 0.f, c1 = 0.f, c2 = 0.f, c3 = 0.f;
#pragma unroll 4
        for (int k = 0; k < TOPK; k++) {
            float wk = wsel[warp][k];
            float4 v4 = *reinterpret_cast<const float4*>(v_s + rsel[warp][k] * RSTR + e0);
            c0 = fmaf(wk, v4.x, c0);
            c1 = fmaf(wk, v4.y, c1);
            c2 = fmaf(wk, v4.z, c2);
            c3 = fmaf(wk, v4.w, c3);
        }

        const size_t ob = baseRow + (size_t)t * SP + h * HD;
        float4 hb4 = *reinterpret_cast<const float4*>(hebC + ob + e0);
        c0 = c0 * inv + hb4.x;
        c1 = c1 * inv + hb4.y;
        c2 = c2 * inv + hb4.z;
        c3 = c3 * inv + hb4.w;

        float4 q4 = *reinterpret_cast<const float4*>(qr + e0);
        ushort4 oh4, ol4;
        split_bf16(q4.x * c0, oh4.x, ol4.x);
        split_bf16(q4.y * c1, oh4.y, ol4.y);
        split_bf16(q4.z * c2, oh4.z, ol4.z);
        split_bf16(q4.w * c3, oh4.w, ol4.w);
        *reinterpret_cast<ushort4*>(osHi + ob + e0) = oh4;
        *reinterpret_cast<ushort4*>(osLo + ob + e0) = ol4;
    }
}

// ---------------- launcher ----------------
extern "C" void kernel_launch(void* const* d_in, const int* in_sizes, int n_in,
                              void* d_out, int out_size)
{
    const float* x      = (const float*)d_in[0];
    const float* enc_q  = (const float*)d_in[1];
    const float* enc_v  = (const float*)d_in[2];
    const float* w1     = (const float*)d_in[3];
    const float* b1     = (const float*)d_in[4];
    const float* w2     = (const float*)d_in[5];
    const float* b2     = (const float*)d_in[6];
    const float* basem  = (const float*)d_in[7];
    const float* hebU   = (const float*)d_in[8];
    const float* hebV   = (const float*)d_in[9];
    const float* dec    = (const float*)d_in[10];
    float* out = (float*)d_out;

    float *qs, *vs, *hebc, *part, *sig, *hbuf, *metric, *hebM;
    ushort_t *xhi, *xlo, *bqh, *bql, *bvh, *bvl, *bdh, *bdl, *oshi, *oslo;
    cudaGetSymbolAddress((void**)&qs, g_qs);
    cudaGetSymbolAddress((void**)&vs, g_vs);
    cudaGetSymbolAddress((void**)&hebc, g_hebC);
    cudaGetSymbolAddress((void**)&part, g_part);
    cudaGetSymbolAddress((void**)&sig, g_sig);
    cudaGetSymbolAddress((void**)&hbuf, g_hbuf);
    cudaGetSymbolAddress((void**)&metric, g_metric);
    cudaGetSymbolAddress((void**)&hebM, g_heb);
    cudaGetSymbolAddress((void**)&xhi, g_x_hi);
    cudaGetSymbolAddress((void**)&xlo, g_x_lo);
    cudaGetSymbolAddress((void**)&bqh, g_btq_hi);
    cudaGetSymbolAddress((void**)&bql, g_btq_lo);
    cudaGetSymbolAddress((void**)&bvh, g_btv_hi);
    cudaGetSymbolAddress((void**)&bvl, g_btv_lo);
    cudaGetSymbolAddress((void**)&bdh, g_btd_hi);
    cudaGetSymbolAddress((void**)&bdl, g_btd_lo);
    cudaGetSymbolAddress((void**)&oshi, g_os_hi);
    cudaGetSymbolAddress((void**)&oslo, g_os_lo);

    cudaFuncSetAttribute(attn_kernel, cudaFuncAttributeMaxDynamicSharedMemorySize, ATTN_SMEM);
    cudaFuncSetAttribute(heb_ctx_kernel, cudaFuncAttributeMaxDynamicSharedMemorySize, HEB_SMEM);
    cudaFuncSetAttribute(gemm_enc_bf16, cudaFuncAttributeMaxDynamicSharedMemorySize, GEMM_SMEM);
    cudaFuncSetAttribute(gemm_dec_bf16, cudaFuncAttributeMaxDynamicSharedMemorySize, GEMM_SMEM);

    // 1-3: splits needed by encoder
    split_x_kernel<<<MT * DENSE / 1024, 256>>>(x, xhi, xlo);
    transpose_split_kernel<<<dim3(32, 4, NH), dim3(32, 8)>>>(enc_q, HD, bqh, bql,
                                                             (long)DENSE * HD, (long)HD * DENSE);
    transpose_split_kernel<<<dim3(32, 4, NH), dim3(32, 8)>>>(enc_v, HD, bvh, bvl,
                                                             (long)DENSE * HD, (long)HD * DENSE);

    // 4: encoders (PROFILED SLOT)
    gemm_enc_bf16<<<dim3(MT / 128, 16), 256, GEMM_SMEM>>>(xhi, xlo, bqh, bql, bvh, bvl, qs, vs);

    // 5: hebbian matrices, 6: hebbian contexts
    heb_kernel<<<NH, HD>>>(hebU, hebV, hebM);
    heb_ctx_kernel<<<dim3(MT / 32, NH), 256, HEB_SMEM>>>(qs, hebM, hebc);

    // 7: decoder weight transpose
    transpose_split_kernel<<<dim3(32, 32, 1), dim3(32, 8)>>>(dec, DENSE, bdh, bdl, 0, 0);

    // 8,9: sig reduction
    reduce_sig_a<<<dim3(BB, SP / 128, TCH), 128>>>(qs, part);
    reduce_sig_b<<<dim3(BB, SP / 128), 128>>>(part, sig);

    // 10,11: parallel metric MLP
    metric1_kernel<<<dim3(BB, 16), 256>>>(sig, w1, b1, hbuf);
    metric2_kernel<<<dim3(BB, 32), 256>>>(hbuf, w2, b2, basem, metric);

    // 12: attention (+hebC add)
    attn_kernel<<<dim3(TT / TTILE, NH, BB), 256, ATTN_SMEM>>>(qs, vs, metric, hebc, oshi, oslo);

    // 13: decoder
    gemm_dec_bf16<<<dim3(MT / 128, SP / 128), 256, GEMM_SMEM>>>(oshi, oslo, bdh, bdl, out);
}

// round 16
// speedup vs baseline: 2.8493x; 1.0033x over previous
#include <cuda_runtime.h>
#include <cuda_bf16.h>
#include <math.h>

// Problem constants
#define BB 2
#define TT 2048
#define DENSE 1024
#define NH 8
#define HD 128
#define WIN 64
#define TOPK 32
#define MT (BB*TT)          // 4096 rows
#define SP 1024             // NH*HD
#define TCH 8               // t-chunks for sig reduction

// GEMM tiling: 128x128 tile, KC=16, 4-stage cp.async ring, sync per 2 chunks, 2 CTAs/SM
#define KTOT 1024
#define KC3 16
#define STR3 24                   // smem row stride in bf16 elems (48B, conflict-free ldsm)
#define TILE3 (128*STR3)          // 3072 elems
#define STAGE3 (4*TILE3)          // Ah, Al, Bh, Bl
#define NBUF 4
#define GEMM_SMEM (NBUF*STAGE3*2) // 98304 B

typedef unsigned short ushort_t;
typedef unsigned int uint32;

// ---------------- device scratch ----------------
__device__ float    g_qs[MT * SP];
__device__ float    g_vs[MT * SP];
__device__ float    g_hebC[MT * SP];
__device__ ushort_t g_x_hi[MT * DENSE];
__device__ ushort_t g_x_lo[MT * DENSE];
__device__ ushort_t g_btq_hi[SP * DENSE];
__device__ ushort_t g_btq_lo[SP * DENSE];
__device__ ushort_t g_btv_hi[SP * DENSE];
__device__ ushort_t g_btv_lo[SP * DENSE];
__device__ ushort_t g_btd_hi[DENSE * SP];
__device__ ushort_t g_btd_lo[DENSE * SP];
__device__ ushort_t g_os_hi[MT * SP];
__device__ ushort_t g_os_lo[MT * SP];
__device__ float    g_part[2 * BB * TCH * SP];
__device__ float    g_sig[BB * SP];
__device__ float    g_hbuf[BB * (SP/2)];
__device__ float    g_metric[BB * SP];
__device__ float    g_heb[NH * HD * HD];

// ---------------- asm helpers ----------------
__device__ __forceinline__ unsigned smem_u32(const void* p) {
    return (unsigned)__cvta_generic_to_shared(p);
}
__device__ __forceinline__ void cp16(unsigned dst, const void* src) {
    asm volatile("cp.async.cg.shared.global [%0], [%1], 16;" :: "r"(dst), "l"(src));
}
__device__ __forceinline__ void cp_commit() { asm volatile("cp.async.commit_group;"); }
template<int N> __device__ __forceinline__ void cp_wait() {
    asm volatile("cp.async.wait_group %0;" :: "n"(N));
}
__device__ __forceinline__ void ldsm4(uint32& r0, uint32& r1, uint32& r2, uint32& r3,
                                      unsigned addr) {
    asm volatile("ldmatrix.sync.aligned.m8n8.x4.shared.b16 {%0,%1,%2,%3}, [%4];"
                 : "=r"(r0), "=r"(r1), "=r"(r2), "=r"(r3) : "r"(addr));
}
__device__ __forceinline__ void mma16816(float* d, const uint32* a, const uint32* b) {
    asm volatile(
        "mma.sync.aligned.m16n8k16.row.col.f32.bf16.bf16.f32 "
        "{%0,%1,%2,%3}, {%4,%5,%6,%7}, {%8,%9}, {%0,%1,%2,%3};"
        : "+f"(d[0]), "+f"(d[1]), "+f"(d[2]), "+f"(d[3])
        : "r"(a[0]), "r"(a[1]), "r"(a[2]), "r"(a[3]), "r"(b[0]), "r"(b[1]));
}
__device__ __forceinline__ void split_bf16(float v, ushort_t& hi, ushort_t& lo) {
    __nv_bfloat16 h = __float2bfloat16_rn(v);
    float hf = __bfloat162float(h);
    __nv_bfloat16 l = __float2bfloat16_rn(v - hf);
    hi = __bfloat16_as_ushort(h);
    lo = __bfloat16_as_ushort(l);
}

// ---------------- split / transpose-split kernels ----------------
__global__ void split_x_kernel(const float* __restrict__ x,
                               ushort_t* __restrict__ xhi, ushort_t* __restrict__ xlo)
{
    int i = (blockIdx.x * 256 + threadIdx.x) * 4;
    float4 v = *reinterpret_cast<const float4*>(x + i);
    ushort_t h0,l0,h1,l1,h2,l2,h3,l3;
    split_bf16(v.x,h0,l0); split_bf16(v.y,h1,l1);
    split_bf16(v.z,h2,l2); split_bf16(v.w,h3,l3);
    ushort4 hv = {h0,h1,h2,h3}, lv = {l0,l1,l2,l3};
    *reinterpret_cast<ushort4*>(xhi + i) = hv;
    *reinterpret_cast<ushort4*>(xlo + i) = lv;
}

// merged q+v encoder weight transpose-split: grid (32, 4, 16)
__global__ void enc_transpose_kernel(const float* __restrict__ eq, const float* __restrict__ ev,
                                     ushort_t* __restrict__ qh, ushort_t* __restrict__ ql,
                                     ushort_t* __restrict__ vh, ushort_t* __restrict__ vl)
{
    __shared__ float tile[32][33];
    const int z = blockIdx.z, isV = z >> 3, head = z & 7;
    const float* in = (isV ? ev : eq) + (long)head * DENSE * HD;
    ushort_t* oh = (isV ? vh : qh) + (long)head * HD * DENSE;
    ushort_t* ol = (isV ? vl : ql) + (long)head * HD * DENSE;
    int k0 = blockIdx.x * 32, n0 = blockIdx.y * 32;
    int tx = threadIdx.x, ty = threadIdx.y;
#pragma unroll
    for (int i = 0; i < 4; i++) {
        int k = ty * 4 + i;
        tile[k][tx] = in[(size_t)(k0 + k) * HD + n0 + tx];
    }
    __syncthreads();
#pragma unroll
    for (int i = 0; i < 4; i++) {
        int n = ty * 4 + i;
        float v = tile[tx][n];
        ushort_t h, l; split_bf16(v, h, l);
        oh[(size_t)(n0 + n) * 1024 + k0 + tx] = h;
        ol[(size_t)(n0 + n) * 1024 + k0 + tx] = l;
    }
}

__global__ void transpose_split_kernel(const float* __restrict__ In, int nld,
                                       ushort_t* __restrict__ outHi, ushort_t* __restrict__ outLo,
                                       long strideIn, long strideOut)
{
    __shared__ float tile[32][33];
    const float* in = In + (long)blockIdx.z * strideIn;
    ushort_t* oh = outHi + (long)blockIdx.z * strideOut;
    ushort_t* ol = outLo + (long)blockIdx.z * strideOut;
    int k0 = blockIdx.x * 32, n0 = blockIdx.y * 32;
    int tx = threadIdx.x, ty = threadIdx.y;
#pragma unroll
    for (int i = 0; i < 4; i++) {
        int k = ty * 4 + i;
        tile[k][tx] = in[(size_t)(k0 + k) * nld + n0 + tx];
    }
    __syncthreads();
#pragma unroll
    for (int i = 0; i < 4; i++) {
        int n = ty * 4 + i;
        float v = tile[tx][n];
        ushort_t h, l; split_bf16(v, h, l);
        oh[(size_t)(n0 + n) * 1024 + k0 + tx] = h;
        ol[(size_t)(n0 + n) * 1024 + k0 + tx] = l;
    }
}

// ---------------- bf16 split-precision HMMA GEMM core (4-stage, sync/2 chunks) ----------------
__device__ __forceinline__ void gemm_core(
    const ushort_t* __restrict__ Ah, const ushort_t* __restrict__ Al,
    const ushort_t* __restrict__ Bh, const ushort_t* __restrict__ Bl,
    float* __restrict__ Cblk, int ldc, int relu)
{
    extern __shared__ ushort_t smem[];

    const int tid = threadIdx.x;
    const int warp = tid >> 5, lane = tid & 31;
    const int wm = warp & 3, wn = warp >> 2;

    const int ldRow = tid >> 1, ldSeg = (tid & 1) * 8;
    const ushort_t* srcs[4] = { Ah, Al, Bh, Bl };

    unsigned aOff[2];
#pragma unroll
    for (int mt = 0; mt < 2; mt++)
        aOff[mt] = (unsigned)(((wm * 32 + mt * 16 + (lane & 15)) * STR3 + (lane >> 4) * 8) * 2);
    unsigned bOff[4];
#pragma unroll
    for (int g = 0; g < 4; g++)
        bOff[g] = (unsigned)(((wn * 64 + g * 16 + (lane & 7) + (lane >> 4) * 8) * STR3
                              + ((lane >> 3) & 1) * 8) * 2);

    float acc[2][8][4];
#pragma unroll
    for (int mt = 0; mt < 2; mt++)
#pragma unroll
        for (int nt = 0; nt < 8; nt++)
#pragma unroll
            for (int r = 0; r < 4; r++) acc[mt][nt][r] = 0.f;

#define PREFETCH(stage, k0)                                                     \
    {                                                                           \
        ushort_t* stb = smem + (stage) * STAGE3;                                \
        _Pragma("unroll")                                                       \
        for (int m = 0; m < 4; m++) {                                           \
            cp16(smem_u32(stb + m * TILE3 + ldRow * STR3 + ldSeg),              \
                 srcs[m] + (size_t)ldRow * KTOT + (k0) + ldSeg);                \
        }                                                                       \
        cp_commit();                                                            \
    }

#define COMPUTE_CHUNK(bufidx)                                                   \
    {                                                                           \
        const unsigned stb = smem_u32(smem + (bufidx) * STAGE3);                \
        const unsigned bAh = stb;                                               \
        const unsigned bAl = stb + TILE3 * 2;                                   \
        const unsigned bBh = stb + 2 * TILE3 * 2;                               \
        const unsigned bBl = stb + 3 * TILE3 * 2;                               \
        uint32 ah[2][4], al[2][4], b[8][2];                                     \
        _Pragma("unroll")                                                       \
        for (int mt = 0; mt < 2; mt++) {                                        \
            ldsm4(ah[mt][0], ah[mt][1], ah[mt][2], ah[mt][3], bAh + aOff[mt]);  \
            ldsm4(al[mt][0], al[mt][1], al[mt][2], al[mt][3], bAl + aOff[mt]);  \
        }                                                                       \
        _Pragma("unroll")                                                       \
        for (int g = 0; g < 4; g++) {                                           \
            uint32 r0, r1, r2, r3;                                              \
            ldsm4(r0, r1, r2, r3, bBh + bOff[g]);                               \
            b[2*g][0] = r0; b[2*g][1] = r1; b[2*g+1][0] = r2; b[2*g+1][1] = r3; \
        }                                                                       \
        _Pragma("unroll")                                                       \
        for (int mt = 0; mt < 2; mt++)                                          \
            _Pragma("unroll")                                                   \
            for (int nt = 0; nt < 8; nt++) {                                    \
                mma16816(acc[mt][nt], ah[mt], b[nt]);                           \
                mma16816(acc[mt][nt], al[mt], b[nt]);                           \
            }                                                                   \
        _Pragma("unroll")                                                       \
        for (int g = 0; g < 4; g++) {                                           \
            uint32 r0, r1, r2, r3;                                              \
            ldsm4(r0, r1, r2, r3, bBl + bOff[g]);                               \
            b[2*g][0] = r0; b[2*g][1] = r1; b[2*g+1][0] = r2; b[2*g+1][1] = r3; \
        }                                                                       \
        _Pragma("unroll")                                                       \
        for (int mt = 0; mt < 2; mt++)                                          \
            _Pragma("unroll")                                                   \
            for (int nt = 0; nt < 8; nt++)                                      \
                mma16816(acc[mt][nt], ah[mt], b[nt]);                           \
    }

    const int NP = (KTOT / KC3) / 2;   // 32 pairs
    PREFETCH(0, 0);
    PREFETCH(1, KC3);

    for (int p = 0; p < NP; p++) {
        cp_wait<0>();                  // chunks 2p, 2p+1 landed
        __syncthreads();               // all warps past pair p-1 compute
        if (p + 1 < NP) {
            const int c2 = 2 * p + 2, c3 = 2 * p + 3;
            PREFETCH(c2 & 3, c2 * KC3);
            PREFETCH(c3 & 3, c3 * KC3);
        }
        COMPUTE_CHUNK((2 * p) & 3);
        COMPUTE_CHUNK((2 * p + 1) & 3);
    }
#undef PREFETCH
#undef COMPUTE_CHUNK

#pragma unroll
    for (int mt = 0; mt < 2; mt++) {
        const int r0 = wm * 32 + mt * 16 + (lane >> 2);
#pragma unroll
        for (int nt = 0; nt < 8; nt++) {
            const int c = wn * 64 + nt * 8 + 2 * (lane & 3);
            float2 v0 = { acc[mt][nt][0], acc[mt][nt][1] };
            float2 v1 = { acc[mt][nt][2], acc[mt][nt][3] };
            if (relu) {
                v0.x = fmaxf(v0.x, 0.f); v0.y = fmaxf(v0.y, 0.f);
                v1.x = fmaxf(v1.x, 0.f); v1.y = fmaxf(v1.y, 0.f);
            }
            *reinterpret_cast<float2*>(Cblk + (size_t)r0 * ldc + c) = v0;
            *reinterpret_cast<float2*>(Cblk + (size_t)(r0 + 8) * ldc + c) = v1;
        }
    }
}

__global__ __launch_bounds__(256, 2) void gemm_enc_bf16(
    const ushort_t* __restrict__ xhi, const ushort_t* __restrict__ xlo,
    const ushort_t* __restrict__ bqh, const ushort_t* __restrict__ bql,
    const ushort_t* __restrict__ bvh, const ushort_t* __restrict__ bvl,
    float* __restrict__ qs, float* __restrict__ vs)
{
    const int y = blockIdx.y;
    const int isV = y >> 3, head = y & 7;
    const ushort_t* Bh = (isV ? bvh : bqh) + (size_t)head * 128 * KTOT;
    const ushort_t* Bl = (isV ? bvl : bql) + (size_t)head * 128 * KTOT;
    float* C = (isV ? vs : qs) + (size_t)blockIdx.x * 128 * SP + head * 128;
    gemm_core(xhi + (size_t)blockIdx.x * 128 * KTOT, xlo + (size_t)blockIdx.x * 128 * KTOT,
              Bh, Bl, C, SP, 1);
}

__global__ __launch_bounds__(256, 2) void gemm_dec_bf16(
    const ushort_t* __restrict__ ahi, const ushort_t* __restrict__ alo,
    const ushort_t* __restrict__ bh, const ushort_t* __restrict__ bl,
    float* __restrict__ out)
{
    gemm_core(ahi + (size_t)blockIdx.x * 128 * KTOT, alo + (size_t)blockIdx.x * 128 * KTOT,
              bh + (size_t)blockIdx.y * 128 * KTOT, bl + (size_t)blockIdx.y * 128 * KTOT,
              out + (size_t)blockIdx.x * 128 * DENSE + blockIdx.y * 128, DENSE, 0);
}

// ---------------- sig reduction ----------------
__global__ void reduce_sig_a(const float* __restrict__ qs, float* __restrict__ part)
{
    const int b = blockIdx.x;
    const int col = blockIdx.y * 128 + threadIdx.x;
    const int tz = blockIdx.z;
    const int t0 = tz * (TT / TCH);
    const float* p = qs + ((size_t)b * TT + t0) * SP + col;
    float s = 0.f, s8 = 0.f;
#pragma unroll 4
    for (int t = 0; t < TT / TCH; t++) {
        float v = p[(size_t)t * SP];
        s += v;
        if (((t0 + t) & 7) == 0) s8 += v;
    }
    part[((size_t)b * TCH + tz) * SP + col] = s;
    part[(size_t)BB * TCH * SP + ((size_t)b * TCH + tz) * SP + col] = s8;
}

__global__ void reduce_sig_b(const float* __restrict__ part, float* __restrict__ sig)
{
    const int b = blockIdx.x;
    const int col = blockIdx.y * 128 + threadIdx.x;
    float s = 0.f, s8 = 0.f;
#pragma unroll
    for (int z = 0; z < TCH; z++) {
        s  += part[((size_t)b * TCH + z) * SP + col];
        s8 += part[(size_t)BB * TCH * SP + ((size_t)b * TCH + z) * SP + col];
    }
    sig[b * SP + col] = s * (1.f / TT) + 0.5f * s8 * (1.f / (TT / 8));
}

// ---------------- parallel metric MLP ----------------
__global__ __launch_bounds__(256) void metric1_kernel(
    const float* __restrict__ sig, const float* __restrict__ w1,
    const float* __restrict__ b1, float* __restrict__ hbuf)
{
    __shared__ float red[8][32];
    const int b = blockIdx.x;
    const int j = blockIdx.y * 32 + (threadIdx.x & 31);
    const int kg = threadIdx.x >> 5;
    const float* sg = sig + b * SP;
    float s = 0.f;
#pragma unroll 4
    for (int d = kg; d < SP; d += 8)
        s = fmaf(sg[d], w1[d * 512 + j], s);
    red[kg][threadIdx.x & 31] = s;
    __syncthreads();
    if (kg == 0) {
        float acc = b1[j];
#pragma unroll
        for (int g = 0; g < 8; g++) acc += red[g][threadIdx.x & 31];
        hbuf[b * 512 + j] = 0.5f * acc * (1.f + erff(acc * 0.7071067811865475f));
    }
}

__global__ __launch_bounds__(256) void metric2_kernel(
    const float* __restrict__ hbuf, const float* __restrict__ w2,
    const float* __restrict__ b2, const float* __restrict__ base,
    float* __restrict__ metric)
{
    __shared__ float red[8][32];
    const int b = blockIdx.x;
    const int col = blockIdx.y * 32 + (threadIdx.x & 31);
    const int kg = threadIdx.x >> 5;
    const float* hb = hbuf + b * 512;
    float s = 0.f;
#pragma unroll 4
    for (int k = kg; k < 512; k += 8)
        s = fmaf(hb[k], w2[k * SP + col], s);
    red[kg][threadIdx.x & 31] = s;
    __syncthreads();
    if (kg == 0) {
        float m = b2[col];
#pragma unroll
        for (int g = 0; g < 8; g++) m += red[g][threadIdx.x & 31];
        float xv = base[col] + 0.1f * m;
        metric[b * SP + col] = fmaxf(xv, 0.f) + log1pf(expf(-fabsf(xv)));
    }
}

// ---------------- Hebbian U@V ----------------
__global__ void heb_kernel(const float* __restrict__ U, const float* __restrict__ V,
                           float* __restrict__ hebM)
{
    int h = blockIdx.x, i = threadIdx.x;
    float u[32];
#pragma unroll
    for (int r = 0; r < 32; r++) u[r] = U[h * HD * 32 + i * 32 + r];
    const float* Vh = V + h * 32 * HD;
    for (int j = 0; j < HD; j++) {
        float s = 0.f;
#pragma unroll
        for (int r = 0; r < 32; r++) s = fmaf(u[r], Vh[r * HD + j], s);
        hebM[h * HD * HD + i * HD + j] = s;
    }
}

// ---------------- Hebbian context precompute ----------------
#define HEB_SMEM ((HD*HD + 8*HD) * 4)
__global__ __launch_bounds__(256) void heb_ctx_kernel(
    const float* __restrict__ qs, const float* __restrict__ hebM,
    float* __restrict__ hebC)
{
    extern __shared__ float hsm[];
    float* HM = hsm;
    float* qrow = hsm + HD * HD;
    const int h = blockIdx.y;
    const int row0 = blockIdx.x * 32;
    const int tid = threadIdx.x, warp = tid >> 5, lane = tid & 31;

    const float* src = hebM + h * HD * HD;
    for (int i = tid * 4; i < HD * HD; i += 1024)
        *reinterpret_cast<float4*>(HM + i) = *reinterpret_cast<const float4*>(src + i);
    __syncthreads();

    float* qw = qrow + warp * HD;
#pragma unroll 1
    for (int it = 0; it < 4; it++) {
        const int r = row0 + warp * 4 + it;
        const float* q = qs + (size_t)r * SP + h * HD;
        float q0 = q[lane], q1 = q[lane + 32], q2 = q[lane + 64], q3 = q[lane + 96];
        qw[lane] = q0; qw[lane + 32] = q1; qw[lane + 64] = q2; qw[lane + 96] = q3;
        float nq = q0 * q0 + q1 * q1 + q2 * q2 + q3 * q3;
#pragma unroll
        for (int o = 16; o; o >>= 1) nq += __shfl_xor_sync(0xffffffffu, nq, o);
        const float nrm = sqrtf(nq);
        const float sc = (nrm > 0.2f) ? (0.1f / fmaxf(nrm, 1e-12f)) : 0.f;
        __syncwarp();

        float a0 = 0.f, a1 = 0.f, a2 = 0.f, a3 = 0.f;
        const int j = lane * 4;
#pragma unroll 8
        for (int e = 0; e < HD; e++) {
            float qe = qw[e];
            float4 hv = *reinterpret_cast<const float4*>(HM + e * HD + j);
            a0 = fmaf(qe, hv.x, a0);
            a1 = fmaf(qe, hv.y, a1);
            a2 = fmaf(qe, hv.z, a2);
            a3 = fmaf(qe, hv.w, a3);
        }
        float4 o4 = { a0 * sc, a1 * sc, a2 * sc, a3 * sc };
        *reinterpret_cast<float4*>(hebC + (size_t)r * SP + h * HD + j) = o4;
        __syncwarp();
    }
}

// ---------------- windowed metric attention (float4 smem everywhere) ----------------
#define TTILE 32
#define NROWS 95
#define RSTR 132
#define ATTN_SMEM ((2*NROWS*RSTR + 128) * 4)

__global__ __launch_bounds__(256) void attn_kernel(
    const float* __restrict__ qs, const float* __restrict__ vs,
    const float* __restrict__ metric, const float* __restrict__ hebC,
    ushort_t* __restrict__ osHi, ushort_t* __restrict__ osLo)
{
    extern __shared__ float sm[];
    float* q_s = sm;
    float* v_s = q_s + NROWS * RSTR;
    float* met_s = v_s + NROWS * RSTR;
    __shared__ float d_s[8][WIN];
    __shared__ float wsel[8][TOPK];
    __shared__ int   rsel[8][TOPK];

    const int t0 = blockIdx.x * TTILE;
    const int h = blockIdx.y;
    const int b = blockIdx.z;
    const int tid = threadIdx.x;
    const int warp = tid >> 5, lane = tid & 31;

    const size_t baseRow = (size_t)b * TT * SP;
    for (int i = tid; i < NROWS * 32; i += 256) {
        int s = i >> 5, e4 = (i & 31) * 4;
        int g = t0 - (WIN - 1) + s; if (g < 0) g = 0;
        size_t gi = baseRow + (size_t)g * SP + h * HD + e4;
        *reinterpret_cast<float4*>(q_s + s * RSTR + e4) =
            *reinterpret_cast<const float4*>(qs + gi);
        *reinterpret_cast<float4*>(v_s + s * RSTR + e4) =
            *reinterpret_cast<const float4*>(vs + gi);
    }
    if (tid < 32)
        *reinterpret_cast<float4*>(met_s + tid * 4) =
            *reinterpret_cast<const float4*>(metric + b * SP + h * HD + tid * 4);
    __syncthreads();

    for (int it = 0; it < 4; it++) {
        const int t = t0 + warp * 4 + it;
        const int qrow = t - t0 + (WIN - 1);
        const float* qr = q_s + qrow * RSTR;

        int gg0 = t - lane;        if (gg0 < 0) gg0 = 0;
        int gg1 = t - lane - 32;   if (gg1 < 0) gg1 = 0;
        const int r0 = gg0 - t0 + (WIN - 1);
        const int r1 = gg1 - t0 + (WIN - 1);
        const float* p0 = q_s + r0 * RSTR;
        const float* p1 = q_s + r1 * RSTR;

        float d0 = 0.f, d1 = 0.f;
#pragma unroll 8
        for (int e = 0; e < HD; e += 4) {
            float4 qv = *reinterpret_cast<const float4*>(qr + e);
            float4 m4 = *reinterpret_cast<const float4*>(met_s + e);
            float4 a4 = *reinterpret_cast<const float4*>(p0 + e);
            float4 b4 = *reinterpret_cast<const float4*>(p1 + e);
            float a;
            a = qv.x - a4.x; d0 = fmaf(a * a, m4.x, d0);
            a = qv.y - a4.y; d0 = fmaf(a * a, m4.y, d0);
            a = qv.z - a4.z; d0 = fmaf(a * a, m4.z, d0);
            a = qv.w - a4.w; d0 = fmaf(a * a, m4.w, d0);
            a = qv.x - b4.x; d1 = fmaf(a * a, m4.x, d1);
            a = qv.y - b4.y; d1 = fmaf(a * a, m4.y, d1);
            a = qv.z - b4.z; d1 = fmaf(a * a, m4.z, d1);
            a = qv.w - b4.w; d1 = fmaf(a * a, m4.w, d1);
        }
        float dist0 = sqrtf(d0 + 1e-8f);
        float dist1 = sqrtf(d1 + 1e-8f);
        d_s[warp][lane] = dist0;
        d_s[warp][lane + 32] = dist1;
        __syncwarp();

        int rk0 = 0, rk1 = 0;
        const int j1 = lane + 32;
#pragma unroll 8
        for (int j = 0; j < WIN; j++) {
            float dj = d_s[warp][j];
            rk0 += (dj < dist0) || (dj == dist0 && j < lane);
            rk1 += (dj < dist1) || (dj == dist1 && j < j1);
        }
        if (rk0 < TOPK) { wsel[warp][rk0] = expf(-dist0); rsel[warp][rk0] = r0; }
        if (rk1 < TOPK) { wsel[warp][rk1] = expf(-dist1); rsel[warp][rk1] = r1; }
        __syncwarp();

        float wsum = wsel[warp][lane];
#pragma unroll
        for (int o = 16; o; o >>= 1) wsum += __shfl_xor_sync(0xffffffffu, wsum, o);
        const float inv = 1.f / (wsum + 1e-8f);

        const int e0 = lane * 4;
        float c0 = 0.f, c1 = 0.f, c2 = 0.f, c3 = 0.f;
#pragma unroll 4
        for (int k = 0; k < TOPK; k++) {
            float wk = wsel[warp][k];
            float4 v4 = *reinterpret_cast<const float4*>(v_s + rsel[warp][k] * RSTR + e0);
            c0 = fmaf(wk, v4.x, c0);
            c1 = fmaf(wk, v4.y, c1);
            c2 = fmaf(wk, v4.z, c2);
            c3 = fmaf(wk, v4.w, c3);
        }

        const size_t ob = baseRow + (size_t)t * SP + h * HD;
        float4 hb4 = *reinterpret_cast<const float4*>(hebC + ob + e0);
        c0 = c0 * inv + hb4.x;
        c1 = c1 * inv + hb4.y;
        c2 = c2 * inv + hb4.z;
        c3 = c3 * inv + hb4.w;

        float4 q4 = *reinterpret_cast<const float4*>(qr + e0);
        ushort4 oh4, ol4;
        split_bf16(q4.x * c0, oh4.x, ol4.x);
        split_bf16(q4.y * c1, oh4.y, ol4.y);
        split_bf16(q4.z * c2, oh4.z, ol4.z);
        split_bf16(q4.w * c3, oh4.w, ol4.w);
        *reinterpret_cast<ushort4*>(osHi + ob + e0) = oh4;
        *reinterpret_cast<ushort4*>(osLo + ob + e0) = ol4;
    }
}

// ---------------- launcher ----------------
extern "C" void kernel_launch(void* const* d_in, const int* in_sizes, int n_in,
                              void* d_out, int out_size)
{
    const float* x      = (const float*)d_in[0];
    const float* enc_q  = (const float*)d_in[1];
    const float* enc_v  = (const float*)d_in[2];
    const float* w1     = (const float*)d_in[3];
    const float* b1     = (const float*)d_in[4];
    const float* w2     = (const float*)d_in[5];
    const float* b2     = (const float*)d_in[6];
    const float* basem  = (const float*)d_in[7];
    const float* hebU   = (const float*)d_in[8];
    const float* hebV   = (const float*)d_in[9];
    const float* dec    = (const float*)d_in[10];
    float* out = (float*)d_out;

    float *qs, *vs, *hebc, *part, *sig, *hbuf, *metric, *hebM;
    ushort_t *xhi, *xlo, *bqh, *bql, *bvh, *bvl, *bdh, *bdl, *oshi, *oslo;
    cudaGetSymbolAddress((void**)&qs, g_qs);
    cudaGetSymbolAddress((void**)&vs, g_vs);
    cudaGetSymbolAddress((void**)&hebc, g_hebC);
    cudaGetSymbolAddress((void**)&part, g_part);
    cudaGetSymbolAddress((void**)&sig, g_sig);
    cudaGetSymbolAddress((void**)&hbuf, g_hbuf);
    cudaGetSymbolAddress((void**)&metric, g_metric);
    cudaGetSymbolAddress((void**)&hebM, g_heb);
    cudaGetSymbolAddress((void**)&xhi, g_x_hi);
    cudaGetSymbolAddress((void**)&xlo, g_x_lo);
    cudaGetSymbolAddress((void**)&bqh, g_btq_hi);
    cudaGetSymbolAddress((void**)&bql, g_btq_lo);
    cudaGetSymbolAddress((void**)&bvh, g_btv_hi);
    cudaGetSymbolAddress((void**)&bvl, g_btv_lo);
    cudaGetSymbolAddress((void**)&bdh, g_btd_hi);
    cudaGetSymbolAddress((void**)&bdl, g_btd_lo);
    cudaGetSymbolAddress((void**)&oshi, g_os_hi);
    cudaGetSymbolAddress((void**)&oslo, g_os_lo);

    cudaFuncSetAttribute(attn_kernel, cudaFuncAttributeMaxDynamicSharedMemorySize, ATTN_SMEM);
    cudaFuncSetAttribute(heb_ctx_kernel, cudaFuncAttributeMaxDynamicSharedMemorySize, HEB_SMEM);
    cudaFuncSetAttribute(gemm_enc_bf16, cudaFuncAttributeMaxDynamicSharedMemorySize, GEMM_SMEM);
    cudaFuncSetAttribute(gemm_dec_bf16, cudaFuncAttributeMaxDynamicSharedMemorySize, GEMM_SMEM);

    // 1,2,3: input prep (merged enc transposes)
    split_x_kernel<<<MT * DENSE / 1024, 256>>>(x, xhi, xlo);
    enc_transpose_kernel<<<dim3(32, 4, 16), dim3(32, 8)>>>(enc_q, enc_v, bqh, bql, bvh, bvl);
    heb_kernel<<<NH, HD>>>(hebU, hebV, hebM);

    // 4: encoders (PROFILED SLOT)
    gemm_enc_bf16<<<dim3(MT / 128, 16), 256, GEMM_SMEM>>>(xhi, xlo, bqh, bql, bvh, bvl, qs, vs);

    // 5: hebbian contexts
    heb_ctx_kernel<<<dim3(MT / 32, NH), 256, HEB_SMEM>>>(qs, hebM, hebc);

    // 6: decoder weight transpose
    transpose_split_kernel<<<dim3(32, 32, 1), dim3(32, 8)>>>(dec, DENSE, bdh, bdl, 0, 0);

    // 7,8: sig reduction
    reduce_sig_a<<<dim3(BB, SP / 128, TCH), 128>>>(qs, part);
    reduce_sig_b<<<dim3(BB, SP / 128), 128>>>(part, sig);

    // 9,10: parallel metric MLP
    metric1_kernel<<<dim3(BB, 16), 256>>>(sig, w1, b1, hbuf);
    metric2_kernel<<<dim3(BB, 32), 256>>>(hbuf, w2, b2, basem, metric);

    // 11: attention (+hebC add)
    attn_kernel<<<dim3(TT / TTILE, NH, BB), 256, ATTN_SMEM>>>(qs, vs, metric, hebc, oshi, oslo);

    // 12: decoder
    gemm_dec_bf16<<<dim3(MT / 128, SP / 128), 256, GEMM_SMEM>>>(oshi, oslo, bdh, bdl, out);
}